// round 13
// speedup vs baseline: 5.0113x; 1.0090x over previous
#include <cuda_runtime.h>
#include <cuda_bf16.h>
#include <math.h>
#include <stdint.h>

#define HW      65536
#define IMG     256
#define BATCH   2
#define CDIM    96
#define HEADS   8
#define CHEAD   12
#define HIDDEN  255

// ---------------------------------------------------------------------------
// Scratch
// ---------------------------------------------------------------------------
__device__ __nv_bfloat16 g_qkvA [BATCH * 3 * CDIM * HW];
__device__ __nv_bfloat16 g_qkvAd[BATCH * 3 * CDIM * HW];
__device__ __nv_bfloat16 g_qkvB [BATCH * 3 * CDIM * HW];
__device__ __nv_bfloat16 g_qkvBd[BATCH * 3 * CDIM * HW];
__device__ __nv_bfloat16 g_xn   [BATCH * CDIM * HW];
__device__ __nv_bfloat16 g_yn   [BATCH * CDIM * HW];
__device__ __nv_bfloat16 g_t    [BATCH * 2 * HIDDEN * HW];
__device__ __nv_bfloat16 g_gate [BATCH * 288 * HW];   // 288-pitch; rows 255..287 stay zero
__device__ float g_x1   [BATCH * CDIM * HW];
// Gram partials: [bh][chunk*4+quad][warp][48]
__device__ float g_gpartA[BATCH * HEADS * 128 * 8 * 48];
__device__ float g_gpartB[BATCH * HEADS * 128 * 8 * 48];
__device__ float g_attnA [BATCH * HEADS * 144];
__device__ float g_attnB [BATCH * HEADS * 144];
__device__ float g_P0  [CDIM * CDIM];
__device__ float g_P1  [CDIM * CDIM];
// prepacked tf32 fragment tiles
__device__ uint32_t g_prepQA  [3 * 9216];
__device__ uint32_t g_prepQB  [3 * 9216];
__device__ uint32_t g_prepPin [6 * 9216];
__device__ uint32_t g_prepPout[3 * 9216];
__device__ uint32_t g_prepC0  [9216];
__device__ uint32_t g_prepC1  [9216];
__device__ uint32_t g_cwApk   [BATCH * 9216];
__device__ uint32_t g_cwBpk   [BATCH * 9216];
__device__ float g_sQA[288],  g_tQA[288];
__device__ float g_sQB[288],  g_tQB[288];
__device__ float g_sPin[576], g_tPin[576];

// ---------------------------------------------------------------------------
// tf32 / cp.async helpers
// ---------------------------------------------------------------------------
__device__ __forceinline__ uint32_t f2tf(float f) {
    uint32_t u;
    asm("cvt.rna.tf32.f32 %0, %1;" : "=r"(u) : "f"(f));
    return u;
}

__device__ __forceinline__ void mma_tf32(float* c, const uint32_t* a, const uint32_t* b) {
    asm volatile(
        "mma.sync.aligned.m16n8k8.row.col.f32.tf32.tf32.f32 "
        "{%0,%1,%2,%3}, {%4,%5,%6,%7}, {%8,%9}, {%0,%1,%2,%3};"
        : "+f"(c[0]), "+f"(c[1]), "+f"(c[2]), "+f"(c[3])
        : "r"(a[0]), "r"(a[1]), "r"(a[2]), "r"(a[3]), "r"(b[0]), "r"(b[1]));
}

__device__ __forceinline__ void cp16(void* smem, const void* gmem) {
    uint32_t a = (uint32_t)__cvta_generic_to_shared(smem);
    asm volatile("cp.async.cg.shared.global [%0], [%1], 16;\n" :: "r"(a), "l"(gmem));
}
#define CP_COMMIT()  asm volatile("cp.async.commit_group;\n")
#define CP_WAIT(n)   asm volatile("cp.async.wait_group %0;\n" :: "n"(n))

__device__ __forceinline__ int a_pack_off(int m, int k) {
    return (k >> 3) * 768 + (m >> 4) * 128 + (m & 7) * 16 + (k & 3) * 4
         + ((k >> 2) & 1) * 2 + ((m >> 3) & 1);
}

// gemm4: A tile + full B panel
#define G4_SMEM_WORDS   (9216 + 96*136)
#define G4_SMEM_BYTES   (G4_SMEM_WORDS * 4)
// gemm96: full B panel + one A tile + stats + ln vectors
#define G96_SMEM_WORDS  (96*136 + 9216 + 256 + 192)
#define G96_SMEM_BYTES  (G96_SMEM_WORDS * 4)
// pout: double-buffered 32-row B ring
#define POUT_SMEM_WORDS (9216 + 2*32*136)
#define POUT_SMEM_BYTES (POUT_SMEM_WORDS * 4)

// ---------------------------------------------------------------------------
// Mega-prep (unchanged).
// ---------------------------------------------------------------------------
__device__ void prep_tile(const float* __restrict__ W, int M, int tile,
                          const float* __restrict__ wln,
                          const float* __restrict__ bln,
                          uint32_t* __restrict__ Apk,
                          float* __restrict__ svec, float* __restrict__ tvec,
                          float* wls, float* bls) {
    int m0 = tile * 96;
    if (threadIdx.x < 96) { wls[threadIdx.x] = wln[threadIdx.x]; bls[threadIdx.x] = bln[threadIdx.x]; }
    __syncthreads();
#pragma unroll
    for (int i = 0; i < 36; i++) {
        int idx = threadIdx.x + i * 256;
        int m = idx / 96;
        int k = idx - m * 96;
        float v = 0.f;
        if (m0 + m < M) v = W[(size_t)(m0 + m) * 96 + k] * wls[k];
        Apk[tile * 9216 + a_pack_off(m, k)] = f2tf(v);
    }
    if (threadIdx.x < 96) {
        int gm = m0 + threadIdx.x;
        float s = 0.f, tt = 0.f;
        if (gm < M) {
            for (int k = 0; k < 96; k++) {
                float w = W[(size_t)gm * 96 + k];
                s  += w * wls[k];
                tt += w * bls[k];
            }
        }
        svec[tile * 96 + threadIdx.x] = s;
        tvec[tile * 96 + threadIdx.x] = tt;
    }
}

__global__ void megaprep(
        const float* __restrict__ qkvA_w, const float* __restrict__ qkvB_w,
        const float* __restrict__ pin_w,  const float* __restrict__ pout_w,
        const float* __restrict__ concat_w,
        const float* __restrict__ projA_w, const float* __restrict__ projB_w,
        const float* __restrict__ ln1_w, const float* __restrict__ ln1_b,
        const float* __restrict__ ln2_w, const float* __restrict__ ln2_b,
        uint32_t* __restrict__ prepQA, uint32_t* __restrict__ prepQB,
        uint32_t* __restrict__ prepPin, uint32_t* __restrict__ prepPout,
        uint32_t* __restrict__ prepC0, uint32_t* __restrict__ prepC1,
        float* __restrict__ sQA, float* __restrict__ tQA,
        float* __restrict__ sQB, float* __restrict__ tQB,
        float* __restrict__ sPin, float* __restrict__ tPin,
        float* __restrict__ P0, float* __restrict__ P1) {
    __shared__ float sbuf[96 * 96];
    int bid = blockIdx.x;
    if (bid < 3) {
        prep_tile(qkvA_w, 288, bid, ln1_w, ln1_b, prepQA, sQA, tQA, sbuf, sbuf + 96);
    } else if (bid < 6) {
        prep_tile(qkvB_w, 288, bid - 3, ln1_w, ln1_b, prepQB, sQB, tQB, sbuf, sbuf + 96);
    } else if (bid < 12) {
        prep_tile(pin_w, 510, bid - 6, ln2_w, ln2_b, prepPin, sPin, tPin, sbuf, sbuf + 96);
    } else if (bid < 15) {
        int s = bid - 12;
#pragma unroll
        for (int i = 0; i < 36; i++) {
            int idx = threadIdx.x + i * 256;
            int m = idx / 96;
            int k = idx - m * 96;
            int kg = s * 96 + k;
            float v = (kg < HIDDEN) ? pout_w[(size_t)m * HIDDEN + kg] : 0.f;
            prepPout[s * 9216 + a_pack_off(m, k)] = f2tf(v);
        }
    } else if (bid < 17) {
        const float* W = concat_w + (bid == 16 ? 96 : 0);
        uint32_t* out = (bid == 16) ? prepC1 : prepC0;
#pragma unroll
        for (int i = 0; i < 36; i++) {
            int idx = threadIdx.x + i * 256;
            int m = idx / 96;
            int k = idx - m * 96;
            out[a_pack_off(m, k)] = f2tf(W[(size_t)m * 192 + k]);
        }
    } else {
        int w = bid - 17;
        int br = w & 1;
        int yt = w >> 1;
        const float* proj = br ? projB_w : projA_w;
        const float* cw   = concat_w + (br ? 96 : 0);
        float* P = br ? P1 : P0;
        for (int i = threadIdx.x; i < 96 * 96; i += 256) sbuf[i] = proj[i];
        __syncthreads();
        int base = yt * 512;
#pragma unroll
        for (int r = 0; r < 2; r++) {
            int o = base + r * 256 + threadIdx.x;
            int m = o / 96, n = o % 96;
            float s = 0.f;
#pragma unroll 8
            for (int c = 0; c < 96; c++) s += cw[m * 192 + c] * sbuf[c * 96 + n];
            P[o] = s;
        }
    }
}

// ---------------------------------------------------------------------------
// 32-k MMA chunk on the 96x128 tile.
// ---------------------------------------------------------------------------
__device__ __forceinline__ void g96_chunk(
        float acc[3][4][4], const uint32_t* __restrict__ As,
        const uint32_t* __restrict__ Bbuf,
        int kc, int g, int t, int wmi, int wn) {
#pragma unroll
    for (int ks2 = 0; ks2 < 4; ks2++) {
        const uint32_t* Ab = As + (kc * 4 + ks2) * 768 + g * 16 + t * 4;
        const uint32_t* Bb = Bbuf + (ks2 * 8 + t) * 136 + wn + g;
        uint4 a4[3];
        uint32_t bf[4][2];
#pragma unroll
        for (int mi = 0; mi < 3; mi++)
            a4[mi] = *reinterpret_cast<const uint4*>(Ab + (wmi + mi) * 128);
#pragma unroll
        for (int ni = 0; ni < 4; ni++) {
            bf[ni][0] = Bb[ni * 8];
            bf[ni][1] = Bb[4 * 136 + ni * 8];
        }
#pragma unroll
        for (int mi = 0; mi < 3; mi++) {
            uint32_t af[4] = {a4[mi].x, a4[mi].y, a4[mi].z, a4[mi].w};
#pragma unroll
            for (int ni = 0; ni < 4; ni++)
                mma_tf32(acc[mi][ni], af, bf[ni]);
        }
    }
}

// ---------------------------------------------------------------------------
// B-resident multi-M gemm96 + optional bf16 LN(x) emission (for gemm4).
// grid (1, HW/128, NB*BATCH).
// ---------------------------------------------------------------------------
struct G96P {
    const uint32_t* Apk[2];
    const float*    sv[2];
    const float*    tv[2];
    const float*    X[2];
    __nv_bfloat16*  xnOut[2];    // may be null
    __nv_bfloat16*  Y[2];
    const float*    lnw;
    const float*    lnb;
};

__global__ void __launch_bounds__(256, 2) gemm96(
        G96P p, int M, int NB, int Mtiles, size_t xBatch, size_t yBatch) {
    extern __shared__ uint32_t sm[];
    uint32_t* Bs = sm;                       // 96*136 = 13056
    uint32_t* As = sm + 13056;               // 9216
    float* mu_s  = (float*)(sm + 13056 + 9216);
    float* inv_s = mu_s + 128;
    float* wl_s  = inv_s + 128;              // 96
    float* bl_s  = wl_s + 96;                // 96

    int z  = blockIdx.z;
    int br = z % NB;
    int bz = z / NB;
    const float* Xb = p.X[br] + (size_t)bz * xBatch;
    __nv_bfloat16* Yb = p.Y[br] + (size_t)bz * yBatch;
    const float* svec = p.sv[br];
    const float* tvec = p.tv[br];
    const uint32_t* Apk = p.Apk[br];
    bool hasXn = (p.xnOut[br] != nullptr);

    int n0 = blockIdx.y * 128;
    int tid  = threadIdx.x;
    int warp = tid >> 5;
    int lane = tid & 31;
    int g = lane >> 2;
    int t = lane & 3;
    int wm  = (warp >> 2) * 48;
    int wmi = (warp >> 2) * 3;
    int wn  = (warp & 3) * 32;

#define LOADA96(mt)                                                          \
    {                                                                        \
        const uint4* Ag = reinterpret_cast<const uint4*>(Apk + (size_t)(mt) * 9216); \
        _Pragma("unroll")                                                    \
        for (int i = 0; i < 9; i++) {                                        \
            int idx = tid + i * 256;                                         \
            cp16(As + idx * 4, Ag + idx);                                    \
        }                                                                    \
    }

    // ---- stage full B panel (96 rows) + A tile 0 ----
#pragma unroll
    for (int j = 0; j < 12; j++) {
        int idx = tid + j * 256;
        int k = idx >> 5, n4 = idx & 31;
        cp16(Bs + k * 136 + n4 * 4, Xb + (size_t)k * HW + n0 + n4 * 4);
    }
    LOADA96(0);
    CP_COMMIT();
    if (hasXn && tid < 96) { wl_s[tid] = p.lnw[tid]; bl_s[tid] = p.lnb[tid]; }
    CP_WAIT(0);
    __syncthreads();

    // ---- stats once per column ----
    if (tid < 128) {
        float csum = 0.f, csq = 0.f;
#pragma unroll 8
        for (int k = 0; k < 96; k++) {
            float v = __uint_as_float(Bs[k * 136 + tid]);
            csum += v; csq += v * v;
        }
        float mu  = csum * (1.f / 96.f);
        float var = csq * (1.f / 96.f) - mu * mu;
        mu_s[tid]  = mu;
        inv_s[tid] = rsqrtf(var + 1e-5f);
    }
    __syncthreads();

    // ---- optional bf16 LN(x) emission (B panel resident) ----
    if (hasXn) {
        __nv_bfloat16* xo = p.xnOut[br] + (size_t)bz * CDIM * HW + n0;
        int c2 = (tid & 63) * 2;
        int rb = tid >> 6;
        float m0v = mu_s[c2],     i0 = inv_s[c2];
        float m1v = mu_s[c2 + 1], i1 = inv_s[c2 + 1];
#pragma unroll
        for (int it = 0; it < 24; it++) {
            int r = it * 4 + rb;
            float v0 = __uint_as_float(Bs[r * 136 + c2]);
            float v1 = __uint_as_float(Bs[r * 136 + c2 + 1]);
            float w = wl_s[r], bb = bl_s[r];
            *reinterpret_cast<__nv_bfloat162*>(xo + (size_t)r * HW + c2) =
                __floats2bfloat162_rn((v0 - m0v) * i0 * w + bb,
                                      (v1 - m1v) * i1 * w + bb);
        }
    }

    for (int mt = 0; mt < Mtiles; mt++) {
        int m0 = mt * 96;
        float acc[3][4][4];
#pragma unroll
        for (int mi = 0; mi < 3; mi++)
#pragma unroll
            for (int ni = 0; ni < 4; ni++)
#pragma unroll
                for (int r = 0; r < 4; r++) acc[mi][ni][r] = 0.f;

#pragma unroll
        for (int kc = 0; kc < 3; kc++)
            g96_chunk(acc, As, Bs + kc * 4352, kc, g, t, wmi, wn);

        __syncthreads();
        if (mt + 1 < Mtiles) {
            LOADA96(mt + 1);
            CP_COMMIT();
        }

#pragma unroll
        for (int mi = 0; mi < 3; mi++) {
            int r0 = m0 + wm + mi * 16 + g;
            int r1 = r0 + 8;
            float s0 = 0.f, t0 = 0.f, s1 = 0.f, t1 = 0.f;
            if (r0 < M) { s0 = svec[r0]; t0 = tvec[r0]; }
            if (r1 < M) { s1 = svec[r1]; t1 = tvec[r1]; }
#pragma unroll
            for (int ni = 0; ni < 4; ni++) {
                int ln = wn + ni * 8 + 2 * t;
                int col = n0 + ln;
                float i0 = inv_s[ln],     m0v = mu_s[ln]     * i0;
                float i1 = inv_s[ln + 1], m1v = mu_s[ln + 1] * i1;
                if (r0 < M) {
                    float vx = acc[mi][ni][0] * i0 - m0v * s0 + t0;
                    float vy = acc[mi][ni][1] * i1 - m1v * s0 + t0;
                    *reinterpret_cast<__nv_bfloat162*>(Yb + (size_t)r0 * HW + col) =
                        __floats2bfloat162_rn(vx, vy);
                }
                if (r1 < M) {
                    float vx = acc[mi][ni][2] * i0 - m0v * s1 + t1;
                    float vy = acc[mi][ni][3] * i1 - m1v * s1 + t1;
                    *reinterpret_cast<__nv_bfloat162*>(Yb + (size_t)r1 * HW + col) =
                        __floats2bfloat162_rn(vx, vy);
                }
            }
        }

        if (mt + 1 < Mtiles) {
            CP_WAIT(0);
            __syncthreads();
        }
    }
#undef LOADA96
}

// ---------------------------------------------------------------------------
// pout (unchanged from R12).
// ---------------------------------------------------------------------------
__global__ void __launch_bounds__(256, 3) gemmPout(
        const uint32_t* __restrict__ Apk,
        const __nv_bfloat16* __restrict__ X,
        const float* __restrict__ Rsrc,
        float* __restrict__ Y,
        size_t xBatch, size_t yBatch, size_t rBatch) {
    extern __shared__ uint32_t sm[];
    uint32_t* As = sm;
    uint32_t* Bs = sm + 9216;

    int bz = blockIdx.z;
    const __nv_bfloat16* Xb = X + (size_t)bz * xBatch;
    float*       Yb = Y    + (size_t)bz * yBatch;
    const float* Rb = Rsrc + (size_t)bz * rBatch;

    int n0 = blockIdx.y * 128;
    int tid  = threadIdx.x;
    int warp = tid >> 5;
    int lane = tid & 31;
    int g = lane >> 2;
    int t = lane & 3;
    int wm  = (warp >> 2) * 48;
    int wmi = (warp >> 2) * 3;
    int wn  = (warp & 3) * 32;

    int kk = tid >> 3;
    int nb = (tid & 7) * 16;

    uint4 rA, rB;
#define LDGB(c)                                                             \
    {                                                                       \
        const uint4* src = reinterpret_cast<const uint4*>(                  \
            Xb + (size_t)((c) * 32 + kk) * HW + n0 + nb);                   \
        rA = src[0]; rB = src[1];                                           \
    }
#define STSB(c)                                                             \
    {                                                                       \
        uint32_t* dst = Bs + ((c) & 1) * 4352 + kk * 136 + nb;              \
        uint32_t u;                                                         \
        u = rA.x; dst[0]  = u << 16; dst[1]  = u & 0xFFFF0000u;             \
        u = rA.y; dst[2]  = u << 16; dst[3]  = u & 0xFFFF0000u;             \
        u = rA.z; dst[4]  = u << 16; dst[5]  = u & 0xFFFF0000u;             \
        u = rA.w; dst[6]  = u << 16; dst[7]  = u & 0xFFFF0000u;             \
        u = rB.x; dst[8]  = u << 16; dst[9]  = u & 0xFFFF0000u;             \
        u = rB.y; dst[10] = u << 16; dst[11] = u & 0xFFFF0000u;             \
        u = rB.z; dst[12] = u << 16; dst[13] = u & 0xFFFF0000u;             \
        u = rB.w; dst[14] = u << 16; dst[15] = u & 0xFFFF0000u;             \
    }
#define LOADA(s)                                                            \
    {                                                                       \
        const uint4* Ag = reinterpret_cast<const uint4*>(Apk + (s) * 9216); \
        _Pragma("unroll")                                                   \
        for (int i = 0; i < 9; i++) {                                       \
            int idx = tid + i * 256;                                        \
            cp16(As + idx * 4, Ag + idx);                                   \
        }                                                                   \
        CP_COMMIT();                                                        \
    }

    LOADA(0);
    LDGB(0);
    STSB(0);
    LDGB(1);
    CP_WAIT(0);
    __syncthreads();

    float acc[3][4][4];
#pragma unroll
    for (int mi = 0; mi < 3; mi++)
#pragma unroll
        for (int ni = 0; ni < 4; ni++)
#pragma unroll
            for (int r = 0; r < 4; r++) acc[mi][ni][r] = 0.f;

#pragma unroll
    for (int c = 0; c < 9; c++) {
        g96_chunk(acc, As, Bs + (c & 1) * 4352, c % 3, g, t, wmi, wn);
        if (c < 8) {
            __syncthreads();
            bool newA = (c % 3 == 2);
            if (newA) LOADA(c / 3 + 1);
            STSB(c + 1);
            if (c + 2 <= 8) LDGB(c + 2);
            if (newA) CP_WAIT(0);
            __syncthreads();
        }
    }
#undef LOADA
#undef LDGB
#undef STSB

#pragma unroll
    for (int mi = 0; mi < 3; mi++) {
        int r0 = wm + mi * 16 + g;
        int r1 = r0 + 8;
#pragma unroll
        for (int ni = 0; ni < 4; ni++) {
            int col = n0 + wn + ni * 8 + 2 * t;
            float2 ra = *reinterpret_cast<const float2*>(Rb + (size_t)r0 * HW + col);
            float2 rb = *reinterpret_cast<const float2*>(Rb + (size_t)r1 * HW + col);
            float2 v01 = make_float2(acc[mi][ni][0] + ra.x, acc[mi][ni][1] + ra.y);
            float2 v23 = make_float2(acc[mi][ni][2] + rb.x, acc[mi][ni][3] + rb.y);
            *reinterpret_cast<float2*>(Yb + (size_t)r0 * HW + col) = v01;
            *reinterpret_cast<float2*>(Yb + (size_t)r1 * HW + col) = v23;
        }
    }
}

// ---------------------------------------------------------------------------
// gemm4 v2: all-bf16 sources, register-prefetch pipeline.
// x1 = x + cwA@vA + cwB@vB + C0@xn + C1@yn.
// ---------------------------------------------------------------------------
struct G4 {
    const uint32_t*      Apk[4];
    size_t               aBatch[4];
    const __nv_bfloat16* X[4];
    size_t               xBatch[4];
};

__global__ void __launch_bounds__(256, 2) gemm4_tc(
        G4 p,
        const float* __restrict__ Rsrc,
        float* __restrict__ Y) {
    extern __shared__ uint32_t smem_u[];
    uint32_t* As = smem_u;          // 9216
    uint32_t* Bs = As + 9216;       // 13056

    int bz = blockIdx.z;
    int n0 = blockIdx.y * 128;
    float*       Yb = Y    + (size_t)bz * CDIM * HW;
    const float* Rb = Rsrc + (size_t)bz * CDIM * HW;

    int tid  = threadIdx.x;
    int warp = tid >> 5;
    int lane = tid & 31;
    int g = lane >> 2;
    int t = lane & 3;
    int wm  = (warp >> 2) * 48;
    int wmi = (warp >> 2) * 3;
    int wn  = (warp & 3) * 32;

    // per-thread B slot indices (6 groups of 8 bf16 each)
    uint4 rB[6];
#define LDGB4(s)                                                             \
    {                                                                        \
        const __nv_bfloat16* Xh = p.X[s] + (size_t)bz * p.xBatch[s];         \
        _Pragma("unroll")                                                    \
        for (int i = 0; i < 6; i++) {                                        \
            int idx = tid + i * 256;                                         \
            int k = idx >> 4, n8 = idx & 15;                                 \
            rB[i] = *reinterpret_cast<const uint4*>(Xh + (size_t)k * HW + n0 + n8 * 8); \
        }                                                                    \
    }
#define STSB4()                                                              \
    {                                                                        \
        _Pragma("unroll")                                                    \
        for (int i = 0; i < 6; i++) {                                        \
            int idx = tid + i * 256;                                         \
            int k = idx >> 4, n8 = idx & 15;                                 \
            uint32_t* dst = Bs + k * 136 + n8 * 8;                           \
            uint32_t u;                                                      \
            u = rB[i].x; dst[0] = u << 16; dst[1] = u & 0xFFFF0000u;         \
            u = rB[i].y; dst[2] = u << 16; dst[3] = u & 0xFFFF0000u;         \
            u = rB[i].z; dst[4] = u << 16; dst[5] = u & 0xFFFF0000u;         \
            u = rB[i].w; dst[6] = u << 16; dst[7] = u & 0xFFFF0000u;         \
        }                                                                    \
    }
#define LOADA4(s)                                                            \
    {                                                                        \
        const uint4* Ag = reinterpret_cast<const uint4*>(p.Apk[s] + (size_t)bz * p.aBatch[s]); \
        _Pragma("unroll")                                                    \
        for (int i = 0; i < 9; i++) {                                        \
            int idx = tid + i * 256;                                         \
            cp16(As + idx * 4, Ag + idx);                                    \
        }                                                                    \
        CP_COMMIT();                                                         \
    }

    LOADA4(0);
    LDGB4(0);

    float acc[3][4][4];
#pragma unroll
    for (int mi = 0; mi < 3; mi++)
#pragma unroll
        for (int ni = 0; ni < 4; ni++)
#pragma unroll
            for (int r = 0; r < 4; r++) acc[mi][ni][r] = 0.f;

#pragma unroll
    for (int s = 0; s < 4; s++) {
        CP_WAIT(0);
        __syncthreads();              // A_s visible; prev MMA done with Bs
        STSB4();
        __syncthreads();              // B_s visible
        if (s < 3) LDGB4(s + 1);      // overlaps MMA below
#pragma unroll
        for (int ks = 0; ks < 12; ks++) {
            const uint32_t* Ab = As + ks * 768 + g * 16 + t * 4;
            const uint32_t* Bb = Bs + (ks * 8 + t) * 136 + wn + g;
            uint4 a4[3];
            uint32_t bf[4][2];
#pragma unroll
            for (int mi = 0; mi < 3; mi++)
                a4[mi] = *reinterpret_cast<const uint4*>(Ab + (wmi + mi) * 128);
#pragma unroll
            for (int ni = 0; ni < 4; ni++) {
                bf[ni][0] = Bb[ni * 8];
                bf[ni][1] = Bb[4 * 136 + ni * 8];
            }
#pragma unroll
            for (int mi = 0; mi < 3; mi++) {
                uint32_t af[4] = {a4[mi].x, a4[mi].y, a4[mi].z, a4[mi].w};
#pragma unroll
                for (int ni = 0; ni < 4; ni++)
                    mma_tf32(acc[mi][ni], af, bf[ni]);
            }
        }
        __syncthreads();              // MMA done; As free for overwrite
        if (s < 3) LOADA4(s + 1);
    }

#pragma unroll
    for (int mi = 0; mi < 3; mi++) {
        int r0 = wm + mi * 16 + g;
        int r1 = r0 + 8;
#pragma unroll
        for (int ni = 0; ni < 4; ni++) {
            int col = n0 + wn + ni * 8 + 2 * t;
            float2 ra = *reinterpret_cast<const float2*>(Rb + (size_t)r0 * HW + col);
            float2 rb = *reinterpret_cast<const float2*>(Rb + (size_t)r1 * HW + col);
            float2 v01 = make_float2(acc[mi][ni][0] + ra.x, acc[mi][ni][1] + ra.y);
            float2 v23 = make_float2(acc[mi][ni][2] + rb.x, acc[mi][ni][3] + rb.y);
            *reinterpret_cast<float2*>(Yb + (size_t)r0 * HW + col) = v01;
            *reinterpret_cast<float2*>(Yb + (size_t)r1 * HW + col) = v23;
        }
    }
#undef LOADA4
#undef LDGB4
#undef STSB4
}

// ---------------------------------------------------------------------------
// Depthwise 3x3, 2 output rows per thread (unchanged).
// ---------------------------------------------------------------------------
__global__ void dw3_kernel(const __nv_bfloat16* __restrict__ qA,
                           const __nv_bfloat16* __restrict__ qB,
                           const float* __restrict__ wA,
                           const float* __restrict__ wB,
                           __nv_bfloat16* __restrict__ oA,
                           __nv_bfloat16* __restrict__ oB) {
    int pl = blockIdx.z;
    int br = pl >= BATCH * 288;
    int rem = pl - br * BATCH * 288;
    int c = rem % 288;
    const __nv_bfloat16* ip = (br ? qB : qA) + (size_t)rem * HW;
    const float* wp = (br ? wB : wA) + c * 9;
    __nv_bfloat16* op = (br ? oB : oA) + (size_t)rem * HW;

    int x0 = (blockIdx.x * 32 + threadIdx.x) * 4;
    int y0 = (blockIdx.y * 8 + threadIdx.y) * 2;

    float w[9];
#pragma unroll
    for (int i = 0; i < 9; i++) w[i] = wp[i];

    float a0[4] = {0.f, 0.f, 0.f, 0.f};
    float a1[4] = {0.f, 0.f, 0.f, 0.f};
#pragma unroll
    for (int dy = -1; dy <= 2; dy++) {
        int yy = y0 + dy;
        if (yy < 0 || yy >= IMG) continue;
        const __nv_bfloat16* row = ip + yy * IMG;
        float v[6];
        v[0] = (x0 > 0) ? __bfloat162float(row[x0 - 1]) : 0.f;
        {
            const __nv_bfloat162* r2 = reinterpret_cast<const __nv_bfloat162*>(row + x0);
            float2 a = __bfloat1622float2(r2[0]);
            float2 b = __bfloat1622float2(r2[1]);
            v[1] = a.x; v[2] = a.y; v[3] = b.x; v[4] = b.y;
        }
        v[5] = (x0 + 4 < IMG) ? __bfloat162float(row[x0 + 4]) : 0.f;
        if (dy <= 1) {
            const float* wr = w + (dy + 1) * 3;
#pragma unroll
            for (int j = 0; j < 4; j++)
                a0[j] += wr[0] * v[j] + wr[1] * v[j + 1] + wr[2] * v[j + 2];
        }
        if (dy >= 0) {
            const float* wr = w + dy * 3;
#pragma unroll
            for (int j = 0; j < 4; j++)
                a1[j] += wr[0] * v[j] + wr[1] * v[j + 1] + wr[2] * v[j + 2];
        }
    }

    *reinterpret_cast<__nv_bfloat162*>(op + y0 * IMG + x0)     = __floats2bfloat162_rn(a0[0], a0[1]);
    *reinterpret_cast<__nv_bfloat162*>(op + y0 * IMG + x0 + 2) = __floats2bfloat162_rn(a0[2], a0[3]);
    *reinterpret_cast<__nv_bfloat162*>(op + (y0 + 1) * IMG + x0)     = __floats2bfloat162_rn(a1[0], a1[1]);
    *reinterpret_cast<__nv_bfloat162*>(op + (y0 + 1) * IMG + x0 + 2) = __floats2bfloat162_rn(a1[2], a1[3]);
}

// ---------------------------------------------------------------------------
// Fused FFN tail (unchanged).
// ---------------------------------------------------------------------------
__global__ void dwgate_kernel(const __nv_bfloat16* __restrict__ t,
                              const float* __restrict__ dwf,
                              __nv_bfloat16* __restrict__ gate) {
    int pl = blockIdx.z;
    int b = pl / HIDDEN, k = pl % HIDDEN;
    int x0 = (blockIdx.x * 32 + threadIdx.x) * 4;
    int y0 = (blockIdx.y * 8 + threadIdx.y) * 2;
    const __nv_bfloat16* i1 = t + ((size_t)b * 2 * HIDDEN + k) * HW;
    const __nv_bfloat16* i2 = t + ((size_t)b * 2 * HIDDEN + HIDDEN + k) * HW;
    const float* w1 = dwf + k * 9;
    const float* w2 = dwf + (HIDDEN + k) * 9;

    float wa[9], wb[9];
#pragma unroll
    for (int i = 0; i < 9; i++) { wa[i] = w1[i]; wb[i] = w2[i]; }

    float s1r0[4] = {0.f, 0.f, 0.f, 0.f}, s2r0[4] = {0.f, 0.f, 0.f, 0.f};
    float s1r1[4] = {0.f, 0.f, 0.f, 0.f}, s2r1[4] = {0.f, 0.f, 0.f, 0.f};
#pragma unroll
    for (int dy = -1; dy <= 2; dy++) {
        int yy = y0 + dy;
        if (yy < 0 || yy >= IMG) continue;
        const __nv_bfloat16* r1 = i1 + yy * IMG;
        const __nv_bfloat16* r2 = i2 + yy * IMG;
        float v1[6], v2[6];
        v1[0] = (x0 > 0) ? __bfloat162float(r1[x0 - 1]) : 0.f;
        v2[0] = (x0 > 0) ? __bfloat162float(r2[x0 - 1]) : 0.f;
        {
            const __nv_bfloat162* p1 = reinterpret_cast<const __nv_bfloat162*>(r1 + x0);
            const __nv_bfloat162* p2 = reinterpret_cast<const __nv_bfloat162*>(r2 + x0);
            float2 a1 = __bfloat1622float2(p1[0]), b1 = __bfloat1622float2(p1[1]);
            float2 a2 = __bfloat1622float2(p2[0]), b2 = __bfloat1622float2(p2[1]);
            v1[1] = a1.x; v1[2] = a1.y; v1[3] = b1.x; v1[4] = b1.y;
            v2[1] = a2.x; v2[2] = a2.y; v2[3] = b2.x; v2[4] = b2.y;
        }
        v1[5] = (x0 + 4 < IMG) ? __bfloat162float(r1[x0 + 4]) : 0.f;
        v2[5] = (x0 + 4 < IMG) ? __bfloat162float(r2[x0 + 4]) : 0.f;
        if (dy <= 1) {
            const float* wra = wa + (dy + 1) * 3;
            const float* wrb = wb + (dy + 1) * 3;
#pragma unroll
            for (int j = 0; j < 4; j++) {
                s1r0[j] += wra[0] * v1[j] + wra[1] * v1[j + 1] + wra[2] * v1[j + 2];
                s2r0[j] += wrb[0] * v2[j] + wrb[1] * v2[j + 1] + wrb[2] * v2[j + 2];
            }
        }
        if (dy >= 0) {
            const float* wra = wa + dy * 3;
            const float* wrb = wb + dy * 3;
#pragma unroll
            for (int j = 0; j < 4; j++) {
                s1r1[j] += wra[0] * v1[j] + wra[1] * v1[j + 1] + wra[2] * v1[j + 2];
                s2r1[j] += wrb[0] * v2[j] + wrb[1] * v2[j + 1] + wrb[2] * v2[j + 2];
            }
        }
    }

    float o0[4], o1[4];
#pragma unroll
    for (int j = 0; j < 4; j++) {
        float gl0 = 0.5f * s1r0[j] * (1.f + erff(s1r0[j] * 0.7071067811865475f));
        o0[j] = gl0 * s2r0[j];
        float gl1 = 0.5f * s1r1[j] * (1.f + erff(s1r1[j] * 0.7071067811865475f));
        o1[j] = gl1 * s2r1[j];
    }
    __nv_bfloat16* gp0 = gate + ((size_t)b * 288 + k) * HW + y0 * IMG + x0;
    __nv_bfloat16* gp1 = gp0 + IMG;
    *reinterpret_cast<__nv_bfloat162*>(gp0)     = __floats2bfloat162_rn(o0[0], o0[1]);
    *reinterpret_cast<__nv_bfloat162*>(gp0 + 2) = __floats2bfloat162_rn(o0[2], o0[3]);
    *reinterpret_cast<__nv_bfloat162*>(gp1)     = __floats2bfloat162_rn(o1[0], o1[1]);
    *reinterpret_cast<__nv_bfloat162*>(gp1 + 2) = __floats2bfloat162_rn(o1[2], o1[3]);
}

// ---------------------------------------------------------------------------
// Gram stage 1, quadrant split, uint2 loads (unchanged).
// ---------------------------------------------------------------------------
__global__ void __launch_bounds__(256, 2) gram1_kernel(
        const __nv_bfloat16* __restrict__ qkvAd,
        const __nv_bfloat16* __restrict__ qkvBd,
        float* __restrict__ gpA, float* __restrict__ gpB) {
    int bx = blockIdx.x;
    int chunk = bx >> 2;
    int quad  = bx & 3;
    int qh = quad >> 1;
    int kh = quad & 1;
    int h = blockIdx.y;
    int b  = blockIdx.z >> 1;
    int br = blockIdx.z & 1;
    const __nv_bfloat16* qb = (br ? qkvAd : qkvBd) + ((size_t)b * 288 + h * CHEAD + qh * 6) * HW;
    const __nv_bfloat16* kb = (br ? qkvBd : qkvAd) + ((size_t)b * 288 + 96 + h * CHEAD + kh * 6) * HW;
    float* part = br ? gpB : gpA;

    float acc[36];
#pragma unroll
    for (int i = 0; i < 36; i++) acc[i] = 0.f;
    float qsq[6] = {0.f, 0.f, 0.f, 0.f, 0.f, 0.f};
    float ksq[6] = {0.f, 0.f, 0.f, 0.f, 0.f, 0.f};

    int p0 = chunk * 2048 + threadIdx.x * 4;
#pragma unroll
    for (int it = 0; it < 2; it++) {
        int p = p0 + it * 1024;
        float2 qv[6][2], kv[6][2];
#pragma unroll
        for (int c = 0; c < 6; c++) {
            uint2 u = *reinterpret_cast<const uint2*>(qb + (size_t)c * HW + p);
            qv[c][0] = __bfloat1622float2(*reinterpret_cast<__nv_bfloat162*>(&u.x));
            qv[c][1] = __bfloat1622float2(*reinterpret_cast<__nv_bfloat162*>(&u.y));
        }
#pragma unroll
        for (int d = 0; d < 6; d++) {
            uint2 u = *reinterpret_cast<const uint2*>(kb + (size_t)d * HW + p);
            kv[d][0] = __bfloat1622float2(*reinterpret_cast<__nv_bfloat162*>(&u.x));
            kv[d][1] = __bfloat1622float2(*reinterpret_cast<__nv_bfloat162*>(&u.y));
        }
#pragma unroll
        for (int c = 0; c < 6; c++)
#pragma unroll
            for (int d = 0; d < 6; d++)
                acc[c * 6 + d] += qv[c][0].x * kv[d][0].x + qv[c][0].y * kv[d][0].y
                                + qv[c][1].x * kv[d][1].x + qv[c][1].y * kv[d][1].y;
#pragma unroll
        for (int c = 0; c < 6; c++)
            qsq[c] += qv[c][0].x * qv[c][0].x + qv[c][0].y * qv[c][0].y
                    + qv[c][1].x * qv[c][1].x + qv[c][1].y * qv[c][1].y;
#pragma unroll
        for (int d = 0; d < 6; d++)
            ksq[d] += kv[d][0].x * kv[d][0].x + kv[d][0].y * kv[d][0].y
                    + kv[d][1].x * kv[d][1].x + kv[d][1].y * kv[d][1].y;
    }

    int warp = threadIdx.x >> 5;
    int lane = threadIdx.x & 31;
    float* outp = part + ((((size_t)(b * HEADS + h)) * 128 + bx) * 8 + warp) * 48;
#pragma unroll
    for (int i = 0; i < 48; i++) {
        float v = (i < 36) ? acc[i] : (i < 42 ? qsq[i - 36] : ksq[i - 42]);
#pragma unroll
        for (int off = 16; off > 0; off >>= 1)
            v += __shfl_down_sync(0xffffffffu, v, off);
        if (lane == 0) outp[i] = v;
    }
}

// ---------------------------------------------------------------------------
// Gram stage 2 + norms + temp + softmax (unchanged).
// ---------------------------------------------------------------------------
__global__ void attn_kernel(const float* __restrict__ partA,
                            const float* __restrict__ partB,
                            const float* __restrict__ temp,
                            float* __restrict__ attnA,
                            float* __restrict__ attnB) {
    int bh = blockIdx.x;
    int h = bh % HEADS;
    __shared__ float GA[144], GB[144];
    __shared__ float nqA[12], nkA[12], nqB[12], nkB[12];
    int i = threadIdx.x;
    float sA = 0.f, sB = 0.f;
    if (i < 168) {
        int quad, off;
        if (i < 144) {
            int c = i / CHEAD, d = i % CHEAD;
            quad = (c / 6) * 2 + (d / 6);
            off  = (c % 6) * 6 + (d % 6);
        } else if (i < 156) {
            int c = i - 144;
            quad = (c / 6) * 2;
            off  = 36 + (c % 6);
        } else {
            int d = i - 156;
            quad = (d / 6);
            off  = 42 + (d % 6);
        }
        const float* pA = partA + (((size_t)bh * 128 + quad) * 8) * 48 + off;
        const float* pB = partB + (((size_t)bh * 128 + quad) * 8) * 48 + off;
        for (int ch = 0; ch < 32; ch++) {
#pragma unroll
            for (int w = 0; w < 8; w++) {
                size_t o = (size_t)ch * (4 * 8 * 48) + (size_t)w * 48;
                sA += pA[o];
                sB += pB[o];
            }
        }
        if (i >= 156) {
            nkA[i - 156] = fmaxf(sqrtf(sA), 1e-12f);
            nkB[i - 156] = fmaxf(sqrtf(sB), 1e-12f);
        } else if (i >= 144) {
            nqA[i - 144] = fmaxf(sqrtf(sA), 1e-12f);
            nqB[i - 144] = fmaxf(sqrtf(sB), 1e-12f);
        }
    }
    __syncthreads();
    if (i < 144) {
        int c = i / CHEAD, d = i % CHEAD;
        float tp = temp[h];
        GA[i] =  sA / (nqA[c] * nkA[d]) * tp;
        GB[i] = -sB / (nqB[c] * nkB[d]) * tp;
    }
    __syncthreads();
    if (i < 24) {
        float* G = (i < CHEAD) ? GA : GB;
        float* O = (i < CHEAD) ? attnA : attnB;
        int c = i % CHEAD;
        float mx = -1e30f;
        for (int d = 0; d < CHEAD; d++) mx = fmaxf(mx, G[c * CHEAD + d]);
        float e[CHEAD];
        float s = 0.f;
        for (int d = 0; d < CHEAD; d++) {
            e[d] = expf(G[c * CHEAD + d] - mx);
            s += e[d];
        }
        float inv = 1.f / s;
        for (int d = 0; d < CHEAD; d++)
            O[(size_t)bh * 144 + c * CHEAD + d] = e[d] * inv;
    }
}

// ---------------------------------------------------------------------------
// cw_pk (unchanged).
// ---------------------------------------------------------------------------
__global__ void cw_kernel(const float* __restrict__ P0,
                          const float* __restrict__ P1,
                          const float* __restrict__ atA,
                          const float* __restrict__ atB,
                          uint32_t* __restrict__ cwApk,
                          uint32_t* __restrict__ cwBpk) {
    int b  = blockIdx.x >> 1;
    int br = blockIdx.x & 1;
    const float* P  = br ? P1 : P0;
    const float* at = (br ? atB : atA) + (size_t)b * HEADS * 144;
    uint32_t* out = (br ? cwBpk : cwApk) + (size_t)b * 9216;
    __shared__ float a_s[HEADS * 144];
    for (int i = threadIdx.x; i < HEADS * 144; i += blockDim.x) a_s[i] = at[i];
    __syncthreads();
    int base = blockIdx.y * 1536;
#pragma unroll
    for (int r = 0; r < 6; r++) {
        int o = base + r * 256 + threadIdx.x;
        int m = o / 96, n = o % 96;
        int h = n / CHEAD, d = n % CHEAD;
        float s = 0.f;
#pragma unroll
        for (int c = 0; c < CHEAD; c++)
            s += P[m * 96 + h * CHEAD + c] * a_s[h * 144 + c * CHEAD + d];
        out[a_pack_off(m, n)] = f2tf(s);
    }
}

// ---------------------------------------------------------------------------
// Launch
// ---------------------------------------------------------------------------
extern "C" void kernel_launch(void* const* d_in, const int* in_sizes, int n_in,
                              void* d_out, int out_size) {
    const float* x       = (const float*)d_in[0];
    const float* y       = (const float*)d_in[1];
    const float* ln1_w   = (const float*)d_in[2];
    const float* ln1_b   = (const float*)d_in[3];
    const float* ln2_w   = (const float*)d_in[4];
    const float* ln2_b   = (const float*)d_in[5];
    const float* qkvA_w  = (const float*)d_in[6];
    const float* dwA_w   = (const float*)d_in[7];
    const float* qkvB_w  = (const float*)d_in[8];
    const float* dwB_w   = (const float*)d_in[9];
    const float* projA_w = (const float*)d_in[10];
    const float* projB_w = (const float*)d_in[11];
    const float* concat_w= (const float*)d_in[12];
    const float* temp    = (const float*)d_in[13];
    const float* pin_w   = (const float*)d_in[14];
    const float* dwf_w   = (const float*)d_in[15];
    const float* pout_w  = (const float*)d_in[16];
    float* out = (float*)d_out;

    cudaFuncSetAttribute(gemm96,   cudaFuncAttributeMaxDynamicSharedMemorySize, G96_SMEM_BYTES);
    cudaFuncSetAttribute(gemmPout, cudaFuncAttributeMaxDynamicSharedMemorySize, POUT_SMEM_BYTES);
    cudaFuncSetAttribute(gemm4_tc, cudaFuncAttributeMaxDynamicSharedMemorySize, G4_SMEM_BYTES);

    __nv_bfloat16 *qkvA, *qkvAd, *qkvB, *qkvBd, *t, *gate, *xn, *yn;
    float *x1, *gpA, *gpB, *atA, *atB, *P0, *P1;
    uint32_t *prepQA, *prepQB, *prepPin, *prepPout_p, *prepC0, *prepC1, *cwApk, *cwBpk;
    float *sQA, *tQA, *sQB, *tQB, *sPin, *tPin;
    cudaGetSymbolAddress((void**)&qkvA,   g_qkvA);
    cudaGetSymbolAddress((void**)&qkvAd,  g_qkvAd);
    cudaGetSymbolAddress((void**)&qkvB,   g_qkvB);
    cudaGetSymbolAddress((void**)&qkvBd,  g_qkvBd);
    cudaGetSymbolAddress((void**)&xn,     g_xn);
    cudaGetSymbolAddress((void**)&yn,     g_yn);
    cudaGetSymbolAddress((void**)&t,      g_t);
    cudaGetSymbolAddress((void**)&gate,   g_gate);
    cudaGetSymbolAddress((void**)&x1,     g_x1);
    cudaGetSymbolAddress((void**)&gpA,    g_gpartA);
    cudaGetSymbolAddress((void**)&gpB,    g_gpartB);
    cudaGetSymbolAddress((void**)&atA,    g_attnA);
    cudaGetSymbolAddress((void**)&atB,    g_attnB);
    cudaGetSymbolAddress((void**)&P0,     g_P0);
    cudaGetSymbolAddress((void**)&P1,     g_P1);
    cudaGetSymbolAddress((void**)&prepQA,   g_prepQA);
    cudaGetSymbolAddress((void**)&prepQB,   g_prepQB);
    cudaGetSymbolAddress((void**)&prepPin,  g_prepPin);
    cudaGetSymbolAddress((void**)&prepPout_p, g_prepPout);
    cudaGetSymbolAddress((void**)&prepC0,   g_prepC0);
    cudaGetSymbolAddress((void**)&prepC1,   g_prepC1);
    cudaGetSymbolAddress((void**)&cwApk,    g_cwApk);
    cudaGetSymbolAddress((void**)&cwBpk,    g_cwBpk);
    cudaGetSymbolAddress((void**)&sQA,    g_sQA);
    cudaGetSymbolAddress((void**)&tQA,    g_tQA);
    cudaGetSymbolAddress((void**)&sQB,    g_sQB);
    cudaGetSymbolAddress((void**)&tQB,    g_tQB);
    cudaGetSymbolAddress((void**)&sPin,   g_sPin);
    cudaGetSymbolAddress((void**)&tPin,   g_tPin);

    const size_t P96   = (size_t)CDIM * HW;       // fp32 batch stride
    const size_t P96E  = (size_t)CDIM * HW;       // bf16 element stride (xn/yn)
    const size_t P288E = (size_t)3 * CDIM * HW;
    const size_t P510E = (size_t)2 * HIDDEN * HW;
    const size_t PGATE = (size_t)288 * HW;

    megaprep<<<53, 256>>>(qkvA_w, qkvB_w, pin_w, pout_w, concat_w,
                          projA_w, projB_w, ln1_w, ln1_b, ln2_w, ln2_b,
                          prepQA, prepQB, prepPin, prepPout_p, prepC0, prepC1,
                          sQA, tQA, sQB, tQB, sPin, tPin, P0, P1);

    // qkv for both branches; also emits bf16 xn/yn for gemm4
    {
        G96P p;
        p.Apk[0] = prepQA; p.Apk[1] = prepQB;
        p.sv[0] = sQA; p.sv[1] = sQB;
        p.tv[0] = tQA; p.tv[1] = tQB;
        p.X[0] = x; p.X[1] = y;
        p.xnOut[0] = xn; p.xnOut[1] = yn;
        p.Y[0] = qkvA; p.Y[1] = qkvB;
        p.lnw = ln1_w; p.lnb = ln1_b;
        dim3 g(1, HW / 128, BATCH * 2);
        gemm96<<<g, 256, G96_SMEM_BYTES>>>(p, 288, 2, 3, P96, P288E);
    }

    // depthwise 3x3, both branches, 2 rows/thread
    {
        dim3 blk(32, 8), g(IMG / 128, IMG / 16, 2 * BATCH * 288);
        dw3_kernel<<<g, blk>>>(qkvA, qkvB, dwA_w, dwB_w, qkvAd, qkvBd);
    }

    // Gram quadrants + fused norms, both branches
    {
        dim3 g(128, HEADS, 2 * BATCH);
        gram1_kernel<<<g, 256>>>(qkvAd, qkvBd, gpA, gpB);
    }

    attn_kernel<<<BATCH * HEADS, 192>>>(gpA, gpB, temp, atA, atB);
    {
        dim3 g(4, 6);
        cw_kernel<<<g, 256>>>(P0, P1, atA, atB, cwApk, cwBpk);
    }

    // fused x1 = x + cwA@vA + cwB@vB + C0@xn + C1@yn  (all-bf16 sources)
    {
        G4 p;
        p.Apk[0] = cwApk;  p.aBatch[0] = 9216;
        p.Apk[1] = cwBpk;  p.aBatch[1] = 9216;
        p.Apk[2] = prepC0; p.aBatch[2] = 0;
        p.Apk[3] = prepC1; p.aBatch[3] = 0;
        p.X[0] = qkvAd + 192 * (size_t)HW; p.xBatch[0] = P288E;
        p.X[1] = qkvBd + 192 * (size_t)HW; p.xBatch[1] = P288E;
        p.X[2] = xn;                       p.xBatch[2] = P96E;
        p.X[3] = yn;                       p.xBatch[3] = P96E;
        dim3 g(1, HW / 128, BATCH);
        gemm4_tc<<<g, 256, G4_SMEM_BYTES>>>(p, x, x1);
    }

    // pin = W@LN2(x1), B-resident with 6 m-tiles in-block (no xn emission)
    {
        G96P p;
        p.Apk[0] = prepPin; p.Apk[1] = prepPin;
        p.sv[0] = sPin; p.sv[1] = sPin;
        p.tv[0] = tPin; p.tv[1] = tPin;
        p.X[0] = x1; p.X[1] = x1;
        p.xnOut[0] = nullptr; p.xnOut[1] = nullptr;
        p.Y[0] = t; p.Y[1] = t;
        p.lnw = ln2_w; p.lnb = ln2_b;
        dim3 g(1, HW / 128, BATCH);
        gemm96<<<g, 256, G96_SMEM_BYTES>>>(p, 510, 1, 6, P96, P510E);
    }

    // fused depthwise + gelu gate, 2 rows/thread
    {
        dim3 blk(32, 8), g(IMG / 128, IMG / 16, BATCH * HIDDEN);
        dwgate_kernel<<<g, blk>>>(t, dwf_w, gate);
    }

    // pout + residual x1 -> output
    {
        dim3 g(1, HW / 128, BATCH);
        gemmPout<<<g, 256, POUT_SMEM_BYTES>>>(prepPout_p, gate, x1, out,
                                              PGATE, P96, P96);
    }
}

// round 14
// speedup vs baseline: 5.1564x; 1.0290x over previous
#include <cuda_runtime.h>
#include <cuda_bf16.h>
#include <math.h>
#include <stdint.h>

#define HW      65536
#define IMG     256
#define BATCH   2
#define CDIM    96
#define HEADS   8
#define CHEAD   12
#define HIDDEN  255

// ---------------------------------------------------------------------------
// Scratch
// ---------------------------------------------------------------------------
__device__ __nv_bfloat16 g_qkvA [BATCH * 3 * CDIM * HW];
__device__ __nv_bfloat16 g_qkvAd[BATCH * 3 * CDIM * HW];
__device__ __nv_bfloat16 g_qkvB [BATCH * 3 * CDIM * HW];
__device__ __nv_bfloat16 g_qkvBd[BATCH * 3 * CDIM * HW];
__device__ __nv_bfloat16 g_xn   [BATCH * CDIM * HW];
__device__ __nv_bfloat16 g_yn   [BATCH * CDIM * HW];
__device__ __nv_bfloat16 g_t    [BATCH * 2 * HIDDEN * HW];
__device__ __nv_bfloat16 g_gate [BATCH * 288 * HW];   // 288-pitch; rows 255..287 stay zero
__device__ float g_x1   [BATCH * CDIM * HW];
// Gram partials: [bh][chunk*4+quad][warp][48]
__device__ float g_gpartA[BATCH * HEADS * 128 * 8 * 48];
__device__ float g_gpartB[BATCH * HEADS * 128 * 8 * 48];
__device__ float g_P0  [CDIM * CDIM];
__device__ float g_P1  [CDIM * CDIM];
// prepacked tf32 fragment tiles
__device__ uint32_t g_prepQA  [3 * 9216];
__device__ uint32_t g_prepQB  [3 * 9216];
__device__ uint32_t g_prepPin [6 * 9216];
__device__ uint32_t g_prepPout[3 * 9216];
__device__ uint32_t g_prepC0  [9216];
__device__ uint32_t g_prepC1  [9216];
__device__ uint32_t g_cwApk   [BATCH * 9216];
__device__ uint32_t g_cwBpk   [BATCH * 9216];
__device__ float g_sQA[288],  g_tQA[288];
__device__ float g_sQB[288],  g_tQB[288];
__device__ float g_sPin[576], g_tPin[576];

// ---------------------------------------------------------------------------
// tf32 / cp.async helpers
// ---------------------------------------------------------------------------
__device__ __forceinline__ uint32_t f2tf(float f) {
    uint32_t u;
    asm("cvt.rna.tf32.f32 %0, %1;" : "=r"(u) : "f"(f));
    return u;
}

__device__ __forceinline__ void mma_tf32(float* c, const uint32_t* a, const uint32_t* b) {
    asm volatile(
        "mma.sync.aligned.m16n8k8.row.col.f32.tf32.tf32.f32 "
        "{%0,%1,%2,%3}, {%4,%5,%6,%7}, {%8,%9}, {%0,%1,%2,%3};"
        : "+f"(c[0]), "+f"(c[1]), "+f"(c[2]), "+f"(c[3])
        : "r"(a[0]), "r"(a[1]), "r"(a[2]), "r"(a[3]), "r"(b[0]), "r"(b[1]));
}

__device__ __forceinline__ void cp16(void* smem, const void* gmem) {
    uint32_t a = (uint32_t)__cvta_generic_to_shared(smem);
    asm volatile("cp.async.cg.shared.global [%0], [%1], 16;\n" :: "r"(a), "l"(gmem));
}
#define CP_COMMIT()  asm volatile("cp.async.commit_group;\n")
#define CP_WAIT(n)   asm volatile("cp.async.wait_group %0;\n" :: "n"(n))

__device__ __forceinline__ int a_pack_off(int m, int k) {
    return (k >> 3) * 768 + (m >> 4) * 128 + (m & 7) * 16 + (k & 3) * 4
         + ((k >> 2) & 1) * 2 + ((m >> 3) & 1);
}

// unpack uint4 (8 bf16) -> 8 floats via bit shifts
__device__ __forceinline__ void unpack8(float* f, uint4 u) {
    f[0] = __uint_as_float(u.x << 16); f[1] = __uint_as_float(u.x & 0xFFFF0000u);
    f[2] = __uint_as_float(u.y << 16); f[3] = __uint_as_float(u.y & 0xFFFF0000u);
    f[4] = __uint_as_float(u.z << 16); f[5] = __uint_as_float(u.z & 0xFFFF0000u);
    f[6] = __uint_as_float(u.w << 16); f[7] = __uint_as_float(u.w & 0xFFFF0000u);
}

// gemm4: A tile + full B panel
#define G4_SMEM_WORDS   (9216 + 96*136)
#define G4_SMEM_BYTES   (G4_SMEM_WORDS * 4)
// gemm96: full B panel + one A tile + stats + ln vectors
#define G96_SMEM_WORDS  (96*136 + 9216 + 256 + 192)
#define G96_SMEM_BYTES  (G96_SMEM_WORDS * 4)
// pout: double-buffered 32-row B ring
#define POUT_SMEM_WORDS (9216 + 2*32*136)
#define POUT_SMEM_BYTES (POUT_SMEM_WORDS * 4)

// ---------------------------------------------------------------------------
// Mega-prep (unchanged).
// ---------------------------------------------------------------------------
__device__ void prep_tile(const float* __restrict__ W, int M, int tile,
                          const float* __restrict__ wln,
                          const float* __restrict__ bln,
                          uint32_t* __restrict__ Apk,
                          float* __restrict__ svec, float* __restrict__ tvec,
                          float* wls, float* bls) {
    int m0 = tile * 96;
    if (threadIdx.x < 96) { wls[threadIdx.x] = wln[threadIdx.x]; bls[threadIdx.x] = bln[threadIdx.x]; }
    __syncthreads();
#pragma unroll
    for (int i = 0; i < 36; i++) {
        int idx = threadIdx.x + i * 256;
        int m = idx / 96;
        int k = idx - m * 96;
        float v = 0.f;
        if (m0 + m < M) v = W[(size_t)(m0 + m) * 96 + k] * wls[k];
        Apk[tile * 9216 + a_pack_off(m, k)] = f2tf(v);
    }
    if (threadIdx.x < 96) {
        int gm = m0 + threadIdx.x;
        float s = 0.f, tt = 0.f;
        if (gm < M) {
            for (int k = 0; k < 96; k++) {
                float w = W[(size_t)gm * 96 + k];
                s  += w * wls[k];
                tt += w * bls[k];
            }
        }
        svec[tile * 96 + threadIdx.x] = s;
        tvec[tile * 96 + threadIdx.x] = tt;
    }
}

__global__ void megaprep(
        const float* __restrict__ qkvA_w, const float* __restrict__ qkvB_w,
        const float* __restrict__ pin_w,  const float* __restrict__ pout_w,
        const float* __restrict__ concat_w,
        const float* __restrict__ projA_w, const float* __restrict__ projB_w,
        const float* __restrict__ ln1_w, const float* __restrict__ ln1_b,
        const float* __restrict__ ln2_w, const float* __restrict__ ln2_b,
        uint32_t* __restrict__ prepQA, uint32_t* __restrict__ prepQB,
        uint32_t* __restrict__ prepPin, uint32_t* __restrict__ prepPout,
        uint32_t* __restrict__ prepC0, uint32_t* __restrict__ prepC1,
        float* __restrict__ sQA, float* __restrict__ tQA,
        float* __restrict__ sQB, float* __restrict__ tQB,
        float* __restrict__ sPin, float* __restrict__ tPin,
        float* __restrict__ P0, float* __restrict__ P1) {
    __shared__ float sbuf[96 * 96];
    int bid = blockIdx.x;
    if (bid < 3) {
        prep_tile(qkvA_w, 288, bid, ln1_w, ln1_b, prepQA, sQA, tQA, sbuf, sbuf + 96);
    } else if (bid < 6) {
        prep_tile(qkvB_w, 288, bid - 3, ln1_w, ln1_b, prepQB, sQB, tQB, sbuf, sbuf + 96);
    } else if (bid < 12) {
        prep_tile(pin_w, 510, bid - 6, ln2_w, ln2_b, prepPin, sPin, tPin, sbuf, sbuf + 96);
    } else if (bid < 15) {
        int s = bid - 12;
#pragma unroll
        for (int i = 0; i < 36; i++) {
            int idx = threadIdx.x + i * 256;
            int m = idx / 96;
            int k = idx - m * 96;
            int kg = s * 96 + k;
            float v = (kg < HIDDEN) ? pout_w[(size_t)m * HIDDEN + kg] : 0.f;
            prepPout[s * 9216 + a_pack_off(m, k)] = f2tf(v);
        }
    } else if (bid < 17) {
        const float* W = concat_w + (bid == 16 ? 96 : 0);
        uint32_t* out = (bid == 16) ? prepC1 : prepC0;
#pragma unroll
        for (int i = 0; i < 36; i++) {
            int idx = threadIdx.x + i * 256;
            int m = idx / 96;
            int k = idx - m * 96;
            out[a_pack_off(m, k)] = f2tf(W[(size_t)m * 192 + k]);
        }
    } else {
        int w = bid - 17;
        int br = w & 1;
        int yt = w >> 1;
        const float* proj = br ? projB_w : projA_w;
        const float* cw   = concat_w + (br ? 96 : 0);
        float* P = br ? P1 : P0;
        for (int i = threadIdx.x; i < 96 * 96; i += 256) sbuf[i] = proj[i];
        __syncthreads();
        int base = yt * 512;
#pragma unroll
        for (int r = 0; r < 2; r++) {
            int o = base + r * 256 + threadIdx.x;
            int m = o / 96, n = o % 96;
            float s = 0.f;
#pragma unroll 8
            for (int c = 0; c < 96; c++) s += cw[m * 192 + c] * sbuf[c * 96 + n];
            P[o] = s;
        }
    }
}

// ---------------------------------------------------------------------------
// 32-k MMA chunk on the 96x128 tile.
// ---------------------------------------------------------------------------
__device__ __forceinline__ void g96_chunk(
        float acc[3][4][4], const uint32_t* __restrict__ As,
        const uint32_t* __restrict__ Bbuf,
        int kc, int g, int t, int wmi, int wn) {
#pragma unroll
    for (int ks2 = 0; ks2 < 4; ks2++) {
        const uint32_t* Ab = As + (kc * 4 + ks2) * 768 + g * 16 + t * 4;
        const uint32_t* Bb = Bbuf + (ks2 * 8 + t) * 136 + wn + g;
        uint4 a4[3];
        uint32_t bf[4][2];
#pragma unroll
        for (int mi = 0; mi < 3; mi++)
            a4[mi] = *reinterpret_cast<const uint4*>(Ab + (wmi + mi) * 128);
#pragma unroll
        for (int ni = 0; ni < 4; ni++) {
            bf[ni][0] = Bb[ni * 8];
            bf[ni][1] = Bb[4 * 136 + ni * 8];
        }
#pragma unroll
        for (int mi = 0; mi < 3; mi++) {
            uint32_t af[4] = {a4[mi].x, a4[mi].y, a4[mi].z, a4[mi].w};
#pragma unroll
            for (int ni = 0; ni < 4; ni++)
                mma_tf32(acc[mi][ni], af, bf[ni]);
        }
    }
}

// ---------------------------------------------------------------------------
// B-resident multi-M gemm96 + optional bf16 LN(x) emission (unchanged).
// ---------------------------------------------------------------------------
struct G96P {
    const uint32_t* Apk[2];
    const float*    sv[2];
    const float*    tv[2];
    const float*    X[2];
    __nv_bfloat16*  xnOut[2];    // may be null
    __nv_bfloat16*  Y[2];
    const float*    lnw;
    const float*    lnb;
};

__global__ void __launch_bounds__(256, 2) gemm96(
        G96P p, int M, int NB, int Mtiles, size_t xBatch, size_t yBatch) {
    extern __shared__ uint32_t sm[];
    uint32_t* Bs = sm;                       // 96*136 = 13056
    uint32_t* As = sm + 13056;               // 9216
    float* mu_s  = (float*)(sm + 13056 + 9216);
    float* inv_s = mu_s + 128;
    float* wl_s  = inv_s + 128;              // 96
    float* bl_s  = wl_s + 96;                // 96

    int z  = blockIdx.z;
    int br = z % NB;
    int bz = z / NB;
    const float* Xb = p.X[br] + (size_t)bz * xBatch;
    __nv_bfloat16* Yb = p.Y[br] + (size_t)bz * yBatch;
    const float* svec = p.sv[br];
    const float* tvec = p.tv[br];
    const uint32_t* Apk = p.Apk[br];
    bool hasXn = (p.xnOut[br] != nullptr);

    int n0 = blockIdx.y * 128;
    int tid  = threadIdx.x;
    int warp = tid >> 5;
    int lane = tid & 31;
    int g = lane >> 2;
    int t = lane & 3;
    int wm  = (warp >> 2) * 48;
    int wmi = (warp >> 2) * 3;
    int wn  = (warp & 3) * 32;

#define LOADA96(mt)                                                          \
    {                                                                        \
        const uint4* Ag = reinterpret_cast<const uint4*>(Apk + (size_t)(mt) * 9216); \
        _Pragma("unroll")                                                    \
        for (int i = 0; i < 9; i++) {                                        \
            int idx = tid + i * 256;                                         \
            cp16(As + idx * 4, Ag + idx);                                    \
        }                                                                    \
    }

#pragma unroll
    for (int j = 0; j < 12; j++) {
        int idx = tid + j * 256;
        int k = idx >> 5, n4 = idx & 31;
        cp16(Bs + k * 136 + n4 * 4, Xb + (size_t)k * HW + n0 + n4 * 4);
    }
    LOADA96(0);
    CP_COMMIT();
    if (hasXn && tid < 96) { wl_s[tid] = p.lnw[tid]; bl_s[tid] = p.lnb[tid]; }
    CP_WAIT(0);
    __syncthreads();

    if (tid < 128) {
        float csum = 0.f, csq = 0.f;
#pragma unroll 8
        for (int k = 0; k < 96; k++) {
            float v = __uint_as_float(Bs[k * 136 + tid]);
            csum += v; csq += v * v;
        }
        float mu  = csum * (1.f / 96.f);
        float var = csq * (1.f / 96.f) - mu * mu;
        mu_s[tid]  = mu;
        inv_s[tid] = rsqrtf(var + 1e-5f);
    }
    __syncthreads();

    if (hasXn) {
        __nv_bfloat16* xo = p.xnOut[br] + (size_t)bz * CDIM * HW + n0;
        int c2 = (tid & 63) * 2;
        int rb = tid >> 6;
        float m0v = mu_s[c2],     i0 = inv_s[c2];
        float m1v = mu_s[c2 + 1], i1 = inv_s[c2 + 1];
#pragma unroll
        for (int it = 0; it < 24; it++) {
            int r = it * 4 + rb;
            float v0 = __uint_as_float(Bs[r * 136 + c2]);
            float v1 = __uint_as_float(Bs[r * 136 + c2 + 1]);
            float w = wl_s[r], bb = bl_s[r];
            *reinterpret_cast<__nv_bfloat162*>(xo + (size_t)r * HW + c2) =
                __floats2bfloat162_rn((v0 - m0v) * i0 * w + bb,
                                      (v1 - m1v) * i1 * w + bb);
        }
    }

    for (int mt = 0; mt < Mtiles; mt++) {
        int m0 = mt * 96;
        float acc[3][4][4];
#pragma unroll
        for (int mi = 0; mi < 3; mi++)
#pragma unroll
            for (int ni = 0; ni < 4; ni++)
#pragma unroll
                for (int r = 0; r < 4; r++) acc[mi][ni][r] = 0.f;

#pragma unroll
        for (int kc = 0; kc < 3; kc++)
            g96_chunk(acc, As, Bs + kc * 4352, kc, g, t, wmi, wn);

        __syncthreads();
        if (mt + 1 < Mtiles) {
            LOADA96(mt + 1);
            CP_COMMIT();
        }

#pragma unroll
        for (int mi = 0; mi < 3; mi++) {
            int r0 = m0 + wm + mi * 16 + g;
            int r1 = r0 + 8;
            float s0 = 0.f, t0 = 0.f, s1 = 0.f, t1 = 0.f;
            if (r0 < M) { s0 = svec[r0]; t0 = tvec[r0]; }
            if (r1 < M) { s1 = svec[r1]; t1 = tvec[r1]; }
#pragma unroll
            for (int ni = 0; ni < 4; ni++) {
                int ln = wn + ni * 8 + 2 * t;
                int col = n0 + ln;
                float i0 = inv_s[ln],     m0v = mu_s[ln]     * i0;
                float i1 = inv_s[ln + 1], m1v = mu_s[ln + 1] * i1;
                if (r0 < M) {
                    float vx = acc[mi][ni][0] * i0 - m0v * s0 + t0;
                    float vy = acc[mi][ni][1] * i1 - m1v * s0 + t0;
                    *reinterpret_cast<__nv_bfloat162*>(Yb + (size_t)r0 * HW + col) =
                        __floats2bfloat162_rn(vx, vy);
                }
                if (r1 < M) {
                    float vx = acc[mi][ni][2] * i0 - m0v * s1 + t1;
                    float vy = acc[mi][ni][3] * i1 - m1v * s1 + t1;
                    *reinterpret_cast<__nv_bfloat162*>(Yb + (size_t)r1 * HW + col) =
                        __floats2bfloat162_rn(vx, vy);
                }
            }
        }

        if (mt + 1 < Mtiles) {
            CP_WAIT(0);
            __syncthreads();
        }
    }
#undef LOADA96
}

// ---------------------------------------------------------------------------
// pout (unchanged).
// ---------------------------------------------------------------------------
__global__ void __launch_bounds__(256, 3) gemmPout(
        const uint32_t* __restrict__ Apk,
        const __nv_bfloat16* __restrict__ X,
        const float* __restrict__ Rsrc,
        float* __restrict__ Y,
        size_t xBatch, size_t yBatch, size_t rBatch) {
    extern __shared__ uint32_t sm[];
    uint32_t* As = sm;
    uint32_t* Bs = sm + 9216;

    int bz = blockIdx.z;
    const __nv_bfloat16* Xb = X + (size_t)bz * xBatch;
    float*       Yb = Y    + (size_t)bz * yBatch;
    const float* Rb = Rsrc + (size_t)bz * rBatch;

    int n0 = blockIdx.y * 128;
    int tid  = threadIdx.x;
    int warp = tid >> 5;
    int lane = tid & 31;
    int g = lane >> 2;
    int t = lane & 3;
    int wm  = (warp >> 2) * 48;
    int wmi = (warp >> 2) * 3;
    int wn  = (warp & 3) * 32;

    int kk = tid >> 3;
    int nb = (tid & 7) * 16;

    uint4 rA, rB;
#define LDGB(c)                                                             \
    {                                                                       \
        const uint4* src = reinterpret_cast<const uint4*>(                  \
            Xb + (size_t)((c) * 32 + kk) * HW + n0 + nb);                   \
        rA = src[0]; rB = src[1];                                           \
    }
#define STSB(c)                                                             \
    {                                                                       \
        uint32_t* dst = Bs + ((c) & 1) * 4352 + kk * 136 + nb;              \
        uint32_t u;                                                         \
        u = rA.x; dst[0]  = u << 16; dst[1]  = u & 0xFFFF0000u;             \
        u = rA.y; dst[2]  = u << 16; dst[3]  = u & 0xFFFF0000u;             \
        u = rA.z; dst[4]  = u << 16; dst[5]  = u & 0xFFFF0000u;             \
        u = rA.w; dst[6]  = u << 16; dst[7]  = u & 0xFFFF0000u;             \
        u = rB.x; dst[8]  = u << 16; dst[9]  = u & 0xFFFF0000u;             \
        u = rB.y; dst[10] = u << 16; dst[11] = u & 0xFFFF0000u;             \
        u = rB.z; dst[12] = u << 16; dst[13] = u & 0xFFFF0000u;             \
        u = rB.w; dst[14] = u << 16; dst[15] = u & 0xFFFF0000u;             \
    }
#define LOADA(s)                                                            \
    {                                                                       \
        const uint4* Ag = reinterpret_cast<const uint4*>(Apk + (s) * 9216); \
        _Pragma("unroll")                                                   \
        for (int i = 0; i < 9; i++) {                                       \
            int idx = tid + i * 256;                                        \
            cp16(As + idx * 4, Ag + idx);                                   \
        }                                                                   \
        CP_COMMIT();                                                        \
    }

    LOADA(0);
    LDGB(0);
    STSB(0);
    LDGB(1);
    CP_WAIT(0);
    __syncthreads();

    float acc[3][4][4];
#pragma unroll
    for (int mi = 0; mi < 3; mi++)
#pragma unroll
        for (int ni = 0; ni < 4; ni++)
#pragma unroll
            for (int r = 0; r < 4; r++) acc[mi][ni][r] = 0.f;

#pragma unroll
    for (int c = 0; c < 9; c++) {
        g96_chunk(acc, As, Bs + (c & 1) * 4352, c % 3, g, t, wmi, wn);
        if (c < 8) {
            __syncthreads();
            bool newA = (c % 3 == 2);
            if (newA) LOADA(c / 3 + 1);
            STSB(c + 1);
            if (c + 2 <= 8) LDGB(c + 2);
            if (newA) CP_WAIT(0);
            __syncthreads();
        }
    }
#undef LOADA
#undef LDGB
#undef STSB

#pragma unroll
    for (int mi = 0; mi < 3; mi++) {
        int r0 = wm + mi * 16 + g;
        int r1 = r0 + 8;
#pragma unroll
        for (int ni = 0; ni < 4; ni++) {
            int col = n0 + wn + ni * 8 + 2 * t;
            float2 ra = *reinterpret_cast<const float2*>(Rb + (size_t)r0 * HW + col);
            float2 rb = *reinterpret_cast<const float2*>(Rb + (size_t)r1 * HW + col);
            float2 v01 = make_float2(acc[mi][ni][0] + ra.x, acc[mi][ni][1] + ra.y);
            float2 v23 = make_float2(acc[mi][ni][2] + rb.x, acc[mi][ni][3] + rb.y);
            *reinterpret_cast<float2*>(Yb + (size_t)r0 * HW + col) = v01;
            *reinterpret_cast<float2*>(Yb + (size_t)r1 * HW + col) = v23;
        }
    }
}

// ---------------------------------------------------------------------------
// gemm4 v2 (unchanged from R13).
// ---------------------------------------------------------------------------
struct G4 {
    const uint32_t*      Apk[4];
    size_t               aBatch[4];
    const __nv_bfloat16* X[4];
    size_t               xBatch[4];
};

__global__ void __launch_bounds__(256, 2) gemm4_tc(
        G4 p,
        const float* __restrict__ Rsrc,
        float* __restrict__ Y) {
    extern __shared__ uint32_t smem_u[];
    uint32_t* As = smem_u;          // 9216
    uint32_t* Bs = As + 9216;       // 13056

    int bz = blockIdx.z;
    int n0 = blockIdx.y * 128;
    float*       Yb = Y    + (size_t)bz * CDIM * HW;
    const float* Rb = Rsrc + (size_t)bz * CDIM * HW;

    int tid  = threadIdx.x;
    int warp = tid >> 5;
    int lane = tid & 31;
    int g = lane >> 2;
    int t = lane & 3;
    int wm  = (warp >> 2) * 48;
    int wmi = (warp >> 2) * 3;
    int wn  = (warp & 3) * 32;

    uint4 rB[6];
#define LDGB4(s)                                                             \
    {                                                                        \
        const __nv_bfloat16* Xh = p.X[s] + (size_t)bz * p.xBatch[s];         \
        _Pragma("unroll")                                                    \
        for (int i = 0; i < 6; i++) {                                        \
            int idx = tid + i * 256;                                         \
            int k = idx >> 4, n8 = idx & 15;                                 \
            rB[i] = *reinterpret_cast<const uint4*>(Xh + (size_t)k * HW + n0 + n8 * 8); \
        }                                                                    \
    }
#define STSB4()                                                              \
    {                                                                        \
        _Pragma("unroll")                                                    \
        for (int i = 0; i < 6; i++) {                                        \
            int idx = tid + i * 256;                                         \
            int k = idx >> 4, n8 = idx & 15;                                 \
            uint32_t* dst = Bs + k * 136 + n8 * 8;                           \
            uint32_t u;                                                      \
            u = rB[i].x; dst[0] = u << 16; dst[1] = u & 0xFFFF0000u;         \
            u = rB[i].y; dst[2] = u << 16; dst[3] = u & 0xFFFF0000u;         \
            u = rB[i].z; dst[4] = u << 16; dst[5] = u & 0xFFFF0000u;         \
            u = rB[i].w; dst[6] = u << 16; dst[7] = u & 0xFFFF0000u;         \
        }                                                                    \
    }
#define LOADA4(s)                                                            \
    {                                                                        \
        const uint4* Ag = reinterpret_cast<const uint4*>(p.Apk[s] + (size_t)bz * p.aBatch[s]); \
        _Pragma("unroll")                                                    \
        for (int i = 0; i < 9; i++) {                                        \
            int idx = tid + i * 256;                                         \
            cp16(As + idx * 4, Ag + idx);                                    \
        }                                                                    \
        CP_COMMIT();                                                         \
    }

    LOADA4(0);
    LDGB4(0);

    float acc[3][4][4];
#pragma unroll
    for (int mi = 0; mi < 3; mi++)
#pragma unroll
        for (int ni = 0; ni < 4; ni++)
#pragma unroll
            for (int r = 0; r < 4; r++) acc[mi][ni][r] = 0.f;

#pragma unroll
    for (int s = 0; s < 4; s++) {
        CP_WAIT(0);
        __syncthreads();
        STSB4();
        __syncthreads();
        if (s < 3) LDGB4(s + 1);
#pragma unroll
        for (int ks = 0; ks < 12; ks++) {
            const uint32_t* Ab = As + ks * 768 + g * 16 + t * 4;
            const uint32_t* Bb = Bs + (ks * 8 + t) * 136 + wn + g;
            uint4 a4[3];
            uint32_t bf[4][2];
#pragma unroll
            for (int mi = 0; mi < 3; mi++)
                a4[mi] = *reinterpret_cast<const uint4*>(Ab + (wmi + mi) * 128);
#pragma unroll
            for (int ni = 0; ni < 4; ni++) {
                bf[ni][0] = Bb[ni * 8];
                bf[ni][1] = Bb[4 * 136 + ni * 8];
            }
#pragma unroll
            for (int mi = 0; mi < 3; mi++) {
                uint32_t af[4] = {a4[mi].x, a4[mi].y, a4[mi].z, a4[mi].w};
#pragma unroll
                for (int ni = 0; ni < 4; ni++)
                    mma_tf32(acc[mi][ni], af, bf[ni]);
            }
        }
        __syncthreads();
        if (s < 3) LOADA4(s + 1);
    }

#pragma unroll
    for (int mi = 0; mi < 3; mi++) {
        int r0 = wm + mi * 16 + g;
        int r1 = r0 + 8;
#pragma unroll
        for (int ni = 0; ni < 4; ni++) {
            int col = n0 + wn + ni * 8 + 2 * t;
            float2 ra = *reinterpret_cast<const float2*>(Rb + (size_t)r0 * HW + col);
            float2 rb = *reinterpret_cast<const float2*>(Rb + (size_t)r1 * HW + col);
            float2 v01 = make_float2(acc[mi][ni][0] + ra.x, acc[mi][ni][1] + ra.y);
            float2 v23 = make_float2(acc[mi][ni][2] + rb.x, acc[mi][ni][3] + rb.y);
            *reinterpret_cast<float2*>(Yb + (size_t)r0 * HW + col) = v01;
            *reinterpret_cast<float2*>(Yb + (size_t)r1 * HW + col) = v23;
        }
    }
#undef LOADA4
#undef LDGB4
#undef STSB4
}

// ---------------------------------------------------------------------------
// Depthwise 3x3, 2 output rows per thread (unchanged).
// ---------------------------------------------------------------------------
__global__ void dw3_kernel(const __nv_bfloat16* __restrict__ qA,
                           const __nv_bfloat16* __restrict__ qB,
                           const float* __restrict__ wA,
                           const float* __restrict__ wB,
                           __nv_bfloat16* __restrict__ oA,
                           __nv_bfloat16* __restrict__ oB) {
    int pl = blockIdx.z;
    int br = pl >= BATCH * 288;
    int rem = pl - br * BATCH * 288;
    int c = rem % 288;
    const __nv_bfloat16* ip = (br ? qB : qA) + (size_t)rem * HW;
    const float* wp = (br ? wB : wA) + c * 9;
    __nv_bfloat16* op = (br ? oB : oA) + (size_t)rem * HW;

    int x0 = (blockIdx.x * 32 + threadIdx.x) * 4;
    int y0 = (blockIdx.y * 8 + threadIdx.y) * 2;

    float w[9];
#pragma unroll
    for (int i = 0; i < 9; i++) w[i] = wp[i];

    float a0[4] = {0.f, 0.f, 0.f, 0.f};
    float a1[4] = {0.f, 0.f, 0.f, 0.f};
#pragma unroll
    for (int dy = -1; dy <= 2; dy++) {
        int yy = y0 + dy;
        if (yy < 0 || yy >= IMG) continue;
        const __nv_bfloat16* row = ip + yy * IMG;
        float v[6];
        v[0] = (x0 > 0) ? __bfloat162float(row[x0 - 1]) : 0.f;
        {
            const __nv_bfloat162* r2 = reinterpret_cast<const __nv_bfloat162*>(row + x0);
            float2 a = __bfloat1622float2(r2[0]);
            float2 b = __bfloat1622float2(r2[1]);
            v[1] = a.x; v[2] = a.y; v[3] = b.x; v[4] = b.y;
        }
        v[5] = (x0 + 4 < IMG) ? __bfloat162float(row[x0 + 4]) : 0.f;
        if (dy <= 1) {
            const float* wr = w + (dy + 1) * 3;
#pragma unroll
            for (int j = 0; j < 4; j++)
                a0[j] += wr[0] * v[j] + wr[1] * v[j + 1] + wr[2] * v[j + 2];
        }
        if (dy >= 0) {
            const float* wr = w + dy * 3;
#pragma unroll
            for (int j = 0; j < 4; j++)
                a1[j] += wr[0] * v[j] + wr[1] * v[j + 1] + wr[2] * v[j + 2];
        }
    }

    *reinterpret_cast<__nv_bfloat162*>(op + y0 * IMG + x0)     = __floats2bfloat162_rn(a0[0], a0[1]);
    *reinterpret_cast<__nv_bfloat162*>(op + y0 * IMG + x0 + 2) = __floats2bfloat162_rn(a0[2], a0[3]);
    *reinterpret_cast<__nv_bfloat162*>(op + (y0 + 1) * IMG + x0)     = __floats2bfloat162_rn(a1[0], a1[1]);
    *reinterpret_cast<__nv_bfloat162*>(op + (y0 + 1) * IMG + x0 + 2) = __floats2bfloat162_rn(a1[2], a1[3]);
}

// ---------------------------------------------------------------------------
// Fused FFN tail (unchanged).
// ---------------------------------------------------------------------------
__global__ void dwgate_kernel(const __nv_bfloat16* __restrict__ t,
                              const float* __restrict__ dwf,
                              __nv_bfloat16* __restrict__ gate) {
    int pl = blockIdx.z;
    int b = pl / HIDDEN, k = pl % HIDDEN;
    int x0 = (blockIdx.x * 32 + threadIdx.x) * 4;
    int y0 = (blockIdx.y * 8 + threadIdx.y) * 2;
    const __nv_bfloat16* i1 = t + ((size_t)b * 2 * HIDDEN + k) * HW;
    const __nv_bfloat16* i2 = t + ((size_t)b * 2 * HIDDEN + HIDDEN + k) * HW;
    const float* w1 = dwf + k * 9;
    const float* w2 = dwf + (HIDDEN + k) * 9;

    float wa[9], wb[9];
#pragma unroll
    for (int i = 0; i < 9; i++) { wa[i] = w1[i]; wb[i] = w2[i]; }

    float s1r0[4] = {0.f, 0.f, 0.f, 0.f}, s2r0[4] = {0.f, 0.f, 0.f, 0.f};
    float s1r1[4] = {0.f, 0.f, 0.f, 0.f}, s2r1[4] = {0.f, 0.f, 0.f, 0.f};
#pragma unroll
    for (int dy = -1; dy <= 2; dy++) {
        int yy = y0 + dy;
        if (yy < 0 || yy >= IMG) continue;
        const __nv_bfloat16* r1 = i1 + yy * IMG;
        const __nv_bfloat16* r2 = i2 + yy * IMG;
        float v1[6], v2[6];
        v1[0] = (x0 > 0) ? __bfloat162float(r1[x0 - 1]) : 0.f;
        v2[0] = (x0 > 0) ? __bfloat162float(r2[x0 - 1]) : 0.f;
        {
            const __nv_bfloat162* p1 = reinterpret_cast<const __nv_bfloat162*>(r1 + x0);
            const __nv_bfloat162* p2 = reinterpret_cast<const __nv_bfloat162*>(r2 + x0);
            float2 a1 = __bfloat1622float2(p1[0]), b1 = __bfloat1622float2(p1[1]);
            float2 a2 = __bfloat1622float2(p2[0]), b2 = __bfloat1622float2(p2[1]);
            v1[1] = a1.x; v1[2] = a1.y; v1[3] = b1.x; v1[4] = b1.y;
            v2[1] = a2.x; v2[2] = a2.y; v2[3] = b2.x; v2[4] = b2.y;
        }
        v1[5] = (x0 + 4 < IMG) ? __bfloat162float(r1[x0 + 4]) : 0.f;
        v2[5] = (x0 + 4 < IMG) ? __bfloat162float(r2[x0 + 4]) : 0.f;
        if (dy <= 1) {
            const float* wra = wa + (dy + 1) * 3;
            const float* wrb = wb + (dy + 1) * 3;
#pragma unroll
            for (int j = 0; j < 4; j++) {
                s1r0[j] += wra[0] * v1[j] + wra[1] * v1[j + 1] + wra[2] * v1[j + 2];
                s2r0[j] += wrb[0] * v2[j] + wrb[1] * v2[j + 1] + wrb[2] * v2[j + 2];
            }
        }
        if (dy >= 0) {
            const float* wra = wa + dy * 3;
            const float* wrb = wb + dy * 3;
#pragma unroll
            for (int j = 0; j < 4; j++) {
                s1r1[j] += wra[0] * v1[j] + wra[1] * v1[j + 1] + wra[2] * v1[j + 2];
                s2r1[j] += wrb[0] * v2[j] + wrb[1] * v2[j + 1] + wrb[2] * v2[j + 2];
            }
        }
    }

    float o0[4], o1[4];
#pragma unroll
    for (int j = 0; j < 4; j++) {
        float gl0 = 0.5f * s1r0[j] * (1.f + erff(s1r0[j] * 0.7071067811865475f));
        o0[j] = gl0 * s2r0[j];
        float gl1 = 0.5f * s1r1[j] * (1.f + erff(s1r1[j] * 0.7071067811865475f));
        o1[j] = gl1 * s2r1[j];
    }
    __nv_bfloat16* gp0 = gate + ((size_t)b * 288 + k) * HW + y0 * IMG + x0;
    __nv_bfloat16* gp1 = gp0 + IMG;
    *reinterpret_cast<__nv_bfloat162*>(gp0)     = __floats2bfloat162_rn(o0[0], o0[1]);
    *reinterpret_cast<__nv_bfloat162*>(gp0 + 2) = __floats2bfloat162_rn(o0[2], o0[3]);
    *reinterpret_cast<__nv_bfloat162*>(gp1)     = __floats2bfloat162_rn(o1[0], o1[1]);
    *reinterpret_cast<__nv_bfloat162*>(gp1 + 2) = __floats2bfloat162_rn(o1[2], o1[3]);
}

// ---------------------------------------------------------------------------
// Gram stage 1 v4: quadrant split, 8 px/thread via uint4 (LDG.128) loads.
// grid (128, HEADS, 2*BATCH): bid.x = chunk*4 + quad. One pass, no it-loop.
// ---------------------------------------------------------------------------
__global__ void __launch_bounds__(256, 2) gram1_kernel(
        const __nv_bfloat16* __restrict__ qkvAd,
        const __nv_bfloat16* __restrict__ qkvBd,
        float* __restrict__ gpA, float* __restrict__ gpB) {
    int bx = blockIdx.x;
    int chunk = bx >> 2;
    int quad  = bx & 3;
    int qh = quad >> 1;
    int kh = quad & 1;
    int h = blockIdx.y;
    int b  = blockIdx.z >> 1;
    int br = blockIdx.z & 1;
    const __nv_bfloat16* qb = (br ? qkvAd : qkvBd) + ((size_t)b * 288 + h * CHEAD + qh * 6) * HW;
    const __nv_bfloat16* kb = (br ? qkvBd : qkvAd) + ((size_t)b * 288 + 96 + h * CHEAD + kh * 6) * HW;
    float* part = br ? gpB : gpA;

    int p = chunk * 2048 + threadIdx.x * 8;

    float qf[6][8];
    float qsq[6], ksq[6];
    float acc[36];
#pragma unroll
    for (int i = 0; i < 36; i++) acc[i] = 0.f;

    // load + unpack q, fuse qsq
#pragma unroll
    for (int c = 0; c < 6; c++) {
        uint4 u = *reinterpret_cast<const uint4*>(qb + (size_t)c * HW + p);
        unpack8(qf[c], u);
        float s = 0.f;
#pragma unroll
        for (int j = 0; j < 8; j++) s += qf[c][j] * qf[c][j];
        qsq[c] = s;
    }

    // stream k channels
#pragma unroll
    for (int d = 0; d < 6; d++) {
        uint4 u = *reinterpret_cast<const uint4*>(kb + (size_t)d * HW + p);
        float kf[8];
        unpack8(kf, u);
        float s = 0.f;
#pragma unroll
        for (int j = 0; j < 8; j++) s += kf[j] * kf[j];
        ksq[d] = s;
#pragma unroll
        for (int c = 0; c < 6; c++) {
            float a = acc[c * 6 + d];
#pragma unroll
            for (int j = 0; j < 8; j++) a += qf[c][j] * kf[j];
            acc[c * 6 + d] = a;
        }
    }

    int warp = threadIdx.x >> 5;
    int lane = threadIdx.x & 31;
    float* outp = part + ((((size_t)(b * HEADS + h)) * 128 + bx) * 8 + warp) * 48;
#pragma unroll
    for (int i = 0; i < 48; i++) {
        float v = (i < 36) ? acc[i] : (i < 42 ? qsq[i - 36] : ksq[i - 42]);
#pragma unroll
        for (int off = 16; off > 0; off >>= 1)
            v += __shfl_down_sync(0xffffffffu, v, off);
        if (lane == 0) outp[i] = v;
    }
}

// ---------------------------------------------------------------------------
// Gram stage 2 + norms + temp + softmax + FUSED cw emission.
// Each block (b,h) reduces its partials, softmaxes, then writes the packed
// tf32 cw columns for its own head: cw[m, h*12+d] = sum_c P[m, h*12+c]*at[c,d].
// grid = BATCH*HEADS, 192 threads.
// ---------------------------------------------------------------------------
__global__ void attn_kernel(const float* __restrict__ partA,
                            const float* __restrict__ partB,
                            const float* __restrict__ temp,
                            const float* __restrict__ P0,
                            const float* __restrict__ P1,
                            uint32_t* __restrict__ cwApk,
                            uint32_t* __restrict__ cwBpk) {
    int bh = blockIdx.x;
    int b = bh / HEADS;
    int h = bh % HEADS;
    __shared__ float GA[144], GB[144];
    __shared__ float nqA[12], nkA[12], nqB[12], nkB[12];
    int i = threadIdx.x;
    float sA = 0.f, sB = 0.f;
    if (i < 168) {
        int quad, off;
        if (i < 144) {
            int c = i / CHEAD, d = i % CHEAD;
            quad = (c / 6) * 2 + (d / 6);
            off  = (c % 6) * 6 + (d % 6);
        } else if (i < 156) {
            int c = i - 144;
            quad = (c / 6) * 2;
            off  = 36 + (c % 6);
        } else {
            int d = i - 156;
            quad = (d / 6);
            off  = 42 + (d % 6);
        }
        const float* pA = partA + (((size_t)bh * 128 + quad) * 8) * 48 + off;
        const float* pB = partB + (((size_t)bh * 128 + quad) * 8) * 48 + off;
        for (int ch = 0; ch < 32; ch++) {
#pragma unroll
            for (int w = 0; w < 8; w++) {
                size_t o = (size_t)ch * (4 * 8 * 48) + (size_t)w * 48;
                sA += pA[o];
                sB += pB[o];
            }
        }
        if (i >= 156) {
            nkA[i - 156] = fmaxf(sqrtf(sA), 1e-12f);
            nkB[i - 156] = fmaxf(sqrtf(sB), 1e-12f);
        } else if (i >= 144) {
            nqA[i - 144] = fmaxf(sqrtf(sA), 1e-12f);
            nqB[i - 144] = fmaxf(sqrtf(sB), 1e-12f);
        }
    }
    __syncthreads();
    if (i < 144) {
        int c = i / CHEAD, d = i % CHEAD;
        float tp = temp[h];
        GA[i] =  sA / (nqA[c] * nkA[d]) * tp;
        GB[i] = -sB / (nqB[c] * nkB[d]) * tp;
    }
    __syncthreads();
    // softmax rows in place (each thread owns one row of one matrix)
    if (i < 24) {
        float* G = (i < CHEAD) ? GA : GB;
        int c = i % CHEAD;
        float mx = -1e30f;
        for (int d = 0; d < CHEAD; d++) mx = fmaxf(mx, G[c * CHEAD + d]);
        float e[CHEAD];
        float s = 0.f;
        for (int d = 0; d < CHEAD; d++) {
            e[d] = expf(G[c * CHEAD + d] - mx);
            s += e[d];
        }
        float inv = 1.f / s;
        for (int d = 0; d < CHEAD; d++)
            G[c * CHEAD + d] = e[d] * inv;
    }
    __syncthreads();
    // fused cw emission: thread i -> branch (i/96), row m = i%96, 12 d-cols.
    {
        int brn = i / 96;
        int m   = i % 96;
        const float* P  = brn ? P1 : P0;
        const float* AT = brn ? GB : GA;
        uint32_t* out = (brn ? cwBpk : cwApk) + (size_t)b * 9216;
        float pr[CHEAD];
#pragma unroll
        for (int c = 0; c < CHEAD; c++) pr[c] = P[m * 96 + h * CHEAD + c];
#pragma unroll
        for (int d = 0; d < CHEAD; d++) {
            float s = 0.f;
#pragma unroll
            for (int c = 0; c < CHEAD; c++) s += pr[c] * AT[c * CHEAD + d];
            out[a_pack_off(m, h * CHEAD + d)] = f2tf(s);
        }
    }
}

// ---------------------------------------------------------------------------
// Launch
// ---------------------------------------------------------------------------
extern "C" void kernel_launch(void* const* d_in, const int* in_sizes, int n_in,
                              void* d_out, int out_size) {
    const float* x       = (const float*)d_in[0];
    const float* y       = (const float*)d_in[1];
    const float* ln1_w   = (const float*)d_in[2];
    const float* ln1_b   = (const float*)d_in[3];
    const float* ln2_w   = (const float*)d_in[4];
    const float* ln2_b   = (const float*)d_in[5];
    const float* qkvA_w  = (const float*)d_in[6];
    const float* dwA_w   = (const float*)d_in[7];
    const float* qkvB_w  = (const float*)d_in[8];
    const float* dwB_w   = (const float*)d_in[9];
    const float* projA_w = (const float*)d_in[10];
    const float* projB_w = (const float*)d_in[11];
    const float* concat_w= (const float*)d_in[12];
    const float* temp    = (const float*)d_in[13];
    const float* pin_w   = (const float*)d_in[14];
    const float* dwf_w   = (const float*)d_in[15];
    const float* pout_w  = (const float*)d_in[16];
    float* out = (float*)d_out;

    cudaFuncSetAttribute(gemm96,   cudaFuncAttributeMaxDynamicSharedMemorySize, G96_SMEM_BYTES);
    cudaFuncSetAttribute(gemmPout, cudaFuncAttributeMaxDynamicSharedMemorySize, POUT_SMEM_BYTES);
    cudaFuncSetAttribute(gemm4_tc, cudaFuncAttributeMaxDynamicSharedMemorySize, G4_SMEM_BYTES);

    __nv_bfloat16 *qkvA, *qkvAd, *qkvB, *qkvBd, *t, *gate, *xn, *yn;
    float *x1, *gpA, *gpB, *P0, *P1;
    uint32_t *prepQA, *prepQB, *prepPin, *prepPout_p, *prepC0, *prepC1, *cwApk, *cwBpk;
    float *sQA, *tQA, *sQB, *tQB, *sPin, *tPin;
    cudaGetSymbolAddress((void**)&qkvA,   g_qkvA);
    cudaGetSymbolAddress((void**)&qkvAd,  g_qkvAd);
    cudaGetSymbolAddress((void**)&qkvB,   g_qkvB);
    cudaGetSymbolAddress((void**)&qkvBd,  g_qkvBd);
    cudaGetSymbolAddress((void**)&xn,     g_xn);
    cudaGetSymbolAddress((void**)&yn,     g_yn);
    cudaGetSymbolAddress((void**)&t,      g_t);
    cudaGetSymbolAddress((void**)&gate,   g_gate);
    cudaGetSymbolAddress((void**)&x1,     g_x1);
    cudaGetSymbolAddress((void**)&gpA,    g_gpartA);
    cudaGetSymbolAddress((void**)&gpB,    g_gpartB);
    cudaGetSymbolAddress((void**)&P0,     g_P0);
    cudaGetSymbolAddress((void**)&P1,     g_P1);
    cudaGetSymbolAddress((void**)&prepQA,   g_prepQA);
    cudaGetSymbolAddress((void**)&prepQB,   g_prepQB);
    cudaGetSymbolAddress((void**)&prepPin,  g_prepPin);
    cudaGetSymbolAddress((void**)&prepPout_p, g_prepPout);
    cudaGetSymbolAddress((void**)&prepC0,   g_prepC0);
    cudaGetSymbolAddress((void**)&prepC1,   g_prepC1);
    cudaGetSymbolAddress((void**)&cwApk,    g_cwApk);
    cudaGetSymbolAddress((void**)&cwBpk,    g_cwBpk);
    cudaGetSymbolAddress((void**)&sQA,    g_sQA);
    cudaGetSymbolAddress((void**)&tQA,    g_tQA);
    cudaGetSymbolAddress((void**)&sQB,    g_sQB);
    cudaGetSymbolAddress((void**)&tQB,    g_tQB);
    cudaGetSymbolAddress((void**)&sPin,   g_sPin);
    cudaGetSymbolAddress((void**)&tPin,   g_tPin);

    const size_t P96   = (size_t)CDIM * HW;
    const size_t P96E  = (size_t)CDIM * HW;
    const size_t P288E = (size_t)3 * CDIM * HW;
    const size_t P510E = (size_t)2 * HIDDEN * HW;
    const size_t PGATE = (size_t)288 * HW;

    megaprep<<<53, 256>>>(qkvA_w, qkvB_w, pin_w, pout_w, concat_w,
                          projA_w, projB_w, ln1_w, ln1_b, ln2_w, ln2_b,
                          prepQA, prepQB, prepPin, prepPout_p, prepC0, prepC1,
                          sQA, tQA, sQB, tQB, sPin, tPin, P0, P1);

    // qkv for both branches; also emits bf16 xn/yn for gemm4
    {
        G96P p;
        p.Apk[0] = prepQA; p.Apk[1] = prepQB;
        p.sv[0] = sQA; p.sv[1] = sQB;
        p.tv[0] = tQA; p.tv[1] = tQB;
        p.X[0] = x; p.X[1] = y;
        p.xnOut[0] = xn; p.xnOut[1] = yn;
        p.Y[0] = qkvA; p.Y[1] = qkvB;
        p.lnw = ln1_w; p.lnb = ln1_b;
        dim3 g(1, HW / 128, BATCH * 2);
        gemm96<<<g, 256, G96_SMEM_BYTES>>>(p, 288, 2, 3, P96, P288E);
    }

    // depthwise 3x3, both branches, 2 rows/thread
    {
        dim3 blk(32, 8), g(IMG / 128, IMG / 16, 2 * BATCH * 288);
        dw3_kernel<<<g, blk>>>(qkvA, qkvB, dwA_w, dwB_w, qkvAd, qkvBd);
    }

    // Gram quadrants + fused norms, both branches (uint4 loads)
    {
        dim3 g(128, HEADS, 2 * BATCH);
        gram1_kernel<<<g, 256>>>(qkvAd, qkvBd, gpA, gpB);
    }

    // attn + fused cw emission
    attn_kernel<<<BATCH * HEADS, 192>>>(gpA, gpB, temp, P0, P1, cwApk, cwBpk);

    // fused x1 = x + cwA@vA + cwB@vB + C0@xn + C1@yn  (all-bf16 sources)
    {
        G4 p;
        p.Apk[0] = cwApk;  p.aBatch[0] = 9216;
        p.Apk[1] = cwBpk;  p.aBatch[1] = 9216;
        p.Apk[2] = prepC0; p.aBatch[2] = 0;
        p.Apk[3] = prepC1; p.aBatch[3] = 0;
        p.X[0] = qkvAd + 192 * (size_t)HW; p.xBatch[0] = P288E;
        p.X[1] = qkvBd + 192 * (size_t)HW; p.xBatch[1] = P288E;
        p.X[2] = xn;                       p.xBatch[2] = P96E;
        p.X[3] = yn;                       p.xBatch[3] = P96E;
        dim3 g(1, HW / 128, BATCH);
        gemm4_tc<<<g, 256, G4_SMEM_BYTES>>>(p, x, x1);
    }

    // pin = W@LN2(x1), B-resident with 6 m-tiles in-block
    {
        G96P p;
        p.Apk[0] = prepPin; p.Apk[1] = prepPin;
        p.sv[0] = sPin; p.sv[1] = sPin;
        p.tv[0] = tPin; p.tv[1] = tPin;
        p.X[0] = x1; p.X[1] = x1;
        p.xnOut[0] = nullptr; p.xnOut[1] = nullptr;
        p.Y[0] = t; p.Y[1] = t;
        p.lnw = ln2_w; p.lnb = ln2_b;
        dim3 g(1, HW / 128, BATCH);
        gemm96<<<g, 256, G96_SMEM_BYTES>>>(p, 510, 1, 6, P96, P510E);
    }

    // fused depthwise + gelu gate, 2 rows/thread
    {
        dim3 blk(32, 8), g(IMG / 128, IMG / 16, BATCH * HIDDEN);
        dwgate_kernel<<<g, blk>>>(t, dwf_w, gate);
    }

    // pout + residual x1 -> output
    {
        dim3 g(1, HW / 128, BATCH);
        gemmPout<<<g, 256, POUT_SMEM_BYTES>>>(prepPout_p, gate, x1, out,
                                              PGATE, P96, P96);
    }
}

// round 15
// speedup vs baseline: 5.3659x; 1.0406x over previous
#include <cuda_runtime.h>
#include <cuda_bf16.h>
#include <math.h>
#include <stdint.h>

#define HW      65536
#define IMG     256
#define BATCH   2
#define CDIM    96
#define HEADS   8
#define CHEAD   12
#define HIDDEN  255

// ---------------------------------------------------------------------------
// Scratch
// ---------------------------------------------------------------------------
__device__ __nv_bfloat16 g_qkvA [BATCH * 3 * CDIM * HW];
__device__ __nv_bfloat16 g_qkvAd[BATCH * 3 * CDIM * HW];
__device__ __nv_bfloat16 g_qkvB [BATCH * 3 * CDIM * HW];
__device__ __nv_bfloat16 g_qkvBd[BATCH * 3 * CDIM * HW];
__device__ __nv_bfloat16 g_xn   [BATCH * CDIM * HW];
__device__ __nv_bfloat16 g_yn   [BATCH * CDIM * HW];
__device__ __nv_bfloat16 g_t    [BATCH * 2 * HIDDEN * HW];
__device__ __nv_bfloat16 g_gate [BATCH * 288 * HW];   // 288-pitch; rows 255..287 stay zero
__device__ float g_x1   [BATCH * CDIM * HW];
// Gram partials: [bh][chunk*4+quad][warp][48]  (8 chunks now)
__device__ float g_gpartA[BATCH * HEADS * 32 * 8 * 48];
__device__ float g_gpartB[BATCH * HEADS * 32 * 8 * 48];
__device__ float g_P0  [CDIM * CDIM];
__device__ float g_P1  [CDIM * CDIM];
// prepacked tf32 fragment tiles
__device__ uint32_t g_prepQA  [3 * 9216];
__device__ uint32_t g_prepQB  [3 * 9216];
__device__ uint32_t g_prepPin [6 * 9216];
__device__ uint32_t g_prepPout[3 * 9216];
__device__ uint32_t g_prepC0  [9216];
__device__ uint32_t g_prepC1  [9216];
__device__ uint32_t g_cwApk   [BATCH * 9216];
__device__ uint32_t g_cwBpk   [BATCH * 9216];
__device__ float g_sQA[288],  g_tQA[288];
__device__ float g_sQB[288],  g_tQB[288];
__device__ float g_sPin[576], g_tPin[576];

// ---------------------------------------------------------------------------
// tf32 / cp.async helpers
// ---------------------------------------------------------------------------
__device__ __forceinline__ uint32_t f2tf(float f) {
    uint32_t u;
    asm("cvt.rna.tf32.f32 %0, %1;" : "=r"(u) : "f"(f));
    return u;
}

__device__ __forceinline__ void mma_tf32(float* c, const uint32_t* a, const uint32_t* b) {
    asm volatile(
        "mma.sync.aligned.m16n8k8.row.col.f32.tf32.tf32.f32 "
        "{%0,%1,%2,%3}, {%4,%5,%6,%7}, {%8,%9}, {%0,%1,%2,%3};"
        : "+f"(c[0]), "+f"(c[1]), "+f"(c[2]), "+f"(c[3])
        : "r"(a[0]), "r"(a[1]), "r"(a[2]), "r"(a[3]), "r"(b[0]), "r"(b[1]));
}

__device__ __forceinline__ void cp16(void* smem, const void* gmem) {
    uint32_t a = (uint32_t)__cvta_generic_to_shared(smem);
    asm volatile("cp.async.cg.shared.global [%0], [%1], 16;\n" :: "r"(a), "l"(gmem));
}
#define CP_COMMIT()  asm volatile("cp.async.commit_group;\n")
#define CP_WAIT(n)   asm volatile("cp.async.wait_group %0;\n" :: "n"(n))

__device__ __forceinline__ int a_pack_off(int m, int k) {
    return (k >> 3) * 768 + (m >> 4) * 128 + (m & 7) * 16 + (k & 3) * 4
         + ((k >> 2) & 1) * 2 + ((m >> 3) & 1);
}

// unpack uint4 (8 bf16) -> 8 floats via bit shifts
__device__ __forceinline__ void unpack8(float* f, uint4 u) {
    f[0] = __uint_as_float(u.x << 16); f[1] = __uint_as_float(u.x & 0xFFFF0000u);
    f[2] = __uint_as_float(u.y << 16); f[3] = __uint_as_float(u.y & 0xFFFF0000u);
    f[4] = __uint_as_float(u.z << 16); f[5] = __uint_as_float(u.z & 0xFFFF0000u);
    f[6] = __uint_as_float(u.w << 16); f[7] = __uint_as_float(u.w & 0xFFFF0000u);
}

// gemm4: A tile + full B panel
#define G4_SMEM_WORDS   (9216 + 96*136)
#define G4_SMEM_BYTES   (G4_SMEM_WORDS * 4)
// gemm96: full B panel + one A tile + stats + ln vectors
#define G96_SMEM_WORDS  (96*136 + 9216 + 256 + 192)
#define G96_SMEM_BYTES  (G96_SMEM_WORDS * 4)
// pout: double-buffered 32-row B ring
#define POUT_SMEM_WORDS (9216 + 2*32*136)
#define POUT_SMEM_BYTES (POUT_SMEM_WORDS * 4)

// ---------------------------------------------------------------------------
// Mega-prep (unchanged).
// ---------------------------------------------------------------------------
__device__ void prep_tile(const float* __restrict__ W, int M, int tile,
                          const float* __restrict__ wln,
                          const float* __restrict__ bln,
                          uint32_t* __restrict__ Apk,
                          float* __restrict__ svec, float* __restrict__ tvec,
                          float* wls, float* bls) {
    int m0 = tile * 96;
    if (threadIdx.x < 96) { wls[threadIdx.x] = wln[threadIdx.x]; bls[threadIdx.x] = bln[threadIdx.x]; }
    __syncthreads();
#pragma unroll
    for (int i = 0; i < 36; i++) {
        int idx = threadIdx.x + i * 256;
        int m = idx / 96;
        int k = idx - m * 96;
        float v = 0.f;
        if (m0 + m < M) v = W[(size_t)(m0 + m) * 96 + k] * wls[k];
        Apk[tile * 9216 + a_pack_off(m, k)] = f2tf(v);
    }
    if (threadIdx.x < 96) {
        int gm = m0 + threadIdx.x;
        float s = 0.f, tt = 0.f;
        if (gm < M) {
            for (int k = 0; k < 96; k++) {
                float w = W[(size_t)gm * 96 + k];
                s  += w * wls[k];
                tt += w * bls[k];
            }
        }
        svec[tile * 96 + threadIdx.x] = s;
        tvec[tile * 96 + threadIdx.x] = tt;
    }
}

__global__ void megaprep(
        const float* __restrict__ qkvA_w, const float* __restrict__ qkvB_w,
        const float* __restrict__ pin_w,  const float* __restrict__ pout_w,
        const float* __restrict__ concat_w,
        const float* __restrict__ projA_w, const float* __restrict__ projB_w,
        const float* __restrict__ ln1_w, const float* __restrict__ ln1_b,
        const float* __restrict__ ln2_w, const float* __restrict__ ln2_b,
        uint32_t* __restrict__ prepQA, uint32_t* __restrict__ prepQB,
        uint32_t* __restrict__ prepPin, uint32_t* __restrict__ prepPout,
        uint32_t* __restrict__ prepC0, uint32_t* __restrict__ prepC1,
        float* __restrict__ sQA, float* __restrict__ tQA,
        float* __restrict__ sQB, float* __restrict__ tQB,
        float* __restrict__ sPin, float* __restrict__ tPin,
        float* __restrict__ P0, float* __restrict__ P1) {
    __shared__ float sbuf[96 * 96];
    int bid = blockIdx.x;
    if (bid < 3) {
        prep_tile(qkvA_w, 288, bid, ln1_w, ln1_b, prepQA, sQA, tQA, sbuf, sbuf + 96);
    } else if (bid < 6) {
        prep_tile(qkvB_w, 288, bid - 3, ln1_w, ln1_b, prepQB, sQB, tQB, sbuf, sbuf + 96);
    } else if (bid < 12) {
        prep_tile(pin_w, 510, bid - 6, ln2_w, ln2_b, prepPin, sPin, tPin, sbuf, sbuf + 96);
    } else if (bid < 15) {
        int s = bid - 12;
#pragma unroll
        for (int i = 0; i < 36; i++) {
            int idx = threadIdx.x + i * 256;
            int m = idx / 96;
            int k = idx - m * 96;
            int kg = s * 96 + k;
            float v = (kg < HIDDEN) ? pout_w[(size_t)m * HIDDEN + kg] : 0.f;
            prepPout[s * 9216 + a_pack_off(m, k)] = f2tf(v);
        }
    } else if (bid < 17) {
        const float* W = concat_w + (bid == 16 ? 96 : 0);
        uint32_t* out = (bid == 16) ? prepC1 : prepC0;
#pragma unroll
        for (int i = 0; i < 36; i++) {
            int idx = threadIdx.x + i * 256;
            int m = idx / 96;
            int k = idx - m * 96;
            out[a_pack_off(m, k)] = f2tf(W[(size_t)m * 192 + k]);
        }
    } else {
        int w = bid - 17;
        int br = w & 1;
        int yt = w >> 1;
        const float* proj = br ? projB_w : projA_w;
        const float* cw   = concat_w + (br ? 96 : 0);
        float* P = br ? P1 : P0;
        for (int i = threadIdx.x; i < 96 * 96; i += 256) sbuf[i] = proj[i];
        __syncthreads();
        int base = yt * 512;
#pragma unroll
        for (int r = 0; r < 2; r++) {
            int o = base + r * 256 + threadIdx.x;
            int m = o / 96, n = o % 96;
            float s = 0.f;
#pragma unroll 8
            for (int c = 0; c < 96; c++) s += cw[m * 192 + c] * sbuf[c * 96 + n];
            P[o] = s;
        }
    }
}

// ---------------------------------------------------------------------------
// 32-k MMA chunk on the 96x128 tile.
// ---------------------------------------------------------------------------
__device__ __forceinline__ void g96_chunk(
        float acc[3][4][4], const uint32_t* __restrict__ As,
        const uint32_t* __restrict__ Bbuf,
        int kc, int g, int t, int wmi, int wn) {
#pragma unroll
    for (int ks2 = 0; ks2 < 4; ks2++) {
        const uint32_t* Ab = As + (kc * 4 + ks2) * 768 + g * 16 + t * 4;
        const uint32_t* Bb = Bbuf + (ks2 * 8 + t) * 136 + wn + g;
        uint4 a4[3];
        uint32_t bf[4][2];
#pragma unroll
        for (int mi = 0; mi < 3; mi++)
            a4[mi] = *reinterpret_cast<const uint4*>(Ab + (wmi + mi) * 128);
#pragma unroll
        for (int ni = 0; ni < 4; ni++) {
            bf[ni][0] = Bb[ni * 8];
            bf[ni][1] = Bb[4 * 136 + ni * 8];
        }
#pragma unroll
        for (int mi = 0; mi < 3; mi++) {
            uint32_t af[4] = {a4[mi].x, a4[mi].y, a4[mi].z, a4[mi].w};
#pragma unroll
            for (int ni = 0; ni < 4; ni++)
                mma_tf32(acc[mi][ni], af, bf[ni]);
        }
    }
}

// ---------------------------------------------------------------------------
// B-resident multi-M gemm96 + optional bf16 LN(x) emission (unchanged).
// ---------------------------------------------------------------------------
struct G96P {
    const uint32_t* Apk[2];
    const float*    sv[2];
    const float*    tv[2];
    const float*    X[2];
    __nv_bfloat16*  xnOut[2];    // may be null
    __nv_bfloat16*  Y[2];
    const float*    lnw;
    const float*    lnb;
};

__global__ void __launch_bounds__(256, 2) gemm96(
        G96P p, int M, int NB, int Mtiles, size_t xBatch, size_t yBatch) {
    extern __shared__ uint32_t sm[];
    uint32_t* Bs = sm;                       // 96*136 = 13056
    uint32_t* As = sm + 13056;               // 9216
    float* mu_s  = (float*)(sm + 13056 + 9216);
    float* inv_s = mu_s + 128;
    float* wl_s  = inv_s + 128;              // 96
    float* bl_s  = wl_s + 96;                // 96

    int z  = blockIdx.z;
    int br = z % NB;
    int bz = z / NB;
    const float* Xb = p.X[br] + (size_t)bz * xBatch;
    __nv_bfloat16* Yb = p.Y[br] + (size_t)bz * yBatch;
    const float* svec = p.sv[br];
    const float* tvec = p.tv[br];
    const uint32_t* Apk = p.Apk[br];
    bool hasXn = (p.xnOut[br] != nullptr);

    int n0 = blockIdx.y * 128;
    int tid  = threadIdx.x;
    int warp = tid >> 5;
    int lane = tid & 31;
    int g = lane >> 2;
    int t = lane & 3;
    int wm  = (warp >> 2) * 48;
    int wmi = (warp >> 2) * 3;
    int wn  = (warp & 3) * 32;

#define LOADA96(mt)                                                          \
    {                                                                        \
        const uint4* Ag = reinterpret_cast<const uint4*>(Apk + (size_t)(mt) * 9216); \
        _Pragma("unroll")                                                    \
        for (int i = 0; i < 9; i++) {                                        \
            int idx = tid + i * 256;                                         \
            cp16(As + idx * 4, Ag + idx);                                    \
        }                                                                    \
    }

#pragma unroll
    for (int j = 0; j < 12; j++) {
        int idx = tid + j * 256;
        int k = idx >> 5, n4 = idx & 31;
        cp16(Bs + k * 136 + n4 * 4, Xb + (size_t)k * HW + n0 + n4 * 4);
    }
    LOADA96(0);
    CP_COMMIT();
    if (hasXn && tid < 96) { wl_s[tid] = p.lnw[tid]; bl_s[tid] = p.lnb[tid]; }
    CP_WAIT(0);
    __syncthreads();

    if (tid < 128) {
        float csum = 0.f, csq = 0.f;
#pragma unroll 8
        for (int k = 0; k < 96; k++) {
            float v = __uint_as_float(Bs[k * 136 + tid]);
            csum += v; csq += v * v;
        }
        float mu  = csum * (1.f / 96.f);
        float var = csq * (1.f / 96.f) - mu * mu;
        mu_s[tid]  = mu;
        inv_s[tid] = rsqrtf(var + 1e-5f);
    }
    __syncthreads();

    if (hasXn) {
        __nv_bfloat16* xo = p.xnOut[br] + (size_t)bz * CDIM * HW + n0;
        int c2 = (tid & 63) * 2;
        int rb = tid >> 6;
        float m0v = mu_s[c2],     i0 = inv_s[c2];
        float m1v = mu_s[c2 + 1], i1 = inv_s[c2 + 1];
#pragma unroll
        for (int it = 0; it < 24; it++) {
            int r = it * 4 + rb;
            float v0 = __uint_as_float(Bs[r * 136 + c2]);
            float v1 = __uint_as_float(Bs[r * 136 + c2 + 1]);
            float w = wl_s[r], bb = bl_s[r];
            *reinterpret_cast<__nv_bfloat162*>(xo + (size_t)r * HW + c2) =
                __floats2bfloat162_rn((v0 - m0v) * i0 * w + bb,
                                      (v1 - m1v) * i1 * w + bb);
        }
    }

    for (int mt = 0; mt < Mtiles; mt++) {
        int m0 = mt * 96;
        float acc[3][4][4];
#pragma unroll
        for (int mi = 0; mi < 3; mi++)
#pragma unroll
            for (int ni = 0; ni < 4; ni++)
#pragma unroll
                for (int r = 0; r < 4; r++) acc[mi][ni][r] = 0.f;

#pragma unroll
        for (int kc = 0; kc < 3; kc++)
            g96_chunk(acc, As, Bs + kc * 4352, kc, g, t, wmi, wn);

        __syncthreads();
        if (mt + 1 < Mtiles) {
            LOADA96(mt + 1);
            CP_COMMIT();
        }

#pragma unroll
        for (int mi = 0; mi < 3; mi++) {
            int r0 = m0 + wm + mi * 16 + g;
            int r1 = r0 + 8;
            float s0 = 0.f, t0 = 0.f, s1 = 0.f, t1 = 0.f;
            if (r0 < M) { s0 = svec[r0]; t0 = tvec[r0]; }
            if (r1 < M) { s1 = svec[r1]; t1 = tvec[r1]; }
#pragma unroll
            for (int ni = 0; ni < 4; ni++) {
                int ln = wn + ni * 8 + 2 * t;
                int col = n0 + ln;
                float i0 = inv_s[ln],     m0v = mu_s[ln]     * i0;
                float i1 = inv_s[ln + 1], m1v = mu_s[ln + 1] * i1;
                if (r0 < M) {
                    float vx = acc[mi][ni][0] * i0 - m0v * s0 + t0;
                    float vy = acc[mi][ni][1] * i1 - m1v * s0 + t0;
                    *reinterpret_cast<__nv_bfloat162*>(Yb + (size_t)r0 * HW + col) =
                        __floats2bfloat162_rn(vx, vy);
                }
                if (r1 < M) {
                    float vx = acc[mi][ni][2] * i0 - m0v * s1 + t1;
                    float vy = acc[mi][ni][3] * i1 - m1v * s1 + t1;
                    *reinterpret_cast<__nv_bfloat162*>(Yb + (size_t)r1 * HW + col) =
                        __floats2bfloat162_rn(vx, vy);
                }
            }
        }

        if (mt + 1 < Mtiles) {
            CP_WAIT(0);
            __syncthreads();
        }
    }
#undef LOADA96
}

// ---------------------------------------------------------------------------
// pout (unchanged).
// ---------------------------------------------------------------------------
__global__ void __launch_bounds__(256, 3) gemmPout(
        const uint32_t* __restrict__ Apk,
        const __nv_bfloat16* __restrict__ X,
        const float* __restrict__ Rsrc,
        float* __restrict__ Y,
        size_t xBatch, size_t yBatch, size_t rBatch) {
    extern __shared__ uint32_t sm[];
    uint32_t* As = sm;
    uint32_t* Bs = sm + 9216;

    int bz = blockIdx.z;
    const __nv_bfloat16* Xb = X + (size_t)bz * xBatch;
    float*       Yb = Y    + (size_t)bz * yBatch;
    const float* Rb = Rsrc + (size_t)bz * rBatch;

    int n0 = blockIdx.y * 128;
    int tid  = threadIdx.x;
    int warp = tid >> 5;
    int lane = tid & 31;
    int g = lane >> 2;
    int t = lane & 3;
    int wm  = (warp >> 2) * 48;
    int wmi = (warp >> 2) * 3;
    int wn  = (warp & 3) * 32;

    int kk = tid >> 3;
    int nb = (tid & 7) * 16;

    uint4 rA, rB;
#define LDGB(c)                                                             \
    {                                                                       \
        const uint4* src = reinterpret_cast<const uint4*>(                  \
            Xb + (size_t)((c) * 32 + kk) * HW + n0 + nb);                   \
        rA = src[0]; rB = src[1];                                           \
    }
#define STSB(c)                                                             \
    {                                                                       \
        uint32_t* dst = Bs + ((c) & 1) * 4352 + kk * 136 + nb;              \
        uint32_t u;                                                         \
        u = rA.x; dst[0]  = u << 16; dst[1]  = u & 0xFFFF0000u;             \
        u = rA.y; dst[2]  = u << 16; dst[3]  = u & 0xFFFF0000u;             \
        u = rA.z; dst[4]  = u << 16; dst[5]  = u & 0xFFFF0000u;             \
        u = rA.w; dst[6]  = u << 16; dst[7]  = u & 0xFFFF0000u;             \
        u = rB.x; dst[8]  = u << 16; dst[9]  = u & 0xFFFF0000u;             \
        u = rB.y; dst[10] = u << 16; dst[11] = u & 0xFFFF0000u;             \
        u = rB.z; dst[12] = u << 16; dst[13] = u & 0xFFFF0000u;             \
        u = rB.w; dst[14] = u << 16; dst[15] = u & 0xFFFF0000u;             \
    }
#define LOADA(s)                                                            \
    {                                                                       \
        const uint4* Ag = reinterpret_cast<const uint4*>(Apk + (s) * 9216); \
        _Pragma("unroll")                                                   \
        for (int i = 0; i < 9; i++) {                                       \
            int idx = tid + i * 256;                                        \
            cp16(As + idx * 4, Ag + idx);                                   \
        }                                                                   \
        CP_COMMIT();                                                        \
    }

    LOADA(0);
    LDGB(0);
    STSB(0);
    LDGB(1);
    CP_WAIT(0);
    __syncthreads();

    float acc[3][4][4];
#pragma unroll
    for (int mi = 0; mi < 3; mi++)
#pragma unroll
        for (int ni = 0; ni < 4; ni++)
#pragma unroll
            for (int r = 0; r < 4; r++) acc[mi][ni][r] = 0.f;

#pragma unroll
    for (int c = 0; c < 9; c++) {
        g96_chunk(acc, As, Bs + (c & 1) * 4352, c % 3, g, t, wmi, wn);
        if (c < 8) {
            __syncthreads();
            bool newA = (c % 3 == 2);
            if (newA) LOADA(c / 3 + 1);
            STSB(c + 1);
            if (c + 2 <= 8) LDGB(c + 2);
            if (newA) CP_WAIT(0);
            __syncthreads();
        }
    }
#undef LOADA
#undef LDGB
#undef STSB

#pragma unroll
    for (int mi = 0; mi < 3; mi++) {
        int r0 = wm + mi * 16 + g;
        int r1 = r0 + 8;
#pragma unroll
        for (int ni = 0; ni < 4; ni++) {
            int col = n0 + wn + ni * 8 + 2 * t;
            float2 ra = *reinterpret_cast<const float2*>(Rb + (size_t)r0 * HW + col);
            float2 rb = *reinterpret_cast<const float2*>(Rb + (size_t)r1 * HW + col);
            float2 v01 = make_float2(acc[mi][ni][0] + ra.x, acc[mi][ni][1] + ra.y);
            float2 v23 = make_float2(acc[mi][ni][2] + rb.x, acc[mi][ni][3] + rb.y);
            *reinterpret_cast<float2*>(Yb + (size_t)r0 * HW + col) = v01;
            *reinterpret_cast<float2*>(Yb + (size_t)r1 * HW + col) = v23;
        }
    }
}

// ---------------------------------------------------------------------------
// gemm4 v2 (unchanged).
// ---------------------------------------------------------------------------
struct G4 {
    const uint32_t*      Apk[4];
    size_t               aBatch[4];
    const __nv_bfloat16* X[4];
    size_t               xBatch[4];
};

__global__ void __launch_bounds__(256, 2) gemm4_tc(
        G4 p,
        const float* __restrict__ Rsrc,
        float* __restrict__ Y) {
    extern __shared__ uint32_t smem_u[];
    uint32_t* As = smem_u;          // 9216
    uint32_t* Bs = As + 9216;       // 13056

    int bz = blockIdx.z;
    int n0 = blockIdx.y * 128;
    float*       Yb = Y    + (size_t)bz * CDIM * HW;
    const float* Rb = Rsrc + (size_t)bz * CDIM * HW;

    int tid  = threadIdx.x;
    int warp = tid >> 5;
    int lane = tid & 31;
    int g = lane >> 2;
    int t = lane & 3;
    int wm  = (warp >> 2) * 48;
    int wmi = (warp >> 2) * 3;
    int wn  = (warp & 3) * 32;

    uint4 rB[6];
#define LDGB4(s)                                                             \
    {                                                                        \
        const __nv_bfloat16* Xh = p.X[s] + (size_t)bz * p.xBatch[s];         \
        _Pragma("unroll")                                                    \
        for (int i = 0; i < 6; i++) {                                        \
            int idx = tid + i * 256;                                         \
            int k = idx >> 4, n8 = idx & 15;                                 \
            rB[i] = *reinterpret_cast<const uint4*>(Xh + (size_t)k * HW + n0 + n8 * 8); \
        }                                                                    \
    }
#define STSB4()                                                              \
    {                                                                        \
        _Pragma("unroll")                                                    \
        for (int i = 0; i < 6; i++) {                                        \
            int idx = tid + i * 256;                                         \
            int k = idx >> 4, n8 = idx & 15;                                 \
            uint32_t* dst = Bs + k * 136 + n8 * 8;                           \
            uint32_t u;                                                      \
            u = rB[i].x; dst[0] = u << 16; dst[1] = u & 0xFFFF0000u;         \
            u = rB[i].y; dst[2] = u << 16; dst[3] = u & 0xFFFF0000u;         \
            u = rB[i].z; dst[4] = u << 16; dst[5] = u & 0xFFFF0000u;         \
            u = rB[i].w; dst[6] = u << 16; dst[7] = u & 0xFFFF0000u;         \
        }                                                                    \
    }
#define LOADA4(s)                                                            \
    {                                                                        \
        const uint4* Ag = reinterpret_cast<const uint4*>(p.Apk[s] + (size_t)bz * p.aBatch[s]); \
        _Pragma("unroll")                                                    \
        for (int i = 0; i < 9; i++) {                                        \
            int idx = tid + i * 256;                                         \
            cp16(As + idx * 4, Ag + idx);                                    \
        }                                                                    \
        CP_COMMIT();                                                         \
    }

    LOADA4(0);
    LDGB4(0);

    float acc[3][4][4];
#pragma unroll
    for (int mi = 0; mi < 3; mi++)
#pragma unroll
        for (int ni = 0; ni < 4; ni++)
#pragma unroll
            for (int r = 0; r < 4; r++) acc[mi][ni][r] = 0.f;

#pragma unroll
    for (int s = 0; s < 4; s++) {
        CP_WAIT(0);
        __syncthreads();
        STSB4();
        __syncthreads();
        if (s < 3) LDGB4(s + 1);
#pragma unroll
        for (int ks = 0; ks < 12; ks++) {
            const uint32_t* Ab = As + ks * 768 + g * 16 + t * 4;
            const uint32_t* Bb = Bs + (ks * 8 + t) * 136 + wn + g;
            uint4 a4[3];
            uint32_t bf[4][2];
#pragma unroll
            for (int mi = 0; mi < 3; mi++)
                a4[mi] = *reinterpret_cast<const uint4*>(Ab + (wmi + mi) * 128);
#pragma unroll
            for (int ni = 0; ni < 4; ni++) {
                bf[ni][0] = Bb[ni * 8];
                bf[ni][1] = Bb[4 * 136 + ni * 8];
            }
#pragma unroll
            for (int mi = 0; mi < 3; mi++) {
                uint32_t af[4] = {a4[mi].x, a4[mi].y, a4[mi].z, a4[mi].w};
#pragma unroll
                for (int ni = 0; ni < 4; ni++)
                    mma_tf32(acc[mi][ni], af, bf[ni]);
            }
        }
        __syncthreads();
        if (s < 3) LOADA4(s + 1);
    }

#pragma unroll
    for (int mi = 0; mi < 3; mi++) {
        int r0 = wm + mi * 16 + g;
        int r1 = r0 + 8;
#pragma unroll
        for (int ni = 0; ni < 4; ni++) {
            int col = n0 + wn + ni * 8 + 2 * t;
            float2 ra = *reinterpret_cast<const float2*>(Rb + (size_t)r0 * HW + col);
            float2 rb = *reinterpret_cast<const float2*>(Rb + (size_t)r1 * HW + col);
            float2 v01 = make_float2(acc[mi][ni][0] + ra.x, acc[mi][ni][1] + ra.y);
            float2 v23 = make_float2(acc[mi][ni][2] + rb.x, acc[mi][ni][3] + rb.y);
            *reinterpret_cast<float2*>(Yb + (size_t)r0 * HW + col) = v01;
            *reinterpret_cast<float2*>(Yb + (size_t)r1 * HW + col) = v23;
        }
    }
#undef LOADA4
#undef LDGB4
#undef STSB4
}

// ---------------------------------------------------------------------------
// Depthwise 3x3, 2 output rows per thread (unchanged).
// ---------------------------------------------------------------------------
__global__ void dw3_kernel(const __nv_bfloat16* __restrict__ qA,
                           const __nv_bfloat16* __restrict__ qB,
                           const float* __restrict__ wA,
                           const float* __restrict__ wB,
                           __nv_bfloat16* __restrict__ oA,
                           __nv_bfloat16* __restrict__ oB) {
    int pl = blockIdx.z;
    int br = pl >= BATCH * 288;
    int rem = pl - br * BATCH * 288;
    int c = rem % 288;
    const __nv_bfloat16* ip = (br ? qB : qA) + (size_t)rem * HW;
    const float* wp = (br ? wB : wA) + c * 9;
    __nv_bfloat16* op = (br ? oB : oA) + (size_t)rem * HW;

    int x0 = (blockIdx.x * 32 + threadIdx.x) * 4;
    int y0 = (blockIdx.y * 8 + threadIdx.y) * 2;

    float w[9];
#pragma unroll
    for (int i = 0; i < 9; i++) w[i] = wp[i];

    float a0[4] = {0.f, 0.f, 0.f, 0.f};
    float a1[4] = {0.f, 0.f, 0.f, 0.f};
#pragma unroll
    for (int dy = -1; dy <= 2; dy++) {
        int yy = y0 + dy;
        if (yy < 0 || yy >= IMG) continue;
        const __nv_bfloat16* row = ip + yy * IMG;
        float v[6];
        v[0] = (x0 > 0) ? __bfloat162float(row[x0 - 1]) : 0.f;
        {
            const __nv_bfloat162* r2 = reinterpret_cast<const __nv_bfloat162*>(row + x0);
            float2 a = __bfloat1622float2(r2[0]);
            float2 b = __bfloat1622float2(r2[1]);
            v[1] = a.x; v[2] = a.y; v[3] = b.x; v[4] = b.y;
        }
        v[5] = (x0 + 4 < IMG) ? __bfloat162float(row[x0 + 4]) : 0.f;
        if (dy <= 1) {
            const float* wr = w + (dy + 1) * 3;
#pragma unroll
            for (int j = 0; j < 4; j++)
                a0[j] += wr[0] * v[j] + wr[1] * v[j + 1] + wr[2] * v[j + 2];
        }
        if (dy >= 0) {
            const float* wr = w + dy * 3;
#pragma unroll
            for (int j = 0; j < 4; j++)
                a1[j] += wr[0] * v[j] + wr[1] * v[j + 1] + wr[2] * v[j + 2];
        }
    }

    *reinterpret_cast<__nv_bfloat162*>(op + y0 * IMG + x0)     = __floats2bfloat162_rn(a0[0], a0[1]);
    *reinterpret_cast<__nv_bfloat162*>(op + y0 * IMG + x0 + 2) = __floats2bfloat162_rn(a0[2], a0[3]);
    *reinterpret_cast<__nv_bfloat162*>(op + (y0 + 1) * IMG + x0)     = __floats2bfloat162_rn(a1[0], a1[1]);
    *reinterpret_cast<__nv_bfloat162*>(op + (y0 + 1) * IMG + x0 + 2) = __floats2bfloat162_rn(a1[2], a1[3]);
}

// ---------------------------------------------------------------------------
// Fused FFN tail (unchanged).
// ---------------------------------------------------------------------------
__global__ void dwgate_kernel(const __nv_bfloat16* __restrict__ t,
                              const float* __restrict__ dwf,
                              __nv_bfloat16* __restrict__ gate) {
    int pl = blockIdx.z;
    int b = pl / HIDDEN, k = pl % HIDDEN;
    int x0 = (blockIdx.x * 32 + threadIdx.x) * 4;
    int y0 = (blockIdx.y * 8 + threadIdx.y) * 2;
    const __nv_bfloat16* i1 = t + ((size_t)b * 2 * HIDDEN + k) * HW;
    const __nv_bfloat16* i2 = t + ((size_t)b * 2 * HIDDEN + HIDDEN + k) * HW;
    const float* w1 = dwf + k * 9;
    const float* w2 = dwf + (HIDDEN + k) * 9;

    float wa[9], wb[9];
#pragma unroll
    for (int i = 0; i < 9; i++) { wa[i] = w1[i]; wb[i] = w2[i]; }

    float s1r0[4] = {0.f, 0.f, 0.f, 0.f}, s2r0[4] = {0.f, 0.f, 0.f, 0.f};
    float s1r1[4] = {0.f, 0.f, 0.f, 0.f}, s2r1[4] = {0.f, 0.f, 0.f, 0.f};
#pragma unroll
    for (int dy = -1; dy <= 2; dy++) {
        int yy = y0 + dy;
        if (yy < 0 || yy >= IMG) continue;
        const __nv_bfloat16* r1 = i1 + yy * IMG;
        const __nv_bfloat16* r2 = i2 + yy * IMG;
        float v1[6], v2[6];
        v1[0] = (x0 > 0) ? __bfloat162float(r1[x0 - 1]) : 0.f;
        v2[0] = (x0 > 0) ? __bfloat162float(r2[x0 - 1]) : 0.f;
        {
            const __nv_bfloat162* p1 = reinterpret_cast<const __nv_bfloat162*>(r1 + x0);
            const __nv_bfloat162* p2 = reinterpret_cast<const __nv_bfloat162*>(r2 + x0);
            float2 a1 = __bfloat1622float2(p1[0]), b1 = __bfloat1622float2(p1[1]);
            float2 a2 = __bfloat1622float2(p2[0]), b2 = __bfloat1622float2(p2[1]);
            v1[1] = a1.x; v1[2] = a1.y; v1[3] = b1.x; v1[4] = b1.y;
            v2[1] = a2.x; v2[2] = a2.y; v2[3] = b2.x; v2[4] = b2.y;
        }
        v1[5] = (x0 + 4 < IMG) ? __bfloat162float(r1[x0 + 4]) : 0.f;
        v2[5] = (x0 + 4 < IMG) ? __bfloat162float(r2[x0 + 4]) : 0.f;
        if (dy <= 1) {
            const float* wra = wa + (dy + 1) * 3;
            const float* wrb = wb + (dy + 1) * 3;
#pragma unroll
            for (int j = 0; j < 4; j++) {
                s1r0[j] += wra[0] * v1[j] + wra[1] * v1[j + 1] + wra[2] * v1[j + 2];
                s2r0[j] += wrb[0] * v2[j] + wrb[1] * v2[j + 1] + wrb[2] * v2[j + 2];
            }
        }
        if (dy >= 0) {
            const float* wra = wa + dy * 3;
            const float* wrb = wb + dy * 3;
#pragma unroll
            for (int j = 0; j < 4; j++) {
                s1r1[j] += wra[0] * v1[j] + wra[1] * v1[j + 1] + wra[2] * v1[j + 2];
                s2r1[j] += wrb[0] * v2[j] + wrb[1] * v2[j + 1] + wrb[2] * v2[j + 2];
            }
        }
    }

    float o0[4], o1[4];
#pragma unroll
    for (int j = 0; j < 4; j++) {
        float gl0 = 0.5f * s1r0[j] * (1.f + erff(s1r0[j] * 0.7071067811865475f));
        o0[j] = gl0 * s2r0[j];
        float gl1 = 0.5f * s1r1[j] * (1.f + erff(s1r1[j] * 0.7071067811865475f));
        o1[j] = gl1 * s2r1[j];
    }
    __nv_bfloat16* gp0 = gate + ((size_t)b * 288 + k) * HW + y0 * IMG + x0;
    __nv_bfloat16* gp1 = gp0 + IMG;
    *reinterpret_cast<__nv_bfloat162*>(gp0)     = __floats2bfloat162_rn(o0[0], o0[1]);
    *reinterpret_cast<__nv_bfloat162*>(gp0 + 2) = __floats2bfloat162_rn(o0[2], o0[3]);
    *reinterpret_cast<__nv_bfloat162*>(gp1)     = __floats2bfloat162_rn(o1[0], o1[1]);
    *reinterpret_cast<__nv_bfloat162*>(gp1 + 2) = __floats2bfloat162_rn(o1[2], o1[3]);
}

// ---------------------------------------------------------------------------
// Gram stage 1 v5: quadrant split, 32 px/thread (4 x uint4 per channel),
// amortizing the 48x5-shfl reduce tail over 4x the work.
// grid (32, HEADS, 2*BATCH): bid.x = chunk*4 + quad; chunk covers 8192 px.
// ---------------------------------------------------------------------------
__global__ void __launch_bounds__(256, 2) gram1_kernel(
        const __nv_bfloat16* __restrict__ qkvAd,
        const __nv_bfloat16* __restrict__ qkvBd,
        float* __restrict__ gpA, float* __restrict__ gpB) {
    int bx = blockIdx.x;
    int chunk = bx >> 2;
    int quad  = bx & 3;
    int qh = quad >> 1;
    int kh = quad & 1;
    int h = blockIdx.y;
    int b  = blockIdx.z >> 1;
    int br = blockIdx.z & 1;
    const __nv_bfloat16* qb = (br ? qkvAd : qkvBd) + ((size_t)b * 288 + h * CHEAD + qh * 6) * HW;
    const __nv_bfloat16* kb = (br ? qkvBd : qkvAd) + ((size_t)b * 288 + 96 + h * CHEAD + kh * 6) * HW;
    float* part = br ? gpB : gpA;

    float qsq[6], ksq[6];
    float acc[36];
#pragma unroll
    for (int i = 0; i < 36; i++) acc[i] = 0.f;
#pragma unroll
    for (int i = 0; i < 6; i++) { qsq[i] = 0.f; ksq[i] = 0.f; }

    int p0 = chunk * 8192 + threadIdx.x * 8;
#pragma unroll
    for (int it = 0; it < 4; it++) {
        int p = p0 + it * 2048;
        float qf[6][8];
#pragma unroll
        for (int c = 0; c < 6; c++) {
            uint4 u = *reinterpret_cast<const uint4*>(qb + (size_t)c * HW + p);
            unpack8(qf[c], u);
            float s = 0.f;
#pragma unroll
            for (int j = 0; j < 8; j++) s += qf[c][j] * qf[c][j];
            qsq[c] += s;
        }
#pragma unroll
        for (int d = 0; d < 6; d++) {
            uint4 u = *reinterpret_cast<const uint4*>(kb + (size_t)d * HW + p);
            float kf[8];
            unpack8(kf, u);
            float s = 0.f;
#pragma unroll
            for (int j = 0; j < 8; j++) s += kf[j] * kf[j];
            ksq[d] += s;
#pragma unroll
            for (int c = 0; c < 6; c++) {
                float a = acc[c * 6 + d];
#pragma unroll
                for (int j = 0; j < 8; j++) a += qf[c][j] * kf[j];
                acc[c * 6 + d] = a;
            }
        }
    }

    int warp = threadIdx.x >> 5;
    int lane = threadIdx.x & 31;
    float* outp = part + ((((size_t)(b * HEADS + h)) * 32 + bx) * 8 + warp) * 48;
#pragma unroll
    for (int i = 0; i < 48; i++) {
        float v = (i < 36) ? acc[i] : (i < 42 ? qsq[i - 36] : ksq[i - 42]);
#pragma unroll
        for (int off = 16; off > 0; off >>= 1)
            v += __shfl_down_sync(0xffffffffu, v, off);
        if (lane == 0) outp[i] = v;
    }
}

// ---------------------------------------------------------------------------
// Gram stage 2 + norms + temp + softmax + fused cw emission.
// Partial layout: [bh][chunk*4+quad][warp][48], 8 chunks.
// ---------------------------------------------------------------------------
__global__ void attn_kernel(const float* __restrict__ partA,
                            const float* __restrict__ partB,
                            const float* __restrict__ temp,
                            const float* __restrict__ P0,
                            const float* __restrict__ P1,
                            uint32_t* __restrict__ cwApk,
                            uint32_t* __restrict__ cwBpk) {
    int bh = blockIdx.x;
    int b = bh / HEADS;
    int h = bh % HEADS;
    __shared__ float GA[144], GB[144];
    __shared__ float nqA[12], nkA[12], nqB[12], nkB[12];
    int i = threadIdx.x;
    float sA = 0.f, sB = 0.f;
    if (i < 168) {
        int quad, off;
        if (i < 144) {
            int c = i / CHEAD, d = i % CHEAD;
            quad = (c / 6) * 2 + (d / 6);
            off  = (c % 6) * 6 + (d % 6);
        } else if (i < 156) {
            int c = i - 144;
            quad = (c / 6) * 2;
            off  = 36 + (c % 6);
        } else {
            int d = i - 156;
            quad = (d / 6);
            off  = 42 + (d % 6);
        }
        const float* pA = partA + (((size_t)bh * 32 + quad) * 8) * 48 + off;
        const float* pB = partB + (((size_t)bh * 32 + quad) * 8) * 48 + off;
        for (int ch = 0; ch < 8; ch++) {
#pragma unroll
            for (int w = 0; w < 8; w++) {
                size_t o = (size_t)ch * (4 * 8 * 48) + (size_t)w * 48;
                sA += pA[o];
                sB += pB[o];
            }
        }
        if (i >= 156) {
            nkA[i - 156] = fmaxf(sqrtf(sA), 1e-12f);
            nkB[i - 156] = fmaxf(sqrtf(sB), 1e-12f);
        } else if (i >= 144) {
            nqA[i - 144] = fmaxf(sqrtf(sA), 1e-12f);
            nqB[i - 144] = fmaxf(sqrtf(sB), 1e-12f);
        }
    }
    __syncthreads();
    if (i < 144) {
        int c = i / CHEAD, d = i % CHEAD;
        float tp = temp[h];
        GA[i] =  sA / (nqA[c] * nkA[d]) * tp;
        GB[i] = -sB / (nqB[c] * nkB[d]) * tp;
    }
    __syncthreads();
    if (i < 24) {
        float* G = (i < CHEAD) ? GA : GB;
        int c = i % CHEAD;
        float mx = -1e30f;
        for (int d = 0; d < CHEAD; d++) mx = fmaxf(mx, G[c * CHEAD + d]);
        float e[CHEAD];
        float s = 0.f;
        for (int d = 0; d < CHEAD; d++) {
            e[d] = expf(G[c * CHEAD + d] - mx);
            s += e[d];
        }
        float inv = 1.f / s;
        for (int d = 0; d < CHEAD; d++)
            G[c * CHEAD + d] = e[d] * inv;
    }
    __syncthreads();
    {
        int brn = i / 96;
        int m   = i % 96;
        const float* P  = brn ? P1 : P0;
        const float* AT = brn ? GB : GA;
        uint32_t* out = (brn ? cwBpk : cwApk) + (size_t)b * 9216;
        float pr[CHEAD];
#pragma unroll
        for (int c = 0; c < CHEAD; c++) pr[c] = P[m * 96 + h * CHEAD + c];
#pragma unroll
        for (int d = 0; d < CHEAD; d++) {
            float s = 0.f;
#pragma unroll
            for (int c = 0; c < CHEAD; c++) s += pr[c] * AT[c * CHEAD + d];
            out[a_pack_off(m, h * CHEAD + d)] = f2tf(s);
        }
    }
}

// ---------------------------------------------------------------------------
// Launch
// ---------------------------------------------------------------------------
extern "C" void kernel_launch(void* const* d_in, const int* in_sizes, int n_in,
                              void* d_out, int out_size) {
    const float* x       = (const float*)d_in[0];
    const float* y       = (const float*)d_in[1];
    const float* ln1_w   = (const float*)d_in[2];
    const float* ln1_b   = (const float*)d_in[3];
    const float* ln2_w   = (const float*)d_in[4];
    const float* ln2_b   = (const float*)d_in[5];
    const float* qkvA_w  = (const float*)d_in[6];
    const float* dwA_w   = (const float*)d_in[7];
    const float* qkvB_w  = (const float*)d_in[8];
    const float* dwB_w   = (const float*)d_in[9];
    const float* projA_w = (const float*)d_in[10];
    const float* projB_w = (const float*)d_in[11];
    const float* concat_w= (const float*)d_in[12];
    const float* temp    = (const float*)d_in[13];
    const float* pin_w   = (const float*)d_in[14];
    const float* dwf_w   = (const float*)d_in[15];
    const float* pout_w  = (const float*)d_in[16];
    float* out = (float*)d_out;

    cudaFuncSetAttribute(gemm96,   cudaFuncAttributeMaxDynamicSharedMemorySize, G96_SMEM_BYTES);
    cudaFuncSetAttribute(gemmPout, cudaFuncAttributeMaxDynamicSharedMemorySize, POUT_SMEM_BYTES);
    cudaFuncSetAttribute(gemm4_tc, cudaFuncAttributeMaxDynamicSharedMemorySize, G4_SMEM_BYTES);

    __nv_bfloat16 *qkvA, *qkvAd, *qkvB, *qkvBd, *t, *gate, *xn, *yn;
    float *x1, *gpA, *gpB, *P0, *P1;
    uint32_t *prepQA, *prepQB, *prepPin, *prepPout_p, *prepC0, *prepC1, *cwApk, *cwBpk;
    float *sQA, *tQA, *sQB, *tQB, *sPin, *tPin;
    cudaGetSymbolAddress((void**)&qkvA,   g_qkvA);
    cudaGetSymbolAddress((void**)&qkvAd,  g_qkvAd);
    cudaGetSymbolAddress((void**)&qkvB,   g_qkvB);
    cudaGetSymbolAddress((void**)&qkvBd,  g_qkvBd);
    cudaGetSymbolAddress((void**)&xn,     g_xn);
    cudaGetSymbolAddress((void**)&yn,     g_yn);
    cudaGetSymbolAddress((void**)&t,      g_t);
    cudaGetSymbolAddress((void**)&gate,   g_gate);
    cudaGetSymbolAddress((void**)&x1,     g_x1);
    cudaGetSymbolAddress((void**)&gpA,    g_gpartA);
    cudaGetSymbolAddress((void**)&gpB,    g_gpartB);
    cudaGetSymbolAddress((void**)&P0,     g_P0);
    cudaGetSymbolAddress((void**)&P1,     g_P1);
    cudaGetSymbolAddress((void**)&prepQA,   g_prepQA);
    cudaGetSymbolAddress((void**)&prepQB,   g_prepQB);
    cudaGetSymbolAddress((void**)&prepPin,  g_prepPin);
    cudaGetSymbolAddress((void**)&prepPout_p, g_prepPout);
    cudaGetSymbolAddress((void**)&prepC0,   g_prepC0);
    cudaGetSymbolAddress((void**)&prepC1,   g_prepC1);
    cudaGetSymbolAddress((void**)&cwApk,    g_cwApk);
    cudaGetSymbolAddress((void**)&cwBpk,    g_cwBpk);
    cudaGetSymbolAddress((void**)&sQA,    g_sQA);
    cudaGetSymbolAddress((void**)&tQA,    g_tQA);
    cudaGetSymbolAddress((void**)&sQB,    g_sQB);
    cudaGetSymbolAddress((void**)&tQB,    g_tQB);
    cudaGetSymbolAddress((void**)&sPin,   g_sPin);
    cudaGetSymbolAddress((void**)&tPin,   g_tPin);

    const size_t P96   = (size_t)CDIM * HW;
    const size_t P96E  = (size_t)CDIM * HW;
    const size_t P288E = (size_t)3 * CDIM * HW;
    const size_t P510E = (size_t)2 * HIDDEN * HW;
    const size_t PGATE = (size_t)288 * HW;

    megaprep<<<53, 256>>>(qkvA_w, qkvB_w, pin_w, pout_w, concat_w,
                          projA_w, projB_w, ln1_w, ln1_b, ln2_w, ln2_b,
                          prepQA, prepQB, prepPin, prepPout_p, prepC0, prepC1,
                          sQA, tQA, sQB, tQB, sPin, tPin, P0, P1);

    // qkv for both branches; also emits bf16 xn/yn for gemm4
    {
        G96P p;
        p.Apk[0] = prepQA; p.Apk[1] = prepQB;
        p.sv[0] = sQA; p.sv[1] = sQB;
        p.tv[0] = tQA; p.tv[1] = tQB;
        p.X[0] = x; p.X[1] = y;
        p.xnOut[0] = xn; p.xnOut[1] = yn;
        p.Y[0] = qkvA; p.Y[1] = qkvB;
        p.lnw = ln1_w; p.lnb = ln1_b;
        dim3 g(1, HW / 128, BATCH * 2);
        gemm96<<<g, 256, G96_SMEM_BYTES>>>(p, 288, 2, 3, P96, P288E);
    }

    // depthwise 3x3, both branches, 2 rows/thread
    {
        dim3 blk(32, 8), g(IMG / 128, IMG / 16, 2 * BATCH * 288);
        dw3_kernel<<<g, blk>>>(qkvA, qkvB, dwA_w, dwB_w, qkvAd, qkvBd);
    }

    // Gram quadrants, 32 px/thread
    {
        dim3 g(32, HEADS, 2 * BATCH);
        gram1_kernel<<<g, 256>>>(qkvAd, qkvBd, gpA, gpB);
    }

    // attn + fused cw emission
    attn_kernel<<<BATCH * HEADS, 192>>>(gpA, gpB, temp, P0, P1, cwApk, cwBpk);

    // fused x1 = x + cwA@vA + cwB@vB + C0@xn + C1@yn  (all-bf16 sources)
    {
        G4 p;
        p.Apk[0] = cwApk;  p.aBatch[0] = 9216;
        p.Apk[1] = cwBpk;  p.aBatch[1] = 9216;
        p.Apk[2] = prepC0; p.aBatch[2] = 0;
        p.Apk[3] = prepC1; p.aBatch[3] = 0;
        p.X[0] = qkvAd + 192 * (size_t)HW; p.xBatch[0] = P288E;
        p.X[1] = qkvBd + 192 * (size_t)HW; p.xBatch[1] = P288E;
        p.X[2] = xn;                       p.xBatch[2] = P96E;
        p.X[3] = yn;                       p.xBatch[3] = P96E;
        dim3 g(1, HW / 128, BATCH);
        gemm4_tc<<<g, 256, G4_SMEM_BYTES>>>(p, x, x1);
    }

    // pin = W@LN2(x1), B-resident with 6 m-tiles in-block
    {
        G96P p;
        p.Apk[0] = prepPin; p.Apk[1] = prepPin;
        p.sv[0] = sPin; p.sv[1] = sPin;
        p.tv[0] = tPin; p.tv[1] = tPin;
        p.X[0] = x1; p.X[1] = x1;
        p.xnOut[0] = nullptr; p.xnOut[1] = nullptr;
        p.Y[0] = t; p.Y[1] = t;
        p.lnw = ln2_w; p.lnb = ln2_b;
        dim3 g(1, HW / 128, BATCH);
        gemm96<<<g, 256, G96_SMEM_BYTES>>>(p, 510, 1, 6, P96, P510E);
    }

    // fused depthwise + gelu gate, 2 rows/thread
    {
        dim3 blk(32, 8), g(IMG / 128, IMG / 16, BATCH * HIDDEN);
        dwgate_kernel<<<g, blk>>>(t, dwf_w, gate);
    }

    // pout + residual x1 -> output
    {
        dim3 g(1, HW / 128, BATCH);
        gemmPout<<<g, 256, POUT_SMEM_BYTES>>>(prepPout_p, gate, x1, out,
                                              PGATE, P96, P96);
    }
}

// round 16
// speedup vs baseline: 5.8439x; 1.0891x over previous
#include <cuda_runtime.h>
#include <cuda_bf16.h>
#include <math.h>
#include <stdint.h>

#define HW      65536
#define IMG     256
#define BATCH   2
#define CDIM    96
#define HEADS   8
#define CHEAD   12
#define HIDDEN  255

// ---------------------------------------------------------------------------
// Scratch
// ---------------------------------------------------------------------------
__device__ __nv_bfloat16 g_qkvA [BATCH * 3 * CDIM * HW];
__device__ __nv_bfloat16 g_qkvAd[BATCH * 3 * CDIM * HW];
__device__ __nv_bfloat16 g_qkvB [BATCH * 3 * CDIM * HW];
__device__ __nv_bfloat16 g_qkvBd[BATCH * 3 * CDIM * HW];
__device__ __nv_bfloat16 g_xn   [BATCH * CDIM * HW];
__device__ __nv_bfloat16 g_yn   [BATCH * CDIM * HW];
__device__ __nv_bfloat16 g_t    [BATCH * 2 * HIDDEN * HW];
__device__ __nv_bfloat16 g_gate [BATCH * 288 * HW];   // 288-pitch; rows 255..287 stay zero
__device__ float g_x1   [BATCH * CDIM * HW];
// Gram partials: [bh][chunk*4+quad][warp][48]  (8 chunks)
__device__ float g_gpartA[BATCH * HEADS * 32 * 8 * 48];
__device__ float g_gpartB[BATCH * HEADS * 32 * 8 * 48];
__device__ float g_P0  [CDIM * CDIM];
__device__ float g_P1  [CDIM * CDIM];
// prepacked tf32 fragment tiles
__device__ uint32_t g_prepQA  [3 * 9216];
__device__ uint32_t g_prepQB  [3 * 9216];
__device__ uint32_t g_prepPin [6 * 9216];
__device__ uint32_t g_prepPout[3 * 9216];
__device__ uint32_t g_prepC0  [9216];
__device__ uint32_t g_prepC1  [9216];
__device__ uint32_t g_cwApk   [BATCH * 9216];
__device__ uint32_t g_cwBpk   [BATCH * 9216];
__device__ float g_sQA[288],  g_tQA[288];
__device__ float g_sQB[288],  g_tQB[288];
__device__ float g_sPin[576], g_tPin[576];

// ---------------------------------------------------------------------------
// tf32 / cp.async helpers
// ---------------------------------------------------------------------------
__device__ __forceinline__ uint32_t f2tf(float f) {
    uint32_t u;
    asm("cvt.rna.tf32.f32 %0, %1;" : "=r"(u) : "f"(f));
    return u;
}

__device__ __forceinline__ void mma_tf32(float* c, const uint32_t* a, const uint32_t* b) {
    asm volatile(
        "mma.sync.aligned.m16n8k8.row.col.f32.tf32.tf32.f32 "
        "{%0,%1,%2,%3}, {%4,%5,%6,%7}, {%8,%9}, {%0,%1,%2,%3};"
        : "+f"(c[0]), "+f"(c[1]), "+f"(c[2]), "+f"(c[3])
        : "r"(a[0]), "r"(a[1]), "r"(a[2]), "r"(a[3]), "r"(b[0]), "r"(b[1]));
}

__device__ __forceinline__ void cp16(void* smem, const void* gmem) {
    uint32_t a = (uint32_t)__cvta_generic_to_shared(smem);
    asm volatile("cp.async.cg.shared.global [%0], [%1], 16;\n" :: "r"(a), "l"(gmem));
}
#define CP_COMMIT()  asm volatile("cp.async.commit_group;\n")
#define CP_WAIT(n)   asm volatile("cp.async.wait_group %0;\n" :: "n"(n))

__device__ __forceinline__ int a_pack_off(int m, int k) {
    return (k >> 3) * 768 + (m >> 4) * 128 + (m & 7) * 16 + (k & 3) * 4
         + ((k >> 2) & 1) * 2 + ((m >> 3) & 1);
}

// unpack uint4 (8 bf16) -> 8 floats via bit shifts
__device__ __forceinline__ void unpack8(float* f, uint4 u) {
    f[0] = __uint_as_float(u.x << 16); f[1] = __uint_as_float(u.x & 0xFFFF0000u);
    f[2] = __uint_as_float(u.y << 16); f[3] = __uint_as_float(u.y & 0xFFFF0000u);
    f[4] = __uint_as_float(u.z << 16); f[5] = __uint_as_float(u.z & 0xFFFF0000u);
    f[6] = __uint_as_float(u.w << 16); f[7] = __uint_as_float(u.w & 0xFFFF0000u);
}

__device__ __forceinline__ uint32_t packbf2(float lo, float hi) {
    __nv_bfloat162 h = __floats2bfloat162_rn(lo, hi);
    return *reinterpret_cast<uint32_t*>(&h);
}

// gemm4: A tile + full B panel
#define G4_SMEM_WORDS   (9216 + 96*136)
#define G4_SMEM_BYTES   (G4_SMEM_WORDS * 4)
// gemm96: full B panel + one A tile + stats + ln vectors
#define G96_SMEM_WORDS  (96*136 + 9216 + 256 + 192)
#define G96_SMEM_BYTES  (G96_SMEM_WORDS * 4)
// pout: double-buffered 32-row B ring
#define POUT_SMEM_WORDS (9216 + 2*32*136)
#define POUT_SMEM_BYTES (POUT_SMEM_WORDS * 4)

// ---------------------------------------------------------------------------
// Mega-prep (unchanged).
// ---------------------------------------------------------------------------
__device__ void prep_tile(const float* __restrict__ W, int M, int tile,
                          const float* __restrict__ wln,
                          const float* __restrict__ bln,
                          uint32_t* __restrict__ Apk,
                          float* __restrict__ svec, float* __restrict__ tvec,
                          float* wls, float* bls) {
    int m0 = tile * 96;
    if (threadIdx.x < 96) { wls[threadIdx.x] = wln[threadIdx.x]; bls[threadIdx.x] = bln[threadIdx.x]; }
    __syncthreads();
#pragma unroll
    for (int i = 0; i < 36; i++) {
        int idx = threadIdx.x + i * 256;
        int m = idx / 96;
        int k = idx - m * 96;
        float v = 0.f;
        if (m0 + m < M) v = W[(size_t)(m0 + m) * 96 + k] * wls[k];
        Apk[tile * 9216 + a_pack_off(m, k)] = f2tf(v);
    }
    if (threadIdx.x < 96) {
        int gm = m0 + threadIdx.x;
        float s = 0.f, tt = 0.f;
        if (gm < M) {
            for (int k = 0; k < 96; k++) {
                float w = W[(size_t)gm * 96 + k];
                s  += w * wls[k];
                tt += w * bls[k];
            }
        }
        svec[tile * 96 + threadIdx.x] = s;
        tvec[tile * 96 + threadIdx.x] = tt;
    }
}

__global__ void megaprep(
        const float* __restrict__ qkvA_w, const float* __restrict__ qkvB_w,
        const float* __restrict__ pin_w,  const float* __restrict__ pout_w,
        const float* __restrict__ concat_w,
        const float* __restrict__ projA_w, const float* __restrict__ projB_w,
        const float* __restrict__ ln1_w, const float* __restrict__ ln1_b,
        const float* __restrict__ ln2_w, const float* __restrict__ ln2_b,
        uint32_t* __restrict__ prepQA, uint32_t* __restrict__ prepQB,
        uint32_t* __restrict__ prepPin, uint32_t* __restrict__ prepPout,
        uint32_t* __restrict__ prepC0, uint32_t* __restrict__ prepC1,
        float* __restrict__ sQA, float* __restrict__ tQA,
        float* __restrict__ sQB, float* __restrict__ tQB,
        float* __restrict__ sPin, float* __restrict__ tPin,
        float* __restrict__ P0, float* __restrict__ P1) {
    __shared__ float sbuf[96 * 96];
    int bid = blockIdx.x;
    if (bid < 3) {
        prep_tile(qkvA_w, 288, bid, ln1_w, ln1_b, prepQA, sQA, tQA, sbuf, sbuf + 96);
    } else if (bid < 6) {
        prep_tile(qkvB_w, 288, bid - 3, ln1_w, ln1_b, prepQB, sQB, tQB, sbuf, sbuf + 96);
    } else if (bid < 12) {
        prep_tile(pin_w, 510, bid - 6, ln2_w, ln2_b, prepPin, sPin, tPin, sbuf, sbuf + 96);
    } else if (bid < 15) {
        int s = bid - 12;
#pragma unroll
        for (int i = 0; i < 36; i++) {
            int idx = threadIdx.x + i * 256;
            int m = idx / 96;
            int k = idx - m * 96;
            int kg = s * 96 + k;
            float v = (kg < HIDDEN) ? pout_w[(size_t)m * HIDDEN + kg] : 0.f;
            prepPout[s * 9216 + a_pack_off(m, k)] = f2tf(v);
        }
    } else if (bid < 17) {
        const float* W = concat_w + (bid == 16 ? 96 : 0);
        uint32_t* out = (bid == 16) ? prepC1 : prepC0;
#pragma unroll
        for (int i = 0; i < 36; i++) {
            int idx = threadIdx.x + i * 256;
            int m = idx / 96;
            int k = idx - m * 96;
            out[a_pack_off(m, k)] = f2tf(W[(size_t)m * 192 + k]);
        }
    } else {
        int w = bid - 17;
        int br = w & 1;
        int yt = w >> 1;
        const float* proj = br ? projB_w : projA_w;
        const float* cw   = concat_w + (br ? 96 : 0);
        float* P = br ? P1 : P0;
        for (int i = threadIdx.x; i < 96 * 96; i += 256) sbuf[i] = proj[i];
        __syncthreads();
        int base = yt * 512;
#pragma unroll
        for (int r = 0; r < 2; r++) {
            int o = base + r * 256 + threadIdx.x;
            int m = o / 96, n = o % 96;
            float s = 0.f;
#pragma unroll 8
            for (int c = 0; c < 96; c++) s += cw[m * 192 + c] * sbuf[c * 96 + n];
            P[o] = s;
        }
    }
}

// ---------------------------------------------------------------------------
// 32-k MMA chunk on the 96x128 tile.
// ---------------------------------------------------------------------------
__device__ __forceinline__ void g96_chunk(
        float acc[3][4][4], const uint32_t* __restrict__ As,
        const uint32_t* __restrict__ Bbuf,
        int kc, int g, int t, int wmi, int wn) {
#pragma unroll
    for (int ks2 = 0; ks2 < 4; ks2++) {
        const uint32_t* Ab = As + (kc * 4 + ks2) * 768 + g * 16 + t * 4;
        const uint32_t* Bb = Bbuf + (ks2 * 8 + t) * 136 + wn + g;
        uint4 a4[3];
        uint32_t bf[4][2];
#pragma unroll
        for (int mi = 0; mi < 3; mi++)
            a4[mi] = *reinterpret_cast<const uint4*>(Ab + (wmi + mi) * 128);
#pragma unroll
        for (int ni = 0; ni < 4; ni++) {
            bf[ni][0] = Bb[ni * 8];
            bf[ni][1] = Bb[4 * 136 + ni * 8];
        }
#pragma unroll
        for (int mi = 0; mi < 3; mi++) {
            uint32_t af[4] = {a4[mi].x, a4[mi].y, a4[mi].z, a4[mi].w};
#pragma unroll
            for (int ni = 0; ni < 4; ni++)
                mma_tf32(acc[mi][ni], af, bf[ni]);
        }
    }
}

// ---------------------------------------------------------------------------
// B-resident multi-M gemm96 + optional bf16 LN(x) emission (unchanged).
// ---------------------------------------------------------------------------
struct G96P {
    const uint32_t* Apk[2];
    const float*    sv[2];
    const float*    tv[2];
    const float*    X[2];
    __nv_bfloat16*  xnOut[2];    // may be null
    __nv_bfloat16*  Y[2];
    const float*    lnw;
    const float*    lnb;
};

__global__ void __launch_bounds__(256, 2) gemm96(
        G96P p, int M, int NB, int Mtiles, size_t xBatch, size_t yBatch) {
    extern __shared__ uint32_t sm[];
    uint32_t* Bs = sm;                       // 96*136 = 13056
    uint32_t* As = sm + 13056;               // 9216
    float* mu_s  = (float*)(sm + 13056 + 9216);
    float* inv_s = mu_s + 128;
    float* wl_s  = inv_s + 128;              // 96
    float* bl_s  = wl_s + 96;                // 96

    int z  = blockIdx.z;
    int br = z % NB;
    int bz = z / NB;
    const float* Xb = p.X[br] + (size_t)bz * xBatch;
    __nv_bfloat16* Yb = p.Y[br] + (size_t)bz * yBatch;
    const float* svec = p.sv[br];
    const float* tvec = p.tv[br];
    const uint32_t* Apk = p.Apk[br];
    bool hasXn = (p.xnOut[br] != nullptr);

    int n0 = blockIdx.y * 128;
    int tid  = threadIdx.x;
    int warp = tid >> 5;
    int lane = tid & 31;
    int g = lane >> 2;
    int t = lane & 3;
    int wm  = (warp >> 2) * 48;
    int wmi = (warp >> 2) * 3;
    int wn  = (warp & 3) * 32;

#define LOADA96(mt)                                                          \
    {                                                                        \
        const uint4* Ag = reinterpret_cast<const uint4*>(Apk + (size_t)(mt) * 9216); \
        _Pragma("unroll")                                                    \
        for (int i = 0; i < 9; i++) {                                        \
            int idx = tid + i * 256;                                         \
            cp16(As + idx * 4, Ag + idx);                                    \
        }                                                                    \
    }

#pragma unroll
    for (int j = 0; j < 12; j++) {
        int idx = tid + j * 256;
        int k = idx >> 5, n4 = idx & 31;
        cp16(Bs + k * 136 + n4 * 4, Xb + (size_t)k * HW + n0 + n4 * 4);
    }
    LOADA96(0);
    CP_COMMIT();
    if (hasXn && tid < 96) { wl_s[tid] = p.lnw[tid]; bl_s[tid] = p.lnb[tid]; }
    CP_WAIT(0);
    __syncthreads();

    if (tid < 128) {
        float csum = 0.f, csq = 0.f;
#pragma unroll 8
        for (int k = 0; k < 96; k++) {
            float v = __uint_as_float(Bs[k * 136 + tid]);
            csum += v; csq += v * v;
        }
        float mu  = csum * (1.f / 96.f);
        float var = csq * (1.f / 96.f) - mu * mu;
        mu_s[tid]  = mu;
        inv_s[tid] = rsqrtf(var + 1e-5f);
    }
    __syncthreads();

    if (hasXn) {
        __nv_bfloat16* xo = p.xnOut[br] + (size_t)bz * CDIM * HW + n0;
        int c2 = (tid & 63) * 2;
        int rb = tid >> 6;
        float m0v = mu_s[c2],     i0 = inv_s[c2];
        float m1v = mu_s[c2 + 1], i1 = inv_s[c2 + 1];
#pragma unroll
        for (int it = 0; it < 24; it++) {
            int r = it * 4 + rb;
            float v0 = __uint_as_float(Bs[r * 136 + c2]);
            float v1 = __uint_as_float(Bs[r * 136 + c2 + 1]);
            float w = wl_s[r], bb = bl_s[r];
            *reinterpret_cast<__nv_bfloat162*>(xo + (size_t)r * HW + c2) =
                __floats2bfloat162_rn((v0 - m0v) * i0 * w + bb,
                                      (v1 - m1v) * i1 * w + bb);
        }
    }

    for (int mt = 0; mt < Mtiles; mt++) {
        int m0 = mt * 96;
        float acc[3][4][4];
#pragma unroll
        for (int mi = 0; mi < 3; mi++)
#pragma unroll
            for (int ni = 0; ni < 4; ni++)
#pragma unroll
                for (int r = 0; r < 4; r++) acc[mi][ni][r] = 0.f;

#pragma unroll
        for (int kc = 0; kc < 3; kc++)
            g96_chunk(acc, As, Bs + kc * 4352, kc, g, t, wmi, wn);

        __syncthreads();
        if (mt + 1 < Mtiles) {
            LOADA96(mt + 1);
            CP_COMMIT();
        }

#pragma unroll
        for (int mi = 0; mi < 3; mi++) {
            int r0 = m0 + wm + mi * 16 + g;
            int r1 = r0 + 8;
            float s0 = 0.f, t0 = 0.f, s1 = 0.f, t1 = 0.f;
            if (r0 < M) { s0 = svec[r0]; t0 = tvec[r0]; }
            if (r1 < M) { s1 = svec[r1]; t1 = tvec[r1]; }
#pragma unroll
            for (int ni = 0; ni < 4; ni++) {
                int ln = wn + ni * 8 + 2 * t;
                int col = n0 + ln;
                float i0 = inv_s[ln],     m0v = mu_s[ln]     * i0;
                float i1 = inv_s[ln + 1], m1v = mu_s[ln + 1] * i1;
                if (r0 < M) {
                    float vx = acc[mi][ni][0] * i0 - m0v * s0 + t0;
                    float vy = acc[mi][ni][1] * i1 - m1v * s0 + t0;
                    *reinterpret_cast<__nv_bfloat162*>(Yb + (size_t)r0 * HW + col) =
                        __floats2bfloat162_rn(vx, vy);
                }
                if (r1 < M) {
                    float vx = acc[mi][ni][2] * i0 - m0v * s1 + t1;
                    float vy = acc[mi][ni][3] * i1 - m1v * s1 + t1;
                    *reinterpret_cast<__nv_bfloat162*>(Yb + (size_t)r1 * HW + col) =
                        __floats2bfloat162_rn(vx, vy);
                }
            }
        }

        if (mt + 1 < Mtiles) {
            CP_WAIT(0);
            __syncthreads();
        }
    }
#undef LOADA96
}

// ---------------------------------------------------------------------------
// pout (unchanged).
// ---------------------------------------------------------------------------
__global__ void __launch_bounds__(256, 3) gemmPout(
        const uint32_t* __restrict__ Apk,
        const __nv_bfloat16* __restrict__ X,
        const float* __restrict__ Rsrc,
        float* __restrict__ Y,
        size_t xBatch, size_t yBatch, size_t rBatch) {
    extern __shared__ uint32_t sm[];
    uint32_t* As = sm;
    uint32_t* Bs = sm + 9216;

    int bz = blockIdx.z;
    const __nv_bfloat16* Xb = X + (size_t)bz * xBatch;
    float*       Yb = Y    + (size_t)bz * yBatch;
    const float* Rb = Rsrc + (size_t)bz * rBatch;

    int n0 = blockIdx.y * 128;
    int tid  = threadIdx.x;
    int warp = tid >> 5;
    int lane = tid & 31;
    int g = lane >> 2;
    int t = lane & 3;
    int wm  = (warp >> 2) * 48;
    int wmi = (warp >> 2) * 3;
    int wn  = (warp & 3) * 32;

    int kk = tid >> 3;
    int nb = (tid & 7) * 16;

    uint4 rA, rB;
#define LDGB(c)                                                             \
    {                                                                       \
        const uint4* src = reinterpret_cast<const uint4*>(                  \
            Xb + (size_t)((c) * 32 + kk) * HW + n0 + nb);                   \
        rA = src[0]; rB = src[1];                                           \
    }
#define STSB(c)                                                             \
    {                                                                       \
        uint32_t* dst = Bs + ((c) & 1) * 4352 + kk * 136 + nb;              \
        uint32_t u;                                                         \
        u = rA.x; dst[0]  = u << 16; dst[1]  = u & 0xFFFF0000u;             \
        u = rA.y; dst[2]  = u << 16; dst[3]  = u & 0xFFFF0000u;             \
        u = rA.z; dst[4]  = u << 16; dst[5]  = u & 0xFFFF0000u;             \
        u = rA.w; dst[6]  = u << 16; dst[7]  = u & 0xFFFF0000u;             \
        u = rB.x; dst[8]  = u << 16; dst[9]  = u & 0xFFFF0000u;             \
        u = rB.y; dst[10] = u << 16; dst[11] = u & 0xFFFF0000u;             \
        u = rB.z; dst[12] = u << 16; dst[13] = u & 0xFFFF0000u;             \
        u = rB.w; dst[14] = u << 16; dst[15] = u & 0xFFFF0000u;             \
    }
#define LOADA(s)                                                            \
    {                                                                       \
        const uint4* Ag = reinterpret_cast<const uint4*>(Apk + (s) * 9216); \
        _Pragma("unroll")                                                   \
        for (int i = 0; i < 9; i++) {                                       \
            int idx = tid + i * 256;                                        \
            cp16(As + idx * 4, Ag + idx);                                   \
        }                                                                   \
        CP_COMMIT();                                                        \
    }

    LOADA(0);
    LDGB(0);
    STSB(0);
    LDGB(1);
    CP_WAIT(0);
    __syncthreads();

    float acc[3][4][4];
#pragma unroll
    for (int mi = 0; mi < 3; mi++)
#pragma unroll
        for (int ni = 0; ni < 4; ni++)
#pragma unroll
            for (int r = 0; r < 4; r++) acc[mi][ni][r] = 0.f;

#pragma unroll
    for (int c = 0; c < 9; c++) {
        g96_chunk(acc, As, Bs + (c & 1) * 4352, c % 3, g, t, wmi, wn);
        if (c < 8) {
            __syncthreads();
            bool newA = (c % 3 == 2);
            if (newA) LOADA(c / 3 + 1);
            STSB(c + 1);
            if (c + 2 <= 8) LDGB(c + 2);
            if (newA) CP_WAIT(0);
            __syncthreads();
        }
    }
#undef LOADA
#undef LDGB
#undef STSB

#pragma unroll
    for (int mi = 0; mi < 3; mi++) {
        int r0 = wm + mi * 16 + g;
        int r1 = r0 + 8;
#pragma unroll
        for (int ni = 0; ni < 4; ni++) {
            int col = n0 + wn + ni * 8 + 2 * t;
            float2 ra = *reinterpret_cast<const float2*>(Rb + (size_t)r0 * HW + col);
            float2 rb = *reinterpret_cast<const float2*>(Rb + (size_t)r1 * HW + col);
            float2 v01 = make_float2(acc[mi][ni][0] + ra.x, acc[mi][ni][1] + ra.y);
            float2 v23 = make_float2(acc[mi][ni][2] + rb.x, acc[mi][ni][3] + rb.y);
            *reinterpret_cast<float2*>(Yb + (size_t)r0 * HW + col) = v01;
            *reinterpret_cast<float2*>(Yb + (size_t)r1 * HW + col) = v23;
        }
    }
}

// ---------------------------------------------------------------------------
// gemm4 v2 (unchanged).
// ---------------------------------------------------------------------------
struct G4 {
    const uint32_t*      Apk[4];
    size_t               aBatch[4];
    const __nv_bfloat16* X[4];
    size_t               xBatch[4];
};

__global__ void __launch_bounds__(256, 2) gemm4_tc(
        G4 p,
        const float* __restrict__ Rsrc,
        float* __restrict__ Y) {
    extern __shared__ uint32_t smem_u[];
    uint32_t* As = smem_u;          // 9216
    uint32_t* Bs = As + 9216;       // 13056

    int bz = blockIdx.z;
    int n0 = blockIdx.y * 128;
    float*       Yb = Y    + (size_t)bz * CDIM * HW;
    const float* Rb = Rsrc + (size_t)bz * CDIM * HW;

    int tid  = threadIdx.x;
    int warp = tid >> 5;
    int lane = tid & 31;
    int g = lane >> 2;
    int t = lane & 3;
    int wm  = (warp >> 2) * 48;
    int wmi = (warp >> 2) * 3;
    int wn  = (warp & 3) * 32;

    uint4 rB[6];
#define LDGB4(s)                                                             \
    {                                                                        \
        const __nv_bfloat16* Xh = p.X[s] + (size_t)bz * p.xBatch[s];         \
        _Pragma("unroll")                                                    \
        for (int i = 0; i < 6; i++) {                                        \
            int idx = tid + i * 256;                                         \
            int k = idx >> 4, n8 = idx & 15;                                 \
            rB[i] = *reinterpret_cast<const uint4*>(Xh + (size_t)k * HW + n0 + n8 * 8); \
        }                                                                    \
    }
#define STSB4()                                                              \
    {                                                                        \
        _Pragma("unroll")                                                    \
        for (int i = 0; i < 6; i++) {                                        \
            int idx = tid + i * 256;                                         \
            int k = idx >> 4, n8 = idx & 15;                                 \
            uint32_t* dst = Bs + k * 136 + n8 * 8;                           \
            uint32_t u;                                                      \
            u = rB[i].x; dst[0] = u << 16; dst[1] = u & 0xFFFF0000u;         \
            u = rB[i].y; dst[2] = u << 16; dst[3] = u & 0xFFFF0000u;         \
            u = rB[i].z; dst[4] = u << 16; dst[5] = u & 0xFFFF0000u;         \
            u = rB[i].w; dst[6] = u << 16; dst[7] = u & 0xFFFF0000u;         \
        }                                                                    \
    }
#define LOADA4(s)                                                            \
    {                                                                        \
        const uint4* Ag = reinterpret_cast<const uint4*>(p.Apk[s] + (size_t)bz * p.aBatch[s]); \
        _Pragma("unroll")                                                    \
        for (int i = 0; i < 9; i++) {                                        \
            int idx = tid + i * 256;                                         \
            cp16(As + idx * 4, Ag + idx);                                    \
        }                                                                    \
        CP_COMMIT();                                                         \
    }

    LOADA4(0);
    LDGB4(0);

    float acc[3][4][4];
#pragma unroll
    for (int mi = 0; mi < 3; mi++)
#pragma unroll
        for (int ni = 0; ni < 4; ni++)
#pragma unroll
            for (int r = 0; r < 4; r++) acc[mi][ni][r] = 0.f;

#pragma unroll
    for (int s = 0; s < 4; s++) {
        CP_WAIT(0);
        __syncthreads();
        STSB4();
        __syncthreads();
        if (s < 3) LDGB4(s + 1);
#pragma unroll
        for (int ks = 0; ks < 12; ks++) {
            const uint32_t* Ab = As + ks * 768 + g * 16 + t * 4;
            const uint32_t* Bb = Bs + (ks * 8 + t) * 136 + wn + g;
            uint4 a4[3];
            uint32_t bf[4][2];
#pragma unroll
            for (int mi = 0; mi < 3; mi++)
                a4[mi] = *reinterpret_cast<const uint4*>(Ab + (wmi + mi) * 128);
#pragma unroll
            for (int ni = 0; ni < 4; ni++) {
                bf[ni][0] = Bb[ni * 8];
                bf[ni][1] = Bb[4 * 136 + ni * 8];
            }
#pragma unroll
            for (int mi = 0; mi < 3; mi++) {
                uint32_t af[4] = {a4[mi].x, a4[mi].y, a4[mi].z, a4[mi].w};
#pragma unroll
                for (int ni = 0; ni < 4; ni++)
                    mma_tf32(acc[mi][ni], af, bf[ni]);
            }
        }
        __syncthreads();
        if (s < 3) LOADA4(s + 1);
    }

#pragma unroll
    for (int mi = 0; mi < 3; mi++) {
        int r0 = wm + mi * 16 + g;
        int r1 = r0 + 8;
#pragma unroll
        for (int ni = 0; ni < 4; ni++) {
            int col = n0 + wn + ni * 8 + 2 * t;
            float2 ra = *reinterpret_cast<const float2*>(Rb + (size_t)r0 * HW + col);
            float2 rb = *reinterpret_cast<const float2*>(Rb + (size_t)r1 * HW + col);
            float2 v01 = make_float2(acc[mi][ni][0] + ra.x, acc[mi][ni][1] + ra.y);
            float2 v23 = make_float2(acc[mi][ni][2] + rb.x, acc[mi][ni][3] + rb.y);
            *reinterpret_cast<float2*>(Yb + (size_t)r0 * HW + col) = v01;
            *reinterpret_cast<float2*>(Yb + (size_t)r1 * HW + col) = v23;
        }
    }
#undef LOADA4
#undef LDGB4
#undef STSB4
}

// ---------------------------------------------------------------------------
// Depthwise 3x3, 8 px x 2 rows per thread. One warp covers a full 256-px row.
// grid: (1, IMG/16, 2*BATCH*288), block (32, 8).
// ---------------------------------------------------------------------------
__global__ void dw3_kernel(const __nv_bfloat16* __restrict__ qA,
                           const __nv_bfloat16* __restrict__ qB,
                           const float* __restrict__ wA,
                           const float* __restrict__ wB,
                           __nv_bfloat16* __restrict__ oA,
                           __nv_bfloat16* __restrict__ oB) {
    int pl = blockIdx.z;
    int br = pl >= BATCH * 288;
    int rem = pl - br * BATCH * 288;
    int c = rem % 288;
    const __nv_bfloat16* ip = (br ? qB : qA) + (size_t)rem * HW;
    const float* wp = (br ? wB : wA) + c * 9;
    __nv_bfloat16* op = (br ? oB : oA) + (size_t)rem * HW;

    int x0 = threadIdx.x * 8;
    int y0 = (blockIdx.y * 8 + threadIdx.y) * 2;

    float w[9];
#pragma unroll
    for (int i = 0; i < 9; i++) w[i] = wp[i];

    float a0[8] = {0.f, 0.f, 0.f, 0.f, 0.f, 0.f, 0.f, 0.f};
    float a1[8] = {0.f, 0.f, 0.f, 0.f, 0.f, 0.f, 0.f, 0.f};
#pragma unroll
    for (int dy = -1; dy <= 2; dy++) {
        int yy = y0 + dy;
        if (yy < 0 || yy >= IMG) continue;
        const __nv_bfloat16* row = ip + yy * IMG;
        float v[10];
        v[0] = (x0 > 0) ? __bfloat162float(row[x0 - 1]) : 0.f;
        unpack8(v + 1, *reinterpret_cast<const uint4*>(row + x0));
        v[9] = (x0 + 8 < IMG) ? __bfloat162float(row[x0 + 8]) : 0.f;
        if (dy <= 1) {
            const float* wr = w + (dy + 1) * 3;
#pragma unroll
            for (int j = 0; j < 8; j++)
                a0[j] += wr[0] * v[j] + wr[1] * v[j + 1] + wr[2] * v[j + 2];
        }
        if (dy >= 0) {
            const float* wr = w + dy * 3;
#pragma unroll
            for (int j = 0; j < 8; j++)
                a1[j] += wr[0] * v[j] + wr[1] * v[j + 1] + wr[2] * v[j + 2];
        }
    }

    uint4 o0 = make_uint4(packbf2(a0[0], a0[1]), packbf2(a0[2], a0[3]),
                          packbf2(a0[4], a0[5]), packbf2(a0[6], a0[7]));
    uint4 o1 = make_uint4(packbf2(a1[0], a1[1]), packbf2(a1[2], a1[3]),
                          packbf2(a1[4], a1[5]), packbf2(a1[6], a1[7]));
    *reinterpret_cast<uint4*>(op + y0 * IMG + x0)       = o0;
    *reinterpret_cast<uint4*>(op + (y0 + 1) * IMG + x0) = o1;
}

// ---------------------------------------------------------------------------
// Fused FFN tail: dw3 on both t halves + gelu + multiply; 8 px x 2 rows.
// grid: (1, IMG/16, BATCH*HIDDEN), block (32, 8).
// ---------------------------------------------------------------------------
__global__ void dwgate_kernel(const __nv_bfloat16* __restrict__ t,
                              const float* __restrict__ dwf,
                              __nv_bfloat16* __restrict__ gate) {
    int pl = blockIdx.z;
    int b = pl / HIDDEN, k = pl % HIDDEN;
    int x0 = threadIdx.x * 8;
    int y0 = (blockIdx.y * 8 + threadIdx.y) * 2;
    const __nv_bfloat16* i1 = t + ((size_t)b * 2 * HIDDEN + k) * HW;
    const __nv_bfloat16* i2 = t + ((size_t)b * 2 * HIDDEN + HIDDEN + k) * HW;
    const float* w1 = dwf + k * 9;
    const float* w2 = dwf + (HIDDEN + k) * 9;

    float wa[9], wb[9];
#pragma unroll
    for (int i = 0; i < 9; i++) { wa[i] = w1[i]; wb[i] = w2[i]; }

    float s1r0[8] = {0,0,0,0,0,0,0,0}, s2r0[8] = {0,0,0,0,0,0,0,0};
    float s1r1[8] = {0,0,0,0,0,0,0,0}, s2r1[8] = {0,0,0,0,0,0,0,0};
#pragma unroll
    for (int dy = -1; dy <= 2; dy++) {
        int yy = y0 + dy;
        if (yy < 0 || yy >= IMG) continue;
        const __nv_bfloat16* r1 = i1 + yy * IMG;
        const __nv_bfloat16* r2 = i2 + yy * IMG;
        float v1[10], v2[10];
        v1[0] = (x0 > 0) ? __bfloat162float(r1[x0 - 1]) : 0.f;
        v2[0] = (x0 > 0) ? __bfloat162float(r2[x0 - 1]) : 0.f;
        unpack8(v1 + 1, *reinterpret_cast<const uint4*>(r1 + x0));
        unpack8(v2 + 1, *reinterpret_cast<const uint4*>(r2 + x0));
        v1[9] = (x0 + 8 < IMG) ? __bfloat162float(r1[x0 + 8]) : 0.f;
        v2[9] = (x0 + 8 < IMG) ? __bfloat162float(r2[x0 + 8]) : 0.f;
        if (dy <= 1) {
            const float* wra = wa + (dy + 1) * 3;
            const float* wrb = wb + (dy + 1) * 3;
#pragma unroll
            for (int j = 0; j < 8; j++) {
                s1r0[j] += wra[0] * v1[j] + wra[1] * v1[j + 1] + wra[2] * v1[j + 2];
                s2r0[j] += wrb[0] * v2[j] + wrb[1] * v2[j + 1] + wrb[2] * v2[j + 2];
            }
        }
        if (dy >= 0) {
            const float* wra = wa + dy * 3;
            const float* wrb = wb + dy * 3;
#pragma unroll
            for (int j = 0; j < 8; j++) {
                s1r1[j] += wra[0] * v1[j] + wra[1] * v1[j + 1] + wra[2] * v1[j + 2];
                s2r1[j] += wrb[0] * v2[j] + wrb[1] * v2[j + 1] + wrb[2] * v2[j + 2];
            }
        }
    }

    float o0[8], o1[8];
#pragma unroll
    for (int j = 0; j < 8; j++) {
        float gl0 = 0.5f * s1r0[j] * (1.f + erff(s1r0[j] * 0.7071067811865475f));
        o0[j] = gl0 * s2r0[j];
        float gl1 = 0.5f * s1r1[j] * (1.f + erff(s1r1[j] * 0.7071067811865475f));
        o1[j] = gl1 * s2r1[j];
    }
    __nv_bfloat16* gp = gate + ((size_t)b * 288 + k) * HW + y0 * IMG + x0;
    uint4 u0 = make_uint4(packbf2(o0[0], o0[1]), packbf2(o0[2], o0[3]),
                          packbf2(o0[4], o0[5]), packbf2(o0[6], o0[7]));
    uint4 u1 = make_uint4(packbf2(o1[0], o1[1]), packbf2(o1[2], o1[3]),
                          packbf2(o1[4], o1[5]), packbf2(o1[6], o1[7]));
    *reinterpret_cast<uint4*>(gp)       = u0;
    *reinterpret_cast<uint4*>(gp + IMG) = u1;
}

// ---------------------------------------------------------------------------
// Gram stage 1 v5 (unchanged): quadrant split, 32 px/thread.
// ---------------------------------------------------------------------------
__global__ void __launch_bounds__(256, 2) gram1_kernel(
        const __nv_bfloat16* __restrict__ qkvAd,
        const __nv_bfloat16* __restrict__ qkvBd,
        float* __restrict__ gpA, float* __restrict__ gpB) {
    int bx = blockIdx.x;
    int chunk = bx >> 2;
    int quad  = bx & 3;
    int qh = quad >> 1;
    int kh = quad & 1;
    int h = blockIdx.y;
    int b  = blockIdx.z >> 1;
    int br = blockIdx.z & 1;
    const __nv_bfloat16* qb = (br ? qkvAd : qkvBd) + ((size_t)b * 288 + h * CHEAD + qh * 6) * HW;
    const __nv_bfloat16* kb = (br ? qkvBd : qkvAd) + ((size_t)b * 288 + 96 + h * CHEAD + kh * 6) * HW;
    float* part = br ? gpB : gpA;

    float qsq[6], ksq[6];
    float acc[36];
#pragma unroll
    for (int i = 0; i < 36; i++) acc[i] = 0.f;
#pragma unroll
    for (int i = 0; i < 6; i++) { qsq[i] = 0.f; ksq[i] = 0.f; }

    int p0 = chunk * 8192 + threadIdx.x * 8;
#pragma unroll
    for (int it = 0; it < 4; it++) {
        int p = p0 + it * 2048;
        float qf[6][8];
#pragma unroll
        for (int c = 0; c < 6; c++) {
            uint4 u = *reinterpret_cast<const uint4*>(qb + (size_t)c * HW + p);
            unpack8(qf[c], u);
            float s = 0.f;
#pragma unroll
            for (int j = 0; j < 8; j++) s += qf[c][j] * qf[c][j];
            qsq[c] += s;
        }
#pragma unroll
        for (int d = 0; d < 6; d++) {
            uint4 u = *reinterpret_cast<const uint4*>(kb + (size_t)d * HW + p);
            float kf[8];
            unpack8(kf, u);
            float s = 0.f;
#pragma unroll
            for (int j = 0; j < 8; j++) s += kf[j] * kf[j];
            ksq[d] += s;
#pragma unroll
            for (int c = 0; c < 6; c++) {
                float a = acc[c * 6 + d];
#pragma unroll
                for (int j = 0; j < 8; j++) a += qf[c][j] * kf[j];
                acc[c * 6 + d] = a;
            }
        }
    }

    int warp = threadIdx.x >> 5;
    int lane = threadIdx.x & 31;
    float* outp = part + ((((size_t)(b * HEADS + h)) * 32 + bx) * 8 + warp) * 48;
#pragma unroll
    for (int i = 0; i < 48; i++) {
        float v = (i < 36) ? acc[i] : (i < 42 ? qsq[i - 36] : ksq[i - 42]);
#pragma unroll
        for (int off = 16; off > 0; off >>= 1)
            v += __shfl_down_sync(0xffffffffu, v, off);
        if (lane == 0) outp[i] = v;
    }
}

// ---------------------------------------------------------------------------
// Gram stage 2 + norms + temp + softmax + fused cw emission (unchanged).
// ---------------------------------------------------------------------------
__global__ void attn_kernel(const float* __restrict__ partA,
                            const float* __restrict__ partB,
                            const float* __restrict__ temp,
                            const float* __restrict__ P0,
                            const float* __restrict__ P1,
                            uint32_t* __restrict__ cwApk,
                            uint32_t* __restrict__ cwBpk) {
    int bh = blockIdx.x;
    int b = bh / HEADS;
    int h = bh % HEADS;
    __shared__ float GA[144], GB[144];
    __shared__ float nqA[12], nkA[12], nqB[12], nkB[12];
    int i = threadIdx.x;
    float sA = 0.f, sB = 0.f;
    if (i < 168) {
        int quad, off;
        if (i < 144) {
            int c = i / CHEAD, d = i % CHEAD;
            quad = (c / 6) * 2 + (d / 6);
            off  = (c % 6) * 6 + (d % 6);
        } else if (i < 156) {
            int c = i - 144;
            quad = (c / 6) * 2;
            off  = 36 + (c % 6);
        } else {
            int d = i - 156;
            quad = (d / 6);
            off  = 42 + (d % 6);
        }
        const float* pA = partA + (((size_t)bh * 32 + quad) * 8) * 48 + off;
        const float* pB = partB + (((size_t)bh * 32 + quad) * 8) * 48 + off;
        for (int ch = 0; ch < 8; ch++) {
#pragma unroll
            for (int w = 0; w < 8; w++) {
                size_t o = (size_t)ch * (4 * 8 * 48) + (size_t)w * 48;
                sA += pA[o];
                sB += pB[o];
            }
        }
        if (i >= 156) {
            nkA[i - 156] = fmaxf(sqrtf(sA), 1e-12f);
            nkB[i - 156] = fmaxf(sqrtf(sB), 1e-12f);
        } else if (i >= 144) {
            nqA[i - 144] = fmaxf(sqrtf(sA), 1e-12f);
            nqB[i - 144] = fmaxf(sqrtf(sB), 1e-12f);
        }
    }
    __syncthreads();
    if (i < 144) {
        int c = i / CHEAD, d = i % CHEAD;
        float tp = temp[h];
        GA[i] =  sA / (nqA[c] * nkA[d]) * tp;
        GB[i] = -sB / (nqB[c] * nkB[d]) * tp;
    }
    __syncthreads();
    if (i < 24) {
        float* G = (i < CHEAD) ? GA : GB;
        int c = i % CHEAD;
        float mx = -1e30f;
        for (int d = 0; d < CHEAD; d++) mx = fmaxf(mx, G[c * CHEAD + d]);
        float e[CHEAD];
        float s = 0.f;
        for (int d = 0; d < CHEAD; d++) {
            e[d] = expf(G[c * CHEAD + d] - mx);
            s += e[d];
        }
        float inv = 1.f / s;
        for (int d = 0; d < CHEAD; d++)
            G[c * CHEAD + d] = e[d] * inv;
    }
    __syncthreads();
    {
        int brn = i / 96;
        int m   = i % 96;
        const float* P  = brn ? P1 : P0;
        const float* AT = brn ? GB : GA;
        uint32_t* out = (brn ? cwBpk : cwApk) + (size_t)b * 9216;
        float pr[CHEAD];
#pragma unroll
        for (int c = 0; c < CHEAD; c++) pr[c] = P[m * 96 + h * CHEAD + c];
#pragma unroll
        for (int d = 0; d < CHEAD; d++) {
            float s = 0.f;
#pragma unroll
            for (int c = 0; c < CHEAD; c++) s += pr[c] * AT[c * CHEAD + d];
            out[a_pack_off(m, h * CHEAD + d)] = f2tf(s);
        }
    }
}

// ---------------------------------------------------------------------------
// Launch
// ---------------------------------------------------------------------------
extern "C" void kernel_launch(void* const* d_in, const int* in_sizes, int n_in,
                              void* d_out, int out_size) {
    const float* x       = (const float*)d_in[0];
    const float* y       = (const float*)d_in[1];
    const float* ln1_w   = (const float*)d_in[2];
    const float* ln1_b   = (const float*)d_in[3];
    const float* ln2_w   = (const float*)d_in[4];
    const float* ln2_b   = (const float*)d_in[5];
    const float* qkvA_w  = (const float*)d_in[6];
    const float* dwA_w   = (const float*)d_in[7];
    const float* qkvB_w  = (const float*)d_in[8];
    const float* dwB_w   = (const float*)d_in[9];
    const float* projA_w = (const float*)d_in[10];
    const float* projB_w = (const float*)d_in[11];
    const float* concat_w= (const float*)d_in[12];
    const float* temp    = (const float*)d_in[13];
    const float* pin_w   = (const float*)d_in[14];
    const float* dwf_w   = (const float*)d_in[15];
    const float* pout_w  = (const float*)d_in[16];
    float* out = (float*)d_out;

    cudaFuncSetAttribute(gemm96,   cudaFuncAttributeMaxDynamicSharedMemorySize, G96_SMEM_BYTES);
    cudaFuncSetAttribute(gemmPout, cudaFuncAttributeMaxDynamicSharedMemorySize, POUT_SMEM_BYTES);
    cudaFuncSetAttribute(gemm4_tc, cudaFuncAttributeMaxDynamicSharedMemorySize, G4_SMEM_BYTES);

    __nv_bfloat16 *qkvA, *qkvAd, *qkvB, *qkvBd, *t, *gate, *xn, *yn;
    float *x1, *gpA, *gpB, *P0, *P1;
    uint32_t *prepQA, *prepQB, *prepPin, *prepPout_p, *prepC0, *prepC1, *cwApk, *cwBpk;
    float *sQA, *tQA, *sQB, *tQB, *sPin, *tPin;
    cudaGetSymbolAddress((void**)&qkvA,   g_qkvA);
    cudaGetSymbolAddress((void**)&qkvAd,  g_qkvAd);
    cudaGetSymbolAddress((void**)&qkvB,   g_qkvB);
    cudaGetSymbolAddress((void**)&qkvBd,  g_qkvBd);
    cudaGetSymbolAddress((void**)&xn,     g_xn);
    cudaGetSymbolAddress((void**)&yn,     g_yn);
    cudaGetSymbolAddress((void**)&t,      g_t);
    cudaGetSymbolAddress((void**)&gate,   g_gate);
    cudaGetSymbolAddress((void**)&x1,     g_x1);
    cudaGetSymbolAddress((void**)&gpA,    g_gpartA);
    cudaGetSymbolAddress((void**)&gpB,    g_gpartB);
    cudaGetSymbolAddress((void**)&P0,     g_P0);
    cudaGetSymbolAddress((void**)&P1,     g_P1);
    cudaGetSymbolAddress((void**)&prepQA,   g_prepQA);
    cudaGetSymbolAddress((void**)&prepQB,   g_prepQB);
    cudaGetSymbolAddress((void**)&prepPin,  g_prepPin);
    cudaGetSymbolAddress((void**)&prepPout_p, g_prepPout);
    cudaGetSymbolAddress((void**)&prepC0,   g_prepC0);
    cudaGetSymbolAddress((void**)&prepC1,   g_prepC1);
    cudaGetSymbolAddress((void**)&cwApk,    g_cwApk);
    cudaGetSymbolAddress((void**)&cwBpk,    g_cwBpk);
    cudaGetSymbolAddress((void**)&sQA,    g_sQA);
    cudaGetSymbolAddress((void**)&tQA,    g_tQA);
    cudaGetSymbolAddress((void**)&sQB,    g_sQB);
    cudaGetSymbolAddress((void**)&tQB,    g_tQB);
    cudaGetSymbolAddress((void**)&sPin,   g_sPin);
    cudaGetSymbolAddress((void**)&tPin,   g_tPin);

    const size_t P96   = (size_t)CDIM * HW;
    const size_t P96E  = (size_t)CDIM * HW;
    const size_t P288E = (size_t)3 * CDIM * HW;
    const size_t P510E = (size_t)2 * HIDDEN * HW;
    const size_t PGATE = (size_t)288 * HW;

    megaprep<<<53, 256>>>(qkvA_w, qkvB_w, pin_w, pout_w, concat_w,
                          projA_w, projB_w, ln1_w, ln1_b, ln2_w, ln2_b,
                          prepQA, prepQB, prepPin, prepPout_p, prepC0, prepC1,
                          sQA, tQA, sQB, tQB, sPin, tPin, P0, P1);

    // qkv for both branches; also emits bf16 xn/yn for gemm4
    {
        G96P p;
        p.Apk[0] = prepQA; p.Apk[1] = prepQB;
        p.sv[0] = sQA; p.sv[1] = sQB;
        p.tv[0] = tQA; p.tv[1] = tQB;
        p.X[0] = x; p.X[1] = y;
        p.xnOut[0] = xn; p.xnOut[1] = yn;
        p.Y[0] = qkvA; p.Y[1] = qkvB;
        p.lnw = ln1_w; p.lnb = ln1_b;
        dim3 g(1, HW / 128, BATCH * 2);
        gemm96<<<g, 256, G96_SMEM_BYTES>>>(p, 288, 2, 3, P96, P288E);
    }

    // depthwise 3x3, both branches, 8 px x 2 rows per thread
    {
        dim3 blk(32, 8), g(1, IMG / 16, 2 * BATCH * 288);
        dw3_kernel<<<g, blk>>>(qkvA, qkvB, dwA_w, dwB_w, qkvAd, qkvBd);
    }

    // Gram quadrants, 32 px/thread
    {
        dim3 g(32, HEADS, 2 * BATCH);
        gram1_kernel<<<g, 256>>>(qkvAd, qkvBd, gpA, gpB);
    }

    // attn + fused cw emission
    attn_kernel<<<BATCH * HEADS, 192>>>(gpA, gpB, temp, P0, P1, cwApk, cwBpk);

    // fused x1 = x + cwA@vA + cwB@vB + C0@xn + C1@yn  (all-bf16 sources)
    {
        G4 p;
        p.Apk[0] = cwApk;  p.aBatch[0] = 9216;
        p.Apk[1] = cwBpk;  p.aBatch[1] = 9216;
        p.Apk[2] = prepC0; p.aBatch[2] = 0;
        p.Apk[3] = prepC1; p.aBatch[3] = 0;
        p.X[0] = qkvAd + 192 * (size_t)HW; p.xBatch[0] = P288E;
        p.X[1] = qkvBd + 192 * (size_t)HW; p.xBatch[1] = P288E;
        p.X[2] = xn;                       p.xBatch[2] = P96E;
        p.X[3] = yn;                       p.xBatch[3] = P96E;
        dim3 g(1, HW / 128, BATCH);
        gemm4_tc<<<g, 256, G4_SMEM_BYTES>>>(p, x, x1);
    }

    // pin = W@LN2(x1), B-resident with 6 m-tiles in-block
    {
        G96P p;
        p.Apk[0] = prepPin; p.Apk[1] = prepPin;
        p.sv[0] = sPin; p.sv[1] = sPin;
        p.tv[0] = tPin; p.tv[1] = tPin;
        p.X[0] = x1; p.X[1] = x1;
        p.xnOut[0] = nullptr; p.xnOut[1] = nullptr;
        p.Y[0] = t; p.Y[1] = t;
        p.lnw = ln2_w; p.lnb = ln2_b;
        dim3 g(1, HW / 128, BATCH);
        gemm96<<<g, 256, G96_SMEM_BYTES>>>(p, 510, 1, 6, P96, P510E);
    }

    // fused depthwise + gelu gate, 8 px x 2 rows per thread
    {
        dim3 blk(32, 8), g(1, IMG / 16, BATCH * HIDDEN);
        dwgate_kernel<<<g, blk>>>(t, dwf_w, gate);
    }

    // pout + residual x1 -> output
    {
        dim3 g(1, HW / 128, BATCH);
        gemmPout<<<g, 256, POUT_SMEM_BYTES>>>(prepPout_p, gate, x1, out,
                                              PGATE, P96, P96);
    }
}